// round 10
// baseline (speedup 1.0000x reference)
#include <cuda_runtime.h>
#include <cuda_fp16.h>
#include <math.h>
#include <stdint.h>

// Problem constants (fixed shapes from setup_inputs)
#define B_   2
#define S_   2048
#define D_   2048
#define H_   16
#define KVH_ 4
#define DH_  128
#define M_   (B_ * S_)          // 4096
#define NQKV 3072               // 2048 q + 512 k + 512 v

// Scratch (static device arrays; no runtime allocation allowed)
__device__ float g_qkv[M_ * NQKV];
__device__ __half g_Ahi[M_ * D_];     // residual fp16; reused as Q after rope
__device__ __half g_Whi[NQKV * D_];   // W_Q|W_K|W_V rows, fp16
__device__ __half g_WOhi[D_ * D_];    // W_O transposed [d][he], fp16
__device__ __half g_Phi[M_ * D_];     // attention output fp16
__device__ __half g_Khi[M_ * 512];
__device__ __half g_Vhi[M_ * 512];

// ---------------------------------------------------------------------------
// helpers
// ---------------------------------------------------------------------------
__device__ __forceinline__ uint32_t smem_u32(const void* p) {
    uint32_t a;
    asm("{ .reg .u64 t; cvta.to.shared.u64 t, %1; cvt.u32.u64 %0, t; }"
        : "=r"(a) : "l"(p));
    return a;
}

__device__ __forceinline__ void cp16(uint32_t dst, const void* src) {
    asm volatile("cp.async.cg.shared.global [%0], [%1], 16;"
                 :: "r"(dst), "l"(src));
}

__device__ __forceinline__ void ldm_x4(uint32_t* r, uint32_t addr) {
    asm volatile("ldmatrix.sync.aligned.m8n8.x4.shared.b16 {%0,%1,%2,%3}, [%4];"
                 : "=r"(r[0]), "=r"(r[1]), "=r"(r[2]), "=r"(r[3]) : "r"(addr));
}

__device__ __forceinline__ void ldm_x4_t(uint32_t* r, uint32_t addr) {
    asm volatile("ldmatrix.sync.aligned.m8n8.x4.trans.shared.b16 {%0,%1,%2,%3}, [%4];"
                 : "=r"(r[0]), "=r"(r[1]), "=r"(r[2]), "=r"(r[3]) : "r"(addr));
}

__device__ __forceinline__ void mma_f16(float* c, const uint32_t* a,
                                        uint32_t b0, uint32_t b1) {
    asm volatile(
        "mma.sync.aligned.m16n8k16.row.col.f32.f16.f16.f32 "
        "{%0,%1,%2,%3}, {%4,%5,%6,%7}, {%8,%9}, {%0,%1,%2,%3};"
        : "+f"(c[0]), "+f"(c[1]), "+f"(c[2]), "+f"(c[3])
        : "r"(a[0]), "r"(a[1]), "r"(a[2]), "r"(a[3]), "r"(b0), "r"(b1));
}

// fp16-accumulate MMA: d/c are 2 b32 regs (4 halves)
__device__ __forceinline__ void mma_f16acc(uint32_t* c, const uint32_t* a,
                                           uint32_t b0, uint32_t b1) {
    asm volatile(
        "mma.sync.aligned.m16n8k16.row.col.f16.f16.f16.f16 "
        "{%0,%1}, {%2,%3,%4,%5}, {%6,%7}, {%0,%1};"
        : "+r"(c[0]), "+r"(c[1])
        : "r"(a[0]), "r"(a[1]), "r"(a[2]), "r"(a[3]), "r"(b0), "r"(b1));
}

// swizzled byte offset for a 16B segment (row r, seg s) in a [rows][32]fp16 block
__device__ __forceinline__ uint32_t swz_off(int r, int s) {
    return (uint32_t)(r * 64 + ((s ^ ((r >> 1) & 3)) * 16));
}

// swizzled byte offset for [rows][128 fp16] tiles (256B rows, 16 segs)
__device__ __forceinline__ uint32_t aswz(int r, int sg) {
    return (uint32_t)(r * 256 + ((sg ^ (r & 7)) * 16));
}

__device__ __forceinline__ uint32_t pack_f2h2(float x0, float x1) {
    __half2 p = __floats2half2_rn(x0, x1);
    return *(uint32_t*)&p;
}

// ---------------------------------------------------------------------------
// HMMA GEMM: C[m,n] = sum_k A[m,k]*B[n,k].
// fp16 inputs, fp16 accumulate within each K=32 chunk (full-rate HMMA),
// chunk sums spilled into fp32 master accumulators.
// CTA tile 128x128, 8 warps (4m x 2n), warp tile 32x64. K-chunk 32.
// stage = Ah|Bh, each [128][32]fp16 (8KB) = 16KB; 4 stages = 64KB. 2 CTA/SM.
// ---------------------------------------------------------------------------
#define GEMM_STAGE 16384
#define GEMM_SMEM (4 * GEMM_STAGE)

__global__ __launch_bounds__(256, 2) void hmma_gemm(
    const __half* __restrict__ Ah, const __half* __restrict__ Bh,
    float* __restrict__ C, int ldc)
{
    extern __shared__ char smem[];
    uint32_t sb = smem_u32(smem);

    int tid = threadIdx.x;
    int lane = tid & 31;
    int warp = tid >> 5;
    int warp_m = warp & 3;
    int warp_n = warp >> 2;
    int m0 = blockIdx.y * 128;
    int n0 = blockIdx.x * 128;

    int q = lane >> 3;
    int lrow = lane & 7;
    int arow_l = (q & 1) * 8 + lrow;
    int ksel = q >> 1;

    float acc[2][8][4];
#pragma unroll
    for (int i = 0; i < 2; i++)
#pragma unroll
        for (int j = 0; j < 8; j++)
#pragma unroll
            for (int k = 0; k < 4; k++) acc[i][j][k] = 0.f;

    auto load_chunk = [&](int c) {
        int k0 = c * 32;
        uint32_t buf = sb + (uint32_t)(c & 3) * GEMM_STAGE;
#pragma unroll
        for (int t = 0; t < 4; t++) {
            int g = tid + t * 256;           // 0..1023
            int mat = g >> 9;                // 0 Ah, 1 Bh
            int inner = g & 511;
            int r = inner >> 2;
            int s = inner & 3;
            const __half* base = mat ? Bh : Ah;
            int row = (mat ? n0 : m0) + r;
            const void* src = base + (size_t)row * 2048 + k0 + s * 8;
            cp16(buf + (uint32_t)mat * 8192u + swz_off(r, s), src);
        }
        asm volatile("cp.async.commit_group;" ::: "memory");
    };

    load_chunk(0);
    load_chunk(1);
    load_chunk(2);
    load_chunk(3);

    for (int c = 0; c < 64; c++) {
        asm volatile("cp.async.wait_group 3;" ::: "memory");
        __syncthreads();

        uint32_t buf = sb + (uint32_t)(c & 3) * GEMM_STAGE;
        uint32_t bAh = buf, bBh = buf + 8192;

        // A fragments for both k16 steps of this chunk
        uint32_t ah[2][2][4];
#pragma unroll
        for (int ks = 0; ks < 2; ks++) {
            int s = ks * 2 + ksel;
#pragma unroll
            for (int mi = 0; mi < 2; mi++) {
                int r = warp_m * 32 + mi * 16 + arow_l;
                ldm_x4(ah[ks][mi], bAh + swz_off(r, s));
            }
        }

        // process N in two halves of 32 cols; fp16 chunk accumulators
#pragma unroll
        for (int nh = 0; nh < 2; nh++) {
            uint32_t cacc[2][4][2];
#pragma unroll
            for (int mi = 0; mi < 2; mi++)
#pragma unroll
                for (int nj = 0; nj < 4; nj++) {
                    cacc[mi][nj][0] = 0u; cacc[mi][nj][1] = 0u;
                }

#pragma unroll
            for (int ks = 0; ks < 2; ks++) {
                int s = ks * 2 + ksel;
                uint32_t bh[4][2];
#pragma unroll
                for (int jj = 0; jj < 2; jj++) {
                    int r = warp_n * 64 + (nh * 2 + jj) * 16 + arow_l;
                    uint32_t t4[4];
                    ldm_x4(t4, bBh + swz_off(r, s));
                    bh[jj * 2 + 0][0] = t4[0]; bh[jj * 2 + 0][1] = t4[2];
                    bh[jj * 2 + 1][0] = t4[1]; bh[jj * 2 + 1][1] = t4[3];
                }
#pragma unroll
                for (int mi = 0; mi < 2; mi++)
#pragma unroll
                    for (int nj = 0; nj < 4; nj++)
                        mma_f16acc(cacc[mi][nj], ah[ks][mi], bh[nj][0], bh[nj][1]);
            }

            // spill fp16 chunk sums -> fp32 master
#pragma unroll
            for (int mi = 0; mi < 2; mi++)
#pragma unroll
                for (int nj = 0; nj < 4; nj++) {
                    float2 lo = __half22float2(*(__half2*)&cacc[mi][nj][0]);
                    float2 hi = __half22float2(*(__half2*)&cacc[mi][nj][1]);
                    float* a4 = acc[mi][nh * 4 + nj];
                    a4[0] += lo.x; a4[1] += lo.y;
                    a4[2] += hi.x; a4[3] += hi.y;
                }
        }
        __syncthreads();
        if (c + 4 < 64) load_chunk(c + 4);
        else asm volatile("cp.async.commit_group;" ::: "memory");
    }

    int rr = lane >> 2;
    int cc = (lane & 3) * 2;
#pragma unroll
    for (int mi = 0; mi < 2; mi++) {
        int r1 = m0 + warp_m * 32 + mi * 16 + rr;
#pragma unroll
        for (int nj = 0; nj < 8; nj++) {
            int col = n0 + warp_n * 64 + nj * 8 + cc;
            float2 v0 = make_float2(acc[mi][nj][0], acc[mi][nj][1]);
            float2 v1 = make_float2(acc[mi][nj][2], acc[mi][nj][3]);
            *(float2*)&C[(size_t)r1 * ldc + col] = v0;
            *(float2*)&C[(size_t)(r1 + 8) * ldc + col] = v1;
        }
    }
}

// ---------------------------------------------------------------------------
// Elementwise fp32 -> fp16
// ---------------------------------------------------------------------------
__global__ __launch_bounds__(256) void cvt_kernel(
    const float* __restrict__ src, __half* __restrict__ dst, int n4)
{
    int i = blockIdx.x * 256 + threadIdx.x;
    if (i >= n4) return;
    float4 v = ((const float4*)src)[i];
    ushort4 hv = make_ushort4(
        __half_as_ushort(__float2half_rn(v.x)),
        __half_as_ushort(__float2half_rn(v.y)),
        __half_as_ushort(__float2half_rn(v.z)),
        __half_as_ushort(__float2half_rn(v.w)));
    ((ushort4*)dst)[i] = hv;
}

// ---------------------------------------------------------------------------
// Transpose + convert W_O: in [he=2048][d=2048] fp32 -> out [d][he] fp16
// ---------------------------------------------------------------------------
__global__ __launch_bounds__(256) void transpose_cvt_wo(
    const float* __restrict__ W, __half* __restrict__ Th)
{
    __shared__ float t[32][33];
    int bx = blockIdx.x * 32;
    int by = blockIdx.y * 32;
    int x = threadIdx.x & 31;
    int y0 = threadIdx.x >> 5;
#pragma unroll
    for (int i = 0; i < 32; i += 8)
        t[y0 + i][x] = W[(size_t)(by + y0 + i) * 2048 + bx + x];
    __syncthreads();
#pragma unroll
    for (int i = 0; i < 32; i += 8) {
        float v = t[x][y0 + i];
        Th[(size_t)(bx + y0 + i) * 2048 + by + x] = __float2half_rn(v);
    }
}

// ---------------------------------------------------------------------------
// RoPE producer:
//  q: rope, scale 1/sqrt(Dh) -> fp16 Qhi
//  k: rope -> fp32 k_cache + fp16 Khi
//  v: copy -> fp32 v_cache + fp16 Vhi
// ---------------------------------------------------------------------------
__global__ __launch_bounds__(256) void rope_split_kernel(
    const float* __restrict__ qkv,
    float* __restrict__ kc, float* __restrict__ vc,
    __half* __restrict__ Qhi,
    __half* __restrict__ Khi, __half* __restrict__ Vhi,
    const int* __restrict__ sp_ptr)
{
    const float LOG2_BASE_OVER_HALF = 13.287712379549449f / 64.0f;
    const float scale = 0.08838834764831845f;  // 1/sqrt(128)
    int m = blockIdx.x;
    int s = m & (S_ - 1);
    int sp = *sp_ptr;
    float pos = (float)(sp + s);
    int tid = threadIdx.x;

    for (int p = tid; p < H_ * 64; p += 256) {
        int h = p >> 6, e = p & 63;
        float inv = exp2f(-(float)e * LOG2_BASE_OVER_HALF);
        float ang = pos * inv;
        float sn, cs;
        sincosf(ang, &sn, &cs);
        const float* base = qkv + (size_t)m * NQKV + h * DH_;
        float x1 = base[e], x2 = base[e + 64];
        float y1 = (x1 * cs - x2 * sn) * scale;
        float y2 = (x1 * sn + x2 * cs) * scale;
        size_t o = (size_t)m * D_ + h * DH_;
        Qhi[o + e]      = __float2half_rn(y1);
        Qhi[o + e + 64] = __float2half_rn(y2);
    }
    for (int p = tid; p < KVH_ * 64; p += 256) {
        int h = p >> 6, e = p & 63;
        float inv = exp2f(-(float)e * LOG2_BASE_OVER_HALF);
        float ang = pos * inv;
        float sn, cs;
        sincosf(ang, &sn, &cs);
        const float* base = qkv + (size_t)m * NQKV + 2048 + h * DH_;
        float x1 = base[e], x2 = base[e + 64];
        float y1 = x1 * cs - x2 * sn;
        float y2 = x1 * sn + x2 * cs;
        size_t o = (size_t)m * (KVH_ * DH_) + h * DH_;
        kc[o + e]      = y1;
        kc[o + e + 64] = y2;
        Khi[o + e]      = __float2half_rn(y1);
        Khi[o + e + 64] = __float2half_rn(y2);
    }
    for (int i = tid; i < KVH_ * DH_; i += 256) {
        float v = qkv[(size_t)m * NQKV + 2560 + i];
        size_t o = (size_t)m * (KVH_ * DH_) + i;
        vc[o] = v;
        Vhi[o] = __float2half_rn(v);
    }
}

// ---------------------------------------------------------------------------
// Tensor-core flash attention, pure fp16 inputs (fp32 accumulate).
// BM=64 (4 warps x m16), BN=64, Dh=128. Q frags hoisted to registers.
// KV stage = Khi|Vhi each 64x128 fp16 (16KB) = 32KB; 2 stages.
// smem: Q 16KB + 64KB = 80KB -> 2 CTAs/SM.
// ---------------------------------------------------------------------------
#define ATT_KV_STAGE 32768
#define ATT2_SMEM (16384 + 2 * ATT_KV_STAGE)

__global__ __launch_bounds__(128, 2) void attn_mma_kernel(
    const __half* __restrict__ Qhi,
    const __half* __restrict__ Khi, const __half* __restrict__ Vhi,
    __half* __restrict__ Ohi,
    const int* __restrict__ sp_ptr)
{
    extern __shared__ char smem[];
    uint32_t sb = smem_u32(smem);
    const uint32_t sQh = sb;
    const uint32_t sKV = sb + 16384;

    int tid = threadIdx.x;
    int lane = tid & 31;
    int warp = tid >> 5;                 // 0..3
    int bh = blockIdx.y;
    int b = bh >> 4, h = bh & 15, kvh = h >> 2;
    int q0 = blockIdx.x * 64;
    int sp = *sp_ptr;
    float slope = exp2f(-0.5f * (float)(h + 1));

    int fr = ((lane >> 3) & 1) * 8 + (lane & 7);
    int fs = lane >> 4;

    int kt_end = (sp + q0 + 63) >> 6;
    if (kt_end > S_ / 64 - 1) kt_end = S_ / 64 - 1;

    // ---- KV tile loader (Khi + Vhi, 64 rows x 128 cols each) ----
    auto load_kv = [&](int kt) {
        int k0 = (kt <= kt_end ? kt : kt_end) * 64;
        uint32_t stage = sKV + (uint32_t)(kt & 1) * ATT_KV_STAGE;
#pragma unroll
        for (int i = 0; i < 16; i++) {
            int idx = tid + i * 128;   // 0..2047
            int t = idx >> 10;         // 0 Khi, 1 Vhi
            int inner = idx & 1023;
            int r = inner >> 4, sg = inner & 15;
            const __half* basep = t ? Vhi : Khi;
            const __half* src =
                basep + (size_t)(b * S_ + k0 + r) * 512 + kvh * 128 + sg * 8;
            cp16(stage + (uint32_t)t * 16384u + aswz(r, sg), src);
        }
        asm volatile("cp.async.commit_group;" ::: "memory");
    };

    // ---- prologue: Q (group 0), KV(0) (group 1), KV(1) (group 2) ----
#pragma unroll
    for (int i = 0; i < 8; i++) {
        int idx = tid + i * 128;          // 0..1023
        int r = idx >> 4, sg = idx & 15;
        const __half* src = Qhi
            + (size_t)(b * S_ + q0 + r) * 2048 + h * 128 + sg * 8;
        cp16(sQh + aswz(r, sg), src);
    }
    asm volatile("cp.async.commit_group;" ::: "memory");
    load_kv(0);
    load_kv(1);

    // ---- Q fragments -> registers (kt-invariant) ----
    asm volatile("cp.async.wait_group 2;" ::: "memory");
    __syncthreads();
    uint32_t qh[8][4];
#pragma unroll
    for (int s = 0; s < 8; s++)
        ldm_x4(qh[s], sQh + aswz(warp * 16 + fr, 2 * s + fs));

    float Oacc[16][4];
#pragma unroll
    for (int e = 0; e < 16; e++)
#pragma unroll
        for (int k = 0; k < 4; k++) Oacc[e][k] = 0.f;
    float m0r = -1e30f, m1r = -1e30f;
    float l0r = 0.f, l1r = 0.f;

    int row0 = q0 + warp * 16 + (lane >> 2);
    int qp0 = sp + row0, qp1 = qp0 + 8;

    for (int kt = 0; kt <= kt_end; kt++) {
        int k0 = kt * 64;
        asm volatile("cp.async.wait_group 1;" ::: "memory");
        __syncthreads();

        uint32_t stage = sKV + (uint32_t)(kt & 1) * ATT_KV_STAGE;
        uint32_t sKh = stage, sVh = stage + 16384;

        // ---- S = Q K^T ----
        float sacc[8][4];
#pragma unroll
        for (int nj = 0; nj < 8; nj++)
#pragma unroll
            for (int k = 0; k < 4; k++) sacc[nj][k] = 0.f;

#pragma unroll
        for (int s = 0; s < 8; s++) {
            uint32_t kbh[8][2], t4[4];
#pragma unroll
            for (int j = 0; j < 4; j++) {
                ldm_x4(t4, sKh + aswz(j * 16 + fr, 2 * s + fs));
                kbh[2 * j][0] = t4[0]; kbh[2 * j][1] = t4[2];
                kbh[2 * j + 1][0] = t4[1]; kbh[2 * j + 1][1] = t4[3];
            }
#pragma unroll
            for (int nj = 0; nj < 8; nj++)
                mma_f16(sacc[nj], qh[s], kbh[nj][0], kbh[nj][1]);
        }

        // ---- bias + causal mask ----
#pragma unroll
        for (int nj = 0; nj < 8; nj++) {
            int c = k0 + nj * 8 + (lane & 3) * 2;
            sacc[nj][0] = (c     <= qp0) ? sacc[nj][0] - slope * (float)(qp0 - c)     : -1e30f;
            sacc[nj][1] = (c + 1 <= qp0) ? sacc[nj][1] - slope * (float)(qp0 - c - 1) : -1e30f;
            sacc[nj][2] = (c     <= qp1) ? sacc[nj][2] - slope * (float)(qp1 - c)     : -1e30f;
            sacc[nj][3] = (c + 1 <= qp1) ? sacc[nj][3] - slope * (float)(qp1 - c - 1) : -1e30f;
        }

        // ---- online softmax ----
        float mx0 = -1e30f, mx1 = -1e30f;
#pragma unroll
        for (int nj = 0; nj < 8; nj++) {
            mx0 = fmaxf(mx0, fmaxf(sacc[nj][0], sacc[nj][1]));
            mx1 = fmaxf(mx1, fmaxf(sacc[nj][2], sacc[nj][3]));
        }
        mx0 = fmaxf(mx0, __shfl_xor_sync(0xffffffffu, mx0, 1));
        mx0 = fmaxf(mx0, __shfl_xor_sync(0xffffffffu, mx0, 2));
        mx1 = fmaxf(mx1, __shfl_xor_sync(0xffffffffu, mx1, 1));
        mx1 = fmaxf(mx1, __shfl_xor_sync(0xffffffffu, mx1, 2));
        float mn0 = fmaxf(m0r, mx0), mn1 = fmaxf(m1r, mx1);
        float corr0 = __expf(m0r - mn0), corr1 = __expf(m1r - mn1);
        m0r = mn0; m1r = mn1;

        float ls0 = 0.f, ls1 = 0.f;
#pragma unroll
        for (int nj = 0; nj < 8; nj++) {
            sacc[nj][0] = __expf(sacc[nj][0] - mn0);
            sacc[nj][1] = __expf(sacc[nj][1] - mn0);
            sacc[nj][2] = __expf(sacc[nj][2] - mn1);
            sacc[nj][3] = __expf(sacc[nj][3] - mn1);
            ls0 += sacc[nj][0] + sacc[nj][1];
            ls1 += sacc[nj][2] + sacc[nj][3];
        }
        ls0 += __shfl_xor_sync(0xffffffffu, ls0, 1);
        ls0 += __shfl_xor_sync(0xffffffffu, ls0, 2);
        ls1 += __shfl_xor_sync(0xffffffffu, ls1, 1);
        ls1 += __shfl_xor_sync(0xffffffffu, ls1, 2);
        l0r = l0r * corr0 + ls0;
        l1r = l1r * corr1 + ls1;

#pragma unroll
        for (int e = 0; e < 16; e++) {
            Oacc[e][0] *= corr0; Oacc[e][1] *= corr0;
            Oacc[e][2] *= corr1; Oacc[e][3] *= corr1;
        }

        // ---- P -> fp16 A-fragments (4 k16 tiles) ----
        uint32_t phi[4][4];
#pragma unroll
        for (int t = 0; t < 4; t++) {
            phi[t][0] = pack_f2h2(sacc[2 * t][0], sacc[2 * t][1]);
            phi[t][1] = pack_f2h2(sacc[2 * t][2], sacc[2 * t][3]);
            phi[t][2] = pack_f2h2(sacc[2 * t + 1][0], sacc[2 * t + 1][1]);
            phi[t][3] = pack_f2h2(sacc[2 * t + 1][2], sacc[2 * t + 1][3]);
        }

        // ---- O += P V ----
#pragma unroll
        for (int t = 0; t < 4; t++) {
#pragma unroll
            for (int u = 0; u < 8; u++) {
                uint32_t th[4];
                ldm_x4_t(th, sVh + aswz(t * 16 + fr, 2 * u + fs));
                mma_f16(Oacc[2 * u], phi[t], th[0], th[1]);
                mma_f16(Oacc[2 * u + 1], phi[t], th[2], th[3]);
            }
        }
        __syncthreads();
        if (kt + 2 <= kt_end) load_kv(kt + 2);
        else asm volatile("cp.async.commit_group;" ::: "memory");
    }

    // ---- epilogue: normalize + fp16 output ----
    float inv0 = 1.f / l0r, inv1 = 1.f / l1r;
    size_t row0g = (size_t)(b * S_ + row0);
#pragma unroll
    for (int e = 0; e < 16; e++) {
        int colb = h * 128 + e * 8 + (lane & 3) * 2;
        uint32_t hp0 = pack_f2h2(Oacc[e][0] * inv0, Oacc[e][1] * inv0);
        uint32_t hp1 = pack_f2h2(Oacc[e][2] * inv1, Oacc[e][3] * inv1);
        *(uint32_t*)&Ohi[row0g * 2048 + colb] = hp0;
        *(uint32_t*)&Ohi[(row0g + 8) * 2048 + colb] = hp1;
    }
}

// ---------------------------------------------------------------------------
extern "C" void kernel_launch(void* const* d_in, const int* in_sizes, int n_in,
                              void* d_out, int out_size)
{
    const float* residual = (const float*)d_in[0];
    const float* W_Q = (const float*)d_in[1];
    const float* W_K = (const float*)d_in[2];
    const float* W_V = (const float*)d_in[3];
    const float* W_O = (const float*)d_in[4];
    const int* sp = (const int*)d_in[5];

    float* out = (float*)d_out;
    float* k_cache = out + (size_t)B_ * S_ * D_;
    float* v_cache = k_cache + (size_t)B_ * S_ * KVH_ * DH_;

    float* qkv_ptr;
    __half *Ahi, *Whi, *WOhi, *Phi, *Khi, *Vhi;
    cudaGetSymbolAddress((void**)&qkv_ptr, g_qkv);
    cudaGetSymbolAddress((void**)&Ahi, g_Ahi);
    cudaGetSymbolAddress((void**)&Whi, g_Whi);
    cudaGetSymbolAddress((void**)&WOhi, g_WOhi);
    cudaGetSymbolAddress((void**)&Phi, g_Phi);
    cudaGetSymbolAddress((void**)&Khi, g_Khi);
    cudaGetSymbolAddress((void**)&Vhi, g_Vhi);

    cudaFuncSetAttribute(hmma_gemm, cudaFuncAttributeMaxDynamicSharedMemorySize,
                         GEMM_SMEM);
    cudaFuncSetAttribute(attn_mma_kernel, cudaFuncAttributeMaxDynamicSharedMemorySize,
                         ATT2_SMEM);

    // 0) converts
    cvt_kernel<<<(M_ * D_ / 4 + 255) / 256, 256>>>(residual, Ahi, M_ * D_ / 4);
    cvt_kernel<<<(2048 * 2048 / 4 + 255) / 256, 256>>>(W_Q, Whi, 2048 * 2048 / 4);
    cvt_kernel<<<(512 * 2048 / 4 + 255) / 256, 256>>>(
        W_K, Whi + (size_t)2048 * 2048, 512 * 2048 / 4);
    cvt_kernel<<<(512 * 2048 / 4 + 255) / 256, 256>>>(
        W_V, Whi + (size_t)2560 * 2048, 512 * 2048 / 4);
    transpose_cvt_wo<<<dim3(64, 64), 256>>>(W_O, WOhi);

    // 1) fused QKV projection (fp16 full-rate, chunked fp32 spill)
    hmma_gemm<<<dim3(NQKV / 128, M_ / 128), 256, GEMM_SMEM>>>(
        Ahi, Whi, qkv_ptr, NQKV);

    // 2) RoPE producer (Qhi reuses g_Ahi)
    rope_split_kernel<<<M_, 256>>>(qkv_ptr, k_cache, v_cache,
                                   Ahi, Khi, Vhi, sp);

    // 3) tensor-core attention (fp16, fp32 acc) -> fp16 output
    attn_mma_kernel<<<dim3(S_ / 64, B_ * H_), 128, ATT2_SMEM>>>(
        Ahi, Khi, Vhi, Phi, sp);

    // 4) output projection (fp16 full-rate, chunked fp32 spill)
    hmma_gemm<<<dim3(D_ / 128, M_ / 128), 256, GEMM_SMEM>>>(
        Phi, WOhi, out, D_);
}

// round 11
// speedup vs baseline: 1.2268x; 1.2268x over previous
#include <cuda_runtime.h>
#include <cuda_fp16.h>
#include <math.h>
#include <stdint.h>

// Problem constants (fixed shapes from setup_inputs)
#define B_   2
#define S_   2048
#define D_   2048
#define H_   16
#define KVH_ 4
#define DH_  128
#define M_   (B_ * S_)          // 4096
#define NQKV 3072               // 2048 q + 512 k + 512 v

// Scratch (static device arrays; no runtime allocation allowed)
__device__ float g_qkv[M_ * NQKV];
__device__ __half g_Ahi[M_ * D_];     // residual fp16; reused as Q after rope
__device__ __half g_Whi[NQKV * D_];   // W_Q|W_K|W_V rows, fp16
__device__ __half g_WOhi[D_ * D_];    // W_O transposed [d][he], fp16
__device__ __half g_Phi[M_ * D_];     // attention output fp16
__device__ __half g_Khi[M_ * 512];
__device__ __half g_Vhi[M_ * 512];

// ---------------------------------------------------------------------------
// helpers
// ---------------------------------------------------------------------------
__device__ __forceinline__ uint32_t smem_u32(const void* p) {
    uint32_t a;
    asm("{ .reg .u64 t; cvta.to.shared.u64 t, %1; cvt.u32.u64 %0, t; }"
        : "=r"(a) : "l"(p));
    return a;
}

__device__ __forceinline__ void cp16(uint32_t dst, const void* src) {
    asm volatile("cp.async.cg.shared.global [%0], [%1], 16;"
                 :: "r"(dst), "l"(src));
}

__device__ __forceinline__ void ldm_x4(uint32_t* r, uint32_t addr) {
    asm volatile("ldmatrix.sync.aligned.m8n8.x4.shared.b16 {%0,%1,%2,%3}, [%4];"
                 : "=r"(r[0]), "=r"(r[1]), "=r"(r[2]), "=r"(r[3]) : "r"(addr));
}

__device__ __forceinline__ void ldm_x4_t(uint32_t* r, uint32_t addr) {
    asm volatile("ldmatrix.sync.aligned.m8n8.x4.trans.shared.b16 {%0,%1,%2,%3}, [%4];"
                 : "=r"(r[0]), "=r"(r[1]), "=r"(r[2]), "=r"(r[3]) : "r"(addr));
}

__device__ __forceinline__ void mma_f16(float* c, const uint32_t* a,
                                        uint32_t b0, uint32_t b1) {
    asm volatile(
        "mma.sync.aligned.m16n8k16.row.col.f32.f16.f16.f32 "
        "{%0,%1,%2,%3}, {%4,%5,%6,%7}, {%8,%9}, {%0,%1,%2,%3};"
        : "+f"(c[0]), "+f"(c[1]), "+f"(c[2]), "+f"(c[3])
        : "r"(a[0]), "r"(a[1]), "r"(a[2]), "r"(a[3]), "r"(b0), "r"(b1));
}

// swizzled byte offset for a 16B segment (row r, seg s) in a [rows][32]fp16 block
__device__ __forceinline__ uint32_t swz_off(int r, int s) {
    return (uint32_t)(r * 64 + ((s ^ ((r >> 1) & 3)) * 16));
}

// swizzled byte offset for [rows][128 fp16] tiles (256B rows, 16 segs)
__device__ __forceinline__ uint32_t aswz(int r, int sg) {
    return (uint32_t)(r * 256 + ((sg ^ (r & 7)) * 16));
}

__device__ __forceinline__ uint32_t pack_f2h2(float x0, float x1) {
    __half2 p = __floats2half2_rn(x0, x1);
    return *(uint32_t*)&p;
}

// ---------------------------------------------------------------------------
// HMMA GEMM (R9 exact): C[m,n] = sum_k A[m,k]*B[n,k], fp16 in, fp32 acc.
// CTA tile 128x128, 8 warps (4m x 2n), warp tile 32x64. K-chunk 32.
// stage = Ah|Bh, each [128][32]fp16 (8KB) = 16KB; 4 stages = 64KB. 2 CTA/SM.
// ---------------------------------------------------------------------------
#define GEMM_STAGE 16384
#define GEMM_SMEM (4 * GEMM_STAGE)

__global__ __launch_bounds__(256, 2) void hmma_gemm(
    const __half* __restrict__ Ah, const __half* __restrict__ Bh,
    float* __restrict__ C, int ldc)
{
    extern __shared__ char smem[];
    uint32_t sb = smem_u32(smem);

    int tid = threadIdx.x;
    int lane = tid & 31;
    int warp = tid >> 5;
    int warp_m = warp & 3;
    int warp_n = warp >> 2;
    int m0 = blockIdx.y * 128;
    int n0 = blockIdx.x * 128;

    int q = lane >> 3;
    int lrow = lane & 7;
    int arow_l = (q & 1) * 8 + lrow;
    int ksel = q >> 1;

    float acc[2][8][4];
#pragma unroll
    for (int i = 0; i < 2; i++)
#pragma unroll
        for (int j = 0; j < 8; j++)
#pragma unroll
            for (int k = 0; k < 4; k++) acc[i][j][k] = 0.f;

    auto load_chunk = [&](int c) {
        int k0 = c * 32;
        uint32_t buf = sb + (uint32_t)(c & 3) * GEMM_STAGE;
#pragma unroll
        for (int t = 0; t < 4; t++) {
            int g = tid + t * 256;           // 0..1023
            int mat = g >> 9;                // 0 Ah, 1 Bh
            int inner = g & 511;
            int r = inner >> 2;
            int s = inner & 3;
            const __half* base = mat ? Bh : Ah;
            int row = (mat ? n0 : m0) + r;
            const void* src = base + (size_t)row * 2048 + k0 + s * 8;
            cp16(buf + (uint32_t)mat * 8192u + swz_off(r, s), src);
        }
        asm volatile("cp.async.commit_group;" ::: "memory");
    };

    load_chunk(0);
    load_chunk(1);
    load_chunk(2);
    load_chunk(3);

    for (int c = 0; c < 64; c++) {
        asm volatile("cp.async.wait_group 3;" ::: "memory");
        __syncthreads();

        uint32_t buf = sb + (uint32_t)(c & 3) * GEMM_STAGE;
        uint32_t bAh = buf, bBh = buf + 8192;

#pragma unroll
        for (int ks = 0; ks < 2; ks++) {
            int s = ks * 2 + ksel;
            uint32_t ah[2][4];
#pragma unroll
            for (int mi = 0; mi < 2; mi++) {
                int r = warp_m * 32 + mi * 16 + arow_l;
                ldm_x4(ah[mi], bAh + swz_off(r, s));
            }
            uint32_t bh[8][2];
#pragma unroll
            for (int j = 0; j < 4; j++) {
                int r = warp_n * 64 + j * 16 + arow_l;
                uint32_t t4[4];
                ldm_x4(t4, bBh + swz_off(r, s));
                bh[j * 2 + 0][0] = t4[0]; bh[j * 2 + 0][1] = t4[2];
                bh[j * 2 + 1][0] = t4[1]; bh[j * 2 + 1][1] = t4[3];
            }
#pragma unroll
            for (int mi = 0; mi < 2; mi++) {
#pragma unroll
                for (int nj = 0; nj < 8; nj++)
                    mma_f16(acc[mi][nj], ah[mi], bh[nj][0], bh[nj][1]);
            }
        }
        __syncthreads();
        if (c + 4 < 64) load_chunk(c + 4);
        else asm volatile("cp.async.commit_group;" ::: "memory");
    }

    int rr = lane >> 2;
    int cc = (lane & 3) * 2;
#pragma unroll
    for (int mi = 0; mi < 2; mi++) {
        int r1 = m0 + warp_m * 32 + mi * 16 + rr;
#pragma unroll
        for (int nj = 0; nj < 8; nj++) {
            int col = n0 + warp_n * 64 + nj * 8 + cc;
            float2 v0 = make_float2(acc[mi][nj][0], acc[mi][nj][1]);
            float2 v1 = make_float2(acc[mi][nj][2], acc[mi][nj][3]);
            *(float2*)&C[(size_t)r1 * ldc + col] = v0;
            *(float2*)&C[(size_t)(r1 + 8) * ldc + col] = v1;
        }
    }
}

// ---------------------------------------------------------------------------
// Merged prep: fp32 -> fp16 for residual + W_Q + W_K + W_V in one launch.
// Region boundaries in float4 units.
// ---------------------------------------------------------------------------
#define N4_RES  (M_ * D_ / 4)            // 2097152
#define N4_WQ   (2048 * 2048 / 4)        // 1048576
#define N4_WK   (512 * 2048 / 4)         // 262144
#define N4_ALL  (N4_RES + N4_WQ + 2 * N4_WK)

__global__ __launch_bounds__(256) void prep_kernel(
    const float* __restrict__ residual, const float* __restrict__ WQ,
    const float* __restrict__ WK, const float* __restrict__ WV,
    __half* __restrict__ Ahi, __half* __restrict__ Whi)
{
    int i = blockIdx.x * 256 + threadIdx.x;
    if (i >= N4_ALL) return;
    const float* src;
    __half* dst;
    int j = i;
    if (j < N4_RES) {
        src = residual; dst = Ahi;
    } else if ((j -= N4_RES) < N4_WQ) {
        src = WQ; dst = Whi;
    } else if ((j -= N4_WQ) < N4_WK) {
        src = WK; dst = Whi + (size_t)2048 * 2048;
    } else {
        j -= N4_WK;
        src = WV; dst = Whi + (size_t)2560 * 2048;
    }
    float4 v = ((const float4*)src)[j];
    ushort4 hv = make_ushort4(
        __half_as_ushort(__float2half_rn(v.x)),
        __half_as_ushort(__float2half_rn(v.y)),
        __half_as_ushort(__float2half_rn(v.z)),
        __half_as_ushort(__float2half_rn(v.w)));
    ((ushort4*)dst)[j] = hv;
}

// ---------------------------------------------------------------------------
// Transpose + convert W_O: in [he=2048][d=2048] fp32 -> out [d][he] fp16
// ---------------------------------------------------------------------------
__global__ __launch_bounds__(256) void transpose_cvt_wo(
    const float* __restrict__ W, __half* __restrict__ Th)
{
    __shared__ float t[32][33];
    int bx = blockIdx.x * 32;
    int by = blockIdx.y * 32;
    int x = threadIdx.x & 31;
    int y0 = threadIdx.x >> 5;
#pragma unroll
    for (int i = 0; i < 32; i += 8)
        t[y0 + i][x] = W[(size_t)(by + y0 + i) * 2048 + bx + x];
    __syncthreads();
#pragma unroll
    for (int i = 0; i < 32; i += 8) {
        float v = t[x][y0 + i];
        Th[(size_t)(bx + y0 + i) * 2048 + by + x] = __float2half_rn(v);
    }
}

// ---------------------------------------------------------------------------
// RoPE producer:
//  q: rope, scale 1/sqrt(Dh) -> fp16 Qhi
//  k: rope -> fp32 k_cache + fp16 Khi
//  v: copy -> fp32 v_cache + fp16 Vhi
// ---------------------------------------------------------------------------
__global__ __launch_bounds__(256) void rope_split_kernel(
    const float* __restrict__ qkv,
    float* __restrict__ kc, float* __restrict__ vc,
    __half* __restrict__ Qhi,
    __half* __restrict__ Khi, __half* __restrict__ Vhi,
    const int* __restrict__ sp_ptr)
{
    const float LOG2_BASE_OVER_HALF = 13.287712379549449f / 64.0f;
    const float scale = 0.08838834764831845f;  // 1/sqrt(128)
    int m = blockIdx.x;
    int s = m & (S_ - 1);
    int sp = *sp_ptr;
    float pos = (float)(sp + s);
    int tid = threadIdx.x;

    for (int p = tid; p < H_ * 64; p += 256) {
        int h = p >> 6, e = p & 63;
        float inv = exp2f(-(float)e * LOG2_BASE_OVER_HALF);
        float ang = pos * inv;
        float sn, cs;
        sincosf(ang, &sn, &cs);
        const float* base = qkv + (size_t)m * NQKV + h * DH_;
        float x1 = base[e], x2 = base[e + 64];
        float y1 = (x1 * cs - x2 * sn) * scale;
        float y2 = (x1 * sn + x2 * cs) * scale;
        size_t o = (size_t)m * D_ + h * DH_;
        Qhi[o + e]      = __float2half_rn(y1);
        Qhi[o + e + 64] = __float2half_rn(y2);
    }
    for (int p = tid; p < KVH_ * 64; p += 256) {
        int h = p >> 6, e = p & 63;
        float inv = exp2f(-(float)e * LOG2_BASE_OVER_HALF);
        float ang = pos * inv;
        float sn, cs;
        sincosf(ang, &sn, &cs);
        const float* base = qkv + (size_t)m * NQKV + 2048 + h * DH_;
        float x1 = base[e], x2 = base[e + 64];
        float y1 = x1 * cs - x2 * sn;
        float y2 = x1 * sn + x2 * cs;
        size_t o = (size_t)m * (KVH_ * DH_) + h * DH_;
        kc[o + e]      = y1;
        kc[o + e + 64] = y2;
        Khi[o + e]      = __float2half_rn(y1);
        Khi[o + e + 64] = __float2half_rn(y2);
    }
    for (int i = tid; i < KVH_ * DH_; i += 256) {
        float v = qkv[(size_t)m * NQKV + 2560 + i];
        size_t o = (size_t)m * (KVH_ * DH_) + i;
        vc[o] = v;
        Vhi[o] = __float2half_rn(v);
    }
}

// ---------------------------------------------------------------------------
// Tensor-core flash attention, pure fp16 inputs (fp32 accumulate).
// BM=64 (4 warps x m16), BN=64, Dh=128. Q frags hoisted to registers.
// KV stage = Khi|Vhi each 64x128 fp16 (16KB) = 32KB; 2 stages.
// smem: Q 16KB + 64KB = 80KB -> 2 CTAs/SM.
// Fast path: interior tiles skip causal masking.
// ---------------------------------------------------------------------------
#define ATT_KV_STAGE 32768
#define ATT2_SMEM (16384 + 2 * ATT_KV_STAGE)

__global__ __launch_bounds__(128, 2) void attn_mma_kernel(
    const __half* __restrict__ Qhi,
    const __half* __restrict__ Khi, const __half* __restrict__ Vhi,
    __half* __restrict__ Ohi,
    const int* __restrict__ sp_ptr)
{
    extern __shared__ char smem[];
    uint32_t sb = smem_u32(smem);
    const uint32_t sQh = sb;
    const uint32_t sKV = sb + 16384;

    int tid = threadIdx.x;
    int lane = tid & 31;
    int warp = tid >> 5;                 // 0..3
    int bh = blockIdx.y;
    int b = bh >> 4, h = bh & 15, kvh = h >> 2;
    int q0 = blockIdx.x * 64;
    int sp = *sp_ptr;
    float slope = exp2f(-0.5f * (float)(h + 1));

    int fr = ((lane >> 3) & 1) * 8 + (lane & 7);
    int fs = lane >> 4;

    int kt_end = (sp + q0 + 63) >> 6;
    if (kt_end > S_ / 64 - 1) kt_end = S_ / 64 - 1;

    // ---- KV tile loader (Khi + Vhi, 64 rows x 128 cols each) ----
    auto load_kv = [&](int kt) {
        int k0 = (kt <= kt_end ? kt : kt_end) * 64;
        uint32_t stage = sKV + (uint32_t)(kt & 1) * ATT_KV_STAGE;
#pragma unroll
        for (int i = 0; i < 16; i++) {
            int idx = tid + i * 128;   // 0..2047
            int t = idx >> 10;         // 0 Khi, 1 Vhi
            int inner = idx & 1023;
            int r = inner >> 4, sg = inner & 15;
            const __half* basep = t ? Vhi : Khi;
            const __half* src =
                basep + (size_t)(b * S_ + k0 + r) * 512 + kvh * 128 + sg * 8;
            cp16(stage + (uint32_t)t * 16384u + aswz(r, sg), src);
        }
        asm volatile("cp.async.commit_group;" ::: "memory");
    };

    // ---- prologue: Q (group 0), KV(0) (group 1), KV(1) (group 2) ----
#pragma unroll
    for (int i = 0; i < 8; i++) {
        int idx = tid + i * 128;          // 0..1023
        int r = idx >> 4, sg = idx & 15;
        const __half* src = Qhi
            + (size_t)(b * S_ + q0 + r) * 2048 + h * 128 + sg * 8;
        cp16(sQh + aswz(r, sg), src);
    }
    asm volatile("cp.async.commit_group;" ::: "memory");
    load_kv(0);
    load_kv(1);

    // ---- Q fragments -> registers (kt-invariant) ----
    asm volatile("cp.async.wait_group 2;" ::: "memory");
    __syncthreads();
    uint32_t qh[8][4];
#pragma unroll
    for (int s = 0; s < 8; s++)
        ldm_x4(qh[s], sQh + aswz(warp * 16 + fr, 2 * s + fs));

    float Oacc[16][4];
#pragma unroll
    for (int e = 0; e < 16; e++)
#pragma unroll
        for (int k = 0; k < 4; k++) Oacc[e][k] = 0.f;
    float m0r = -1e30f, m1r = -1e30f;
    float l0r = 0.f, l1r = 0.f;

    int row0 = q0 + warp * 16 + (lane >> 2);
    int qp0 = sp + row0, qp1 = qp0 + 8;

    for (int kt = 0; kt <= kt_end; kt++) {
        int k0 = kt * 64;
        asm volatile("cp.async.wait_group 1;" ::: "memory");
        __syncthreads();

        uint32_t stage = sKV + (uint32_t)(kt & 1) * ATT_KV_STAGE;
        uint32_t sKh = stage, sVh = stage + 16384;

        // ---- S = Q K^T ----
        float sacc[8][4];
#pragma unroll
        for (int nj = 0; nj < 8; nj++)
#pragma unroll
            for (int k = 0; k < 4; k++) sacc[nj][k] = 0.f;

#pragma unroll
        for (int s = 0; s < 8; s++) {
            uint32_t kbh[8][2], t4[4];
#pragma unroll
            for (int j = 0; j < 4; j++) {
                ldm_x4(t4, sKh + aswz(j * 16 + fr, 2 * s + fs));
                kbh[2 * j][0] = t4[0]; kbh[2 * j][1] = t4[2];
                kbh[2 * j + 1][0] = t4[1]; kbh[2 * j + 1][1] = t4[3];
            }
#pragma unroll
            for (int nj = 0; nj < 8; nj++)
                mma_f16(sacc[nj], qh[s], kbh[nj][0], kbh[nj][1]);
        }

        // ---- bias (+ causal mask only on boundary tiles) ----
        if (k0 + 63 <= sp + q0) {
            // interior tile: no masking possible
#pragma unroll
            for (int nj = 0; nj < 8; nj++) {
                int c = k0 + nj * 8 + (lane & 3) * 2;
                sacc[nj][0] -= slope * (float)(qp0 - c);
                sacc[nj][1] -= slope * (float)(qp0 - c - 1);
                sacc[nj][2] -= slope * (float)(qp1 - c);
                sacc[nj][3] -= slope * (float)(qp1 - c - 1);
            }
        } else {
#pragma unroll
            for (int nj = 0; nj < 8; nj++) {
                int c = k0 + nj * 8 + (lane & 3) * 2;
                sacc[nj][0] = (c     <= qp0) ? sacc[nj][0] - slope * (float)(qp0 - c)     : -1e30f;
                sacc[nj][1] = (c + 1 <= qp0) ? sacc[nj][1] - slope * (float)(qp0 - c - 1) : -1e30f;
                sacc[nj][2] = (c     <= qp1) ? sacc[nj][2] - slope * (float)(qp1 - c)     : -1e30f;
                sacc[nj][3] = (c + 1 <= qp1) ? sacc[nj][3] - slope * (float)(qp1 - c - 1) : -1e30f;
            }
        }

        // ---- online softmax ----
        float mx0 = -1e30f, mx1 = -1e30f;
#pragma unroll
        for (int nj = 0; nj < 8; nj++) {
            mx0 = fmaxf(mx0, fmaxf(sacc[nj][0], sacc[nj][1]));
            mx1 = fmaxf(mx1, fmaxf(sacc[nj][2], sacc[nj][3]));
        }
        mx0 = fmaxf(mx0, __shfl_xor_sync(0xffffffffu, mx0, 1));
        mx0 = fmaxf(mx0, __shfl_xor_sync(0xffffffffu, mx0, 2));
        mx1 = fmaxf(mx1, __shfl_xor_sync(0xffffffffu, mx1, 1));
        mx1 = fmaxf(mx1, __shfl_xor_sync(0xffffffffu, mx1, 2));
        float mn0 = fmaxf(m0r, mx0), mn1 = fmaxf(m1r, mx1);
        float corr0 = __expf(m0r - mn0), corr1 = __expf(m1r - mn1);
        m0r = mn0; m1r = mn1;

        float ls0 = 0.f, ls1 = 0.f;
#pragma unroll
        for (int nj = 0; nj < 8; nj++) {
            sacc[nj][0] = __expf(sacc[nj][0] - mn0);
            sacc[nj][1] = __expf(sacc[nj][1] - mn0);
            sacc[nj][2] = __expf(sacc[nj][2] - mn1);
            sacc[nj][3] = __expf(sacc[nj][3] - mn1);
            ls0 += sacc[nj][0] + sacc[nj][1];
            ls1 += sacc[nj][2] + sacc[nj][3];
        }
        ls0 += __shfl_xor_sync(0xffffffffu, ls0, 1);
        ls0 += __shfl_xor_sync(0xffffffffu, ls0, 2);
        ls1 += __shfl_xor_sync(0xffffffffu, ls1, 1);
        ls1 += __shfl_xor_sync(0xffffffffu, ls1, 2);
        l0r = l0r * corr0 + ls0;
        l1r = l1r * corr1 + ls1;

#pragma unroll
        for (int e = 0; e < 16; e++) {
            Oacc[e][0] *= corr0; Oacc[e][1] *= corr0;
            Oacc[e][2] *= corr1; Oacc[e][3] *= corr1;
        }

        // ---- P -> fp16 A-fragments (4 k16 tiles) ----
        uint32_t phi[4][4];
#pragma unroll
        for (int t = 0; t < 4; t++) {
            phi[t][0] = pack_f2h2(sacc[2 * t][0], sacc[2 * t][1]);
            phi[t][1] = pack_f2h2(sacc[2 * t][2], sacc[2 * t][3]);
            phi[t][2] = pack_f2h2(sacc[2 * t + 1][0], sacc[2 * t + 1][1]);
            phi[t][3] = pack_f2h2(sacc[2 * t + 1][2], sacc[2 * t + 1][3]);
        }

        // ---- O += P V ----
#pragma unroll
        for (int t = 0; t < 4; t++) {
#pragma unroll
            for (int u = 0; u < 8; u++) {
                uint32_t th[4];
                ldm_x4_t(th, sVh + aswz(t * 16 + fr, 2 * u + fs));
                mma_f16(Oacc[2 * u], phi[t], th[0], th[1]);
                mma_f16(Oacc[2 * u + 1], phi[t], th[2], th[3]);
            }
        }
        __syncthreads();
        if (kt + 2 <= kt_end) load_kv(kt + 2);
        else asm volatile("cp.async.commit_group;" ::: "memory");
    }

    // ---- epilogue: normalize + fp16 output ----
    float inv0 = 1.f / l0r, inv1 = 1.f / l1r;
    size_t row0g = (size_t)(b * S_ + row0);
#pragma unroll
    for (int e = 0; e < 16; e++) {
        int colb = h * 128 + e * 8 + (lane & 3) * 2;
        uint32_t hp0 = pack_f2h2(Oacc[e][0] * inv0, Oacc[e][1] * inv0);
        uint32_t hp1 = pack_f2h2(Oacc[e][2] * inv1, Oacc[e][3] * inv1);
        *(uint32_t*)&Ohi[row0g * 2048 + colb] = hp0;
        *(uint32_t*)&Ohi[(row0g + 8) * 2048 + colb] = hp1;
    }
}

// ---------------------------------------------------------------------------
extern "C" void kernel_launch(void* const* d_in, const int* in_sizes, int n_in,
                              void* d_out, int out_size)
{
    const float* residual = (const float*)d_in[0];
    const float* W_Q = (const float*)d_in[1];
    const float* W_K = (const float*)d_in[2];
    const float* W_V = (const float*)d_in[3];
    const float* W_O = (const float*)d_in[4];
    const int* sp = (const int*)d_in[5];

    float* out = (float*)d_out;
    float* k_cache = out + (size_t)B_ * S_ * D_;
    float* v_cache = k_cache + (size_t)B_ * S_ * KVH_ * DH_;

    float* qkv_ptr;
    __half *Ahi, *Whi, *WOhi, *Phi, *Khi, *Vhi;
    cudaGetSymbolAddress((void**)&qkv_ptr, g_qkv);
    cudaGetSymbolAddress((void**)&Ahi, g_Ahi);
    cudaGetSymbolAddress((void**)&Whi, g_Whi);
    cudaGetSymbolAddress((void**)&WOhi, g_WOhi);
    cudaGetSymbolAddress((void**)&Phi, g_Phi);
    cudaGetSymbolAddress((void**)&Khi, g_Khi);
    cudaGetSymbolAddress((void**)&Vhi, g_Vhi);

    cudaFuncSetAttribute(hmma_gemm, cudaFuncAttributeMaxDynamicSharedMemorySize,
                         GEMM_SMEM);
    cudaFuncSetAttribute(attn_mma_kernel, cudaFuncAttributeMaxDynamicSharedMemorySize,
                         ATT2_SMEM);

    // 0) merged converts + W_O transpose
    prep_kernel<<<(N4_ALL + 255) / 256, 256>>>(residual, W_Q, W_K, W_V, Ahi, Whi);
    transpose_cvt_wo<<<dim3(64, 64), 256>>>(W_O, WOhi);

    // 1) fused QKV projection (fp16 single-pass)
    hmma_gemm<<<dim3(NQKV / 128, M_ / 128), 256, GEMM_SMEM>>>(
        Ahi, Whi, qkv_ptr, NQKV);

    // 2) RoPE producer (Qhi reuses g_Ahi)
    rope_split_kernel<<<M_, 256>>>(qkv_ptr, k_cache, v_cache,
                                   Ahi, Khi, Vhi, sp);

    // 3) tensor-core attention (fp16, fp32 acc) -> fp16 output
    attn_mma_kernel<<<dim3(S_ / 64, B_ * H_), 128, ATT2_SMEM>>>(
        Ahi, Khi, Vhi, Phi, sp);

    // 4) output projection (fp16 single-pass)
    hmma_gemm<<<dim3(D_ / 128, M_ / 128), 256, GEMM_SMEM>>>(
        Phi, WOhi, out, D_);
}

// round 12
// speedup vs baseline: 1.2333x; 1.0053x over previous
#include <cuda_runtime.h>
#include <cuda_fp16.h>
#include <math.h>
#include <stdint.h>

// Problem constants (fixed shapes from setup_inputs)
#define B_   2
#define S_   2048
#define D_   2048
#define H_   16
#define KVH_ 4
#define DH_  128
#define M_   (B_ * S_)          // 4096
#define NQKV 3072               // 2048 q + 512 k + 512 v

// Scratch (static device arrays; no runtime allocation allowed)
__device__ float g_qkv[M_ * NQKV];
__device__ __half g_Ahi[M_ * D_];     // residual fp16; reused as Q after rope
__device__ __half g_Whi[NQKV * D_];   // W_Q|W_K|W_V rows, fp16
__device__ __half g_WOhi[D_ * D_];    // W_O transposed [d][he], fp16
__device__ __half g_Phi[M_ * D_];     // attention output fp16
__device__ __half g_Khi[M_ * 512];
__device__ __half g_Vhi[M_ * 512];
__device__ float2 g_rope[S_ * 64];    // per (s, e): (cos, sin)

// ---------------------------------------------------------------------------
// helpers
// ---------------------------------------------------------------------------
__device__ __forceinline__ uint32_t smem_u32(const void* p) {
    uint32_t a;
    asm("{ .reg .u64 t; cvta.to.shared.u64 t, %1; cvt.u32.u64 %0, t; }"
        : "=r"(a) : "l"(p));
    return a;
}

__device__ __forceinline__ void cp16(uint32_t dst, const void* src) {
    asm volatile("cp.async.cg.shared.global [%0], [%1], 16;"
                 :: "r"(dst), "l"(src));
}

__device__ __forceinline__ void ldm_x4(uint32_t* r, uint32_t addr) {
    asm volatile("ldmatrix.sync.aligned.m8n8.x4.shared.b16 {%0,%1,%2,%3}, [%4];"
                 : "=r"(r[0]), "=r"(r[1]), "=r"(r[2]), "=r"(r[3]) : "r"(addr));
}

__device__ __forceinline__ void ldm_x4_t(uint32_t* r, uint32_t addr) {
    asm volatile("ldmatrix.sync.aligned.m8n8.x4.trans.shared.b16 {%0,%1,%2,%3}, [%4];"
                 : "=r"(r[0]), "=r"(r[1]), "=r"(r[2]), "=r"(r[3]) : "r"(addr));
}

__device__ __forceinline__ void mma_f16(float* c, const uint32_t* a,
                                        uint32_t b0, uint32_t b1) {
    asm volatile(
        "mma.sync.aligned.m16n8k16.row.col.f32.f16.f16.f32 "
        "{%0,%1,%2,%3}, {%4,%5,%6,%7}, {%8,%9}, {%0,%1,%2,%3};"
        : "+f"(c[0]), "+f"(c[1]), "+f"(c[2]), "+f"(c[3])
        : "r"(a[0]), "r"(a[1]), "r"(a[2]), "r"(a[3]), "r"(b0), "r"(b1));
}

// swizzled byte offset for a 16B segment (row r, seg s) in a [rows][32]fp16 block
__device__ __forceinline__ uint32_t swz_off(int r, int s) {
    return (uint32_t)(r * 64 + ((s ^ ((r >> 1) & 3)) * 16));
}

// swizzled byte offset for [rows][128 fp16] tiles (256B rows, 16 segs)
__device__ __forceinline__ uint32_t aswz(int r, int sg) {
    return (uint32_t)(r * 256 + ((sg ^ (r & 7)) * 16));
}

__device__ __forceinline__ uint32_t pack_f2h2(float x0, float x1) {
    __half2 p = __floats2half2_rn(x0, x1);
    return *(uint32_t*)&p;
}

// ---------------------------------------------------------------------------
// HMMA GEMM (R9 exact): C[m,n] = sum_k A[m,k]*B[n,k], fp16 in, fp32 acc.
// CTA tile 128x128, 8 warps (4m x 2n), warp tile 32x64. K-chunk 32.
// stage = Ah|Bh, each [128][32]fp16 (8KB) = 16KB; 4 stages = 64KB. 2 CTA/SM.
// ---------------------------------------------------------------------------
#define GEMM_STAGE 16384
#define GEMM_SMEM (4 * GEMM_STAGE)

__global__ __launch_bounds__(256, 2) void hmma_gemm(
    const __half* __restrict__ Ah, const __half* __restrict__ Bh,
    float* __restrict__ C, int ldc)
{
    extern __shared__ char smem[];
    uint32_t sb = smem_u32(smem);

    int tid = threadIdx.x;
    int lane = tid & 31;
    int warp = tid >> 5;
    int warp_m = warp & 3;
    int warp_n = warp >> 2;
    int m0 = blockIdx.y * 128;
    int n0 = blockIdx.x * 128;

    int q = lane >> 3;
    int lrow = lane & 7;
    int arow_l = (q & 1) * 8 + lrow;
    int ksel = q >> 1;

    float acc[2][8][4];
#pragma unroll
    for (int i = 0; i < 2; i++)
#pragma unroll
        for (int j = 0; j < 8; j++)
#pragma unroll
            for (int k = 0; k < 4; k++) acc[i][j][k] = 0.f;

    auto load_chunk = [&](int c) {
        int k0 = c * 32;
        uint32_t buf = sb + (uint32_t)(c & 3) * GEMM_STAGE;
#pragma unroll
        for (int t = 0; t < 4; t++) {
            int g = tid + t * 256;           // 0..1023
            int mat = g >> 9;                // 0 Ah, 1 Bh
            int inner = g & 511;
            int r = inner >> 2;
            int s = inner & 3;
            const __half* base = mat ? Bh : Ah;
            int row = (mat ? n0 : m0) + r;
            const void* src = base + (size_t)row * 2048 + k0 + s * 8;
            cp16(buf + (uint32_t)mat * 8192u + swz_off(r, s), src);
        }
        asm volatile("cp.async.commit_group;" ::: "memory");
    };

    load_chunk(0);
    load_chunk(1);
    load_chunk(2);
    load_chunk(3);

    for (int c = 0; c < 64; c++) {
        asm volatile("cp.async.wait_group 3;" ::: "memory");
        __syncthreads();

        uint32_t buf = sb + (uint32_t)(c & 3) * GEMM_STAGE;
        uint32_t bAh = buf, bBh = buf + 8192;

#pragma unroll
        for (int ks = 0; ks < 2; ks++) {
            int s = ks * 2 + ksel;
            uint32_t ah[2][4];
#pragma unroll
            for (int mi = 0; mi < 2; mi++) {
                int r = warp_m * 32 + mi * 16 + arow_l;
                ldm_x4(ah[mi], bAh + swz_off(r, s));
            }
            uint32_t bh[8][2];
#pragma unroll
            for (int j = 0; j < 4; j++) {
                int r = warp_n * 64 + j * 16 + arow_l;
                uint32_t t4[4];
                ldm_x4(t4, bBh + swz_off(r, s));
                bh[j * 2 + 0][0] = t4[0]; bh[j * 2 + 0][1] = t4[2];
                bh[j * 2 + 1][0] = t4[1]; bh[j * 2 + 1][1] = t4[3];
            }
#pragma unroll
            for (int mi = 0; mi < 2; mi++) {
#pragma unroll
                for (int nj = 0; nj < 8; nj++)
                    mma_f16(acc[mi][nj], ah[mi], bh[nj][0], bh[nj][1]);
            }
        }
        __syncthreads();
        if (c + 4 < 64) load_chunk(c + 4);
        else asm volatile("cp.async.commit_group;" ::: "memory");
    }

    int rr = lane >> 2;
    int cc = (lane & 3) * 2;
#pragma unroll
    for (int mi = 0; mi < 2; mi++) {
        int r1 = m0 + warp_m * 32 + mi * 16 + rr;
#pragma unroll
        for (int nj = 0; nj < 8; nj++) {
            int col = n0 + warp_n * 64 + nj * 8 + cc;
            float2 v0 = make_float2(acc[mi][nj][0], acc[mi][nj][1]);
            float2 v1 = make_float2(acc[mi][nj][2], acc[mi][nj][3]);
            *(float2*)&C[(size_t)r1 * ldc + col] = v0;
            *(float2*)&C[(size_t)(r1 + 8) * ldc + col] = v1;
        }
    }
}

// ---------------------------------------------------------------------------
// Rope table: per (s, e) pair -> (cos, sin) of (sp+s)*invfreq(e)
// ---------------------------------------------------------------------------
__global__ __launch_bounds__(64) void rope_table_kernel(const int* __restrict__ sp_ptr)
{
    const float LOG2_BASE_OVER_HALF = 13.287712379549449f / 64.0f;
    int s = blockIdx.x;
    int e = threadIdx.x;
    float pos = (float)(*sp_ptr + s);
    float inv = exp2f(-(float)e * LOG2_BASE_OVER_HALF);
    float sn, cs;
    sincosf(pos * inv, &sn, &cs);
    g_rope[s * 64 + e] = make_float2(cs, sn);
}

// ---------------------------------------------------------------------------
// Merged prep: fp32 -> fp16 for residual + W_Q + W_K + W_V, plus the
// W_O transpose+convert, in ONE launch. Transpose blocks appended after the
// elementwise range.
// ---------------------------------------------------------------------------
#define N4_RES  (M_ * D_ / 4)            // 2097152
#define N4_WQ   (2048 * 2048 / 4)        // 1048576
#define N4_WK   (512 * 2048 / 4)         // 262144
#define N4_ALL  (N4_RES + N4_WQ + 2 * N4_WK)
#define PREP_EW_BLOCKS ((N4_ALL + 255) / 256)
#define PREP_TR_BLOCKS (64 * 64)
#define PREP_BLOCKS (PREP_EW_BLOCKS + PREP_TR_BLOCKS)

__global__ __launch_bounds__(256) void prep_kernel(
    const float* __restrict__ residual, const float* __restrict__ WQ,
    const float* __restrict__ WK, const float* __restrict__ WV,
    const float* __restrict__ WO,
    __half* __restrict__ Ahi, __half* __restrict__ Whi,
    __half* __restrict__ WOhi)
{
    if (blockIdx.x < PREP_EW_BLOCKS) {
        int i = blockIdx.x * 256 + threadIdx.x;
        if (i >= N4_ALL) return;
        const float* src;
        __half* dst;
        int j = i;
        if (j < N4_RES) {
            src = residual; dst = Ahi;
        } else if ((j -= N4_RES) < N4_WQ) {
            src = WQ; dst = Whi;
        } else if ((j -= N4_WQ) < N4_WK) {
            src = WK; dst = Whi + (size_t)2048 * 2048;
        } else {
            j -= N4_WK;
            src = WV; dst = Whi + (size_t)2560 * 2048;
        }
        float4 v = ((const float4*)src)[j];
        ushort4 hv = make_ushort4(
            __half_as_ushort(__float2half_rn(v.x)),
            __half_as_ushort(__float2half_rn(v.y)),
            __half_as_ushort(__float2half_rn(v.z)),
            __half_as_ushort(__float2half_rn(v.w)));
        ((ushort4*)dst)[j] = hv;
    } else {
        // W_O transpose: [he][d] -> [d][he]
        __shared__ float t[32][33];
        int bid = blockIdx.x - PREP_EW_BLOCKS;
        int bx = (bid & 63) * 32;   // d tile
        int by = (bid >> 6) * 32;   // he tile
        int x = threadIdx.x & 31;
        int y0 = threadIdx.x >> 5;
#pragma unroll
        for (int i = 0; i < 32; i += 8)
            t[y0 + i][x] = WO[(size_t)(by + y0 + i) * 2048 + bx + x];
        __syncthreads();
#pragma unroll
        for (int i = 0; i < 32; i += 8) {
            float v = t[x][y0 + i];
            WOhi[(size_t)(bx + y0 + i) * 2048 + by + x] = __float2half_rn(v);
        }
    }
}

// ---------------------------------------------------------------------------
// RoPE producer (table-driven):
//  q: rope, scale 1/sqrt(Dh) -> fp16 Qhi
//  k: rope -> fp32 k_cache + fp16 Khi
//  v: copy -> fp32 v_cache + fp16 Vhi
// ---------------------------------------------------------------------------
__global__ __launch_bounds__(256) void rope_split_kernel(
    const float* __restrict__ qkv,
    float* __restrict__ kc, float* __restrict__ vc,
    __half* __restrict__ Qhi,
    __half* __restrict__ Khi, __half* __restrict__ Vhi)
{
    const float scale = 0.08838834764831845f;  // 1/sqrt(128)
    int m = blockIdx.x;
    int s = m & (S_ - 1);
    int tid = threadIdx.x;
    const float2* rope = g_rope + s * 64;

    for (int p = tid; p < H_ * 64; p += 256) {
        int h = p >> 6, e = p & 63;
        float2 r = rope[e];
        const float* base = qkv + (size_t)m * NQKV + h * DH_;
        float x1 = base[e], x2 = base[e + 64];
        float y1 = (x1 * r.x - x2 * r.y) * scale;
        float y2 = (x1 * r.y + x2 * r.x) * scale;
        size_t o = (size_t)m * D_ + h * DH_;
        Qhi[o + e]      = __float2half_rn(y1);
        Qhi[o + e + 64] = __float2half_rn(y2);
    }
    for (int p = tid; p < KVH_ * 64; p += 256) {
        int h = p >> 6, e = p & 63;
        float2 r = rope[e];
        const float* base = qkv + (size_t)m * NQKV + 2048 + h * DH_;
        float x1 = base[e], x2 = base[e + 64];
        float y1 = x1 * r.x - x2 * r.y;
        float y2 = x1 * r.y + x2 * r.x;
        size_t o = (size_t)m * (KVH_ * DH_) + h * DH_;
        kc[o + e]      = y1;
        kc[o + e + 64] = y2;
        Khi[o + e]      = __float2half_rn(y1);
        Khi[o + e + 64] = __float2half_rn(y2);
    }
    for (int i = tid; i < KVH_ * DH_; i += 256) {
        float v = qkv[(size_t)m * NQKV + 2560 + i];
        size_t o = (size_t)m * (KVH_ * DH_) + i;
        vc[o] = v;
        Vhi[o] = __float2half_rn(v);
    }
}

// ---------------------------------------------------------------------------
// Tensor-core flash attention, pure fp16 inputs (fp32 accumulate).
// BM=64 (4 warps x m16), BN=64, Dh=128. Q frags hoisted to registers.
// KV stage = Khi|Vhi each 64x128 fp16 (16KB) = 32KB; 2 stages.
// smem: Q 16KB + 64KB = 80KB -> 2 CTAs/SM.
// Fast path: interior tiles skip causal masking.
// ---------------------------------------------------------------------------
#define ATT_KV_STAGE 32768
#define ATT2_SMEM (16384 + 2 * ATT_KV_STAGE)

__global__ __launch_bounds__(128, 2) void attn_mma_kernel(
    const __half* __restrict__ Qhi,
    const __half* __restrict__ Khi, const __half* __restrict__ Vhi,
    __half* __restrict__ Ohi,
    const int* __restrict__ sp_ptr)
{
    extern __shared__ char smem[];
    uint32_t sb = smem_u32(smem);
    const uint32_t sQh = sb;
    const uint32_t sKV = sb + 16384;

    int tid = threadIdx.x;
    int lane = tid & 31;
    int warp = tid >> 5;                 // 0..3
    int bh = blockIdx.y;
    int b = bh >> 4, h = bh & 15, kvh = h >> 2;
    int q0 = blockIdx.x * 64;
    int sp = *sp_ptr;
    float slope = exp2f(-0.5f * (float)(h + 1));

    int fr = ((lane >> 3) & 1) * 8 + (lane & 7);
    int fs = lane >> 4;

    int kt_end = (sp + q0 + 63) >> 6;
    if (kt_end > S_ / 64 - 1) kt_end = S_ / 64 - 1;

    // ---- KV tile loader (Khi + Vhi, 64 rows x 128 cols each) ----
    auto load_kv = [&](int kt) {
        int k0 = (kt <= kt_end ? kt : kt_end) * 64;
        uint32_t stage = sKV + (uint32_t)(kt & 1) * ATT_KV_STAGE;
#pragma unroll
        for (int i = 0; i < 16; i++) {
            int idx = tid + i * 128;   // 0..2047
            int t = idx >> 10;         // 0 Khi, 1 Vhi
            int inner = idx & 1023;
            int r = inner >> 4, sg = inner & 15;
            const __half* basep = t ? Vhi : Khi;
            const __half* src =
                basep + (size_t)(b * S_ + k0 + r) * 512 + kvh * 128 + sg * 8;
            cp16(stage + (uint32_t)t * 16384u + aswz(r, sg), src);
        }
        asm volatile("cp.async.commit_group;" ::: "memory");
    };

    // ---- prologue: Q (group 0), KV(0) (group 1), KV(1) (group 2) ----
#pragma unroll
    for (int i = 0; i < 8; i++) {
        int idx = tid + i * 128;          // 0..1023
        int r = idx >> 4, sg = idx & 15;
        const __half* src = Qhi
            + (size_t)(b * S_ + q0 + r) * 2048 + h * 128 + sg * 8;
        cp16(sQh + aswz(r, sg), src);
    }
    asm volatile("cp.async.commit_group;" ::: "memory");
    load_kv(0);
    load_kv(1);

    // ---- Q fragments -> registers (kt-invariant) ----
    asm volatile("cp.async.wait_group 2;" ::: "memory");
    __syncthreads();
    uint32_t qh[8][4];
#pragma unroll
    for (int s = 0; s < 8; s++)
        ldm_x4(qh[s], sQh + aswz(warp * 16 + fr, 2 * s + fs));

    float Oacc[16][4];
#pragma unroll
    for (int e = 0; e < 16; e++)
#pragma unroll
        for (int k = 0; k < 4; k++) Oacc[e][k] = 0.f;
    float m0r = -1e30f, m1r = -1e30f;
    float l0r = 0.f, l1r = 0.f;

    int row0 = q0 + warp * 16 + (lane >> 2);
    int qp0 = sp + row0, qp1 = qp0 + 8;

    for (int kt = 0; kt <= kt_end; kt++) {
        int k0 = kt * 64;
        asm volatile("cp.async.wait_group 1;" ::: "memory");
        __syncthreads();

        uint32_t stage = sKV + (uint32_t)(kt & 1) * ATT_KV_STAGE;
        uint32_t sKh = stage, sVh = stage + 16384;

        // ---- S = Q K^T ----
        float sacc[8][4];
#pragma unroll
        for (int nj = 0; nj < 8; nj++)
#pragma unroll
            for (int k = 0; k < 4; k++) sacc[nj][k] = 0.f;

#pragma unroll
        for (int s = 0; s < 8; s++) {
            uint32_t kbh[8][2], t4[4];
#pragma unroll
            for (int j = 0; j < 4; j++) {
                ldm_x4(t4, sKh + aswz(j * 16 + fr, 2 * s + fs));
                kbh[2 * j][0] = t4[0]; kbh[2 * j][1] = t4[2];
                kbh[2 * j + 1][0] = t4[1]; kbh[2 * j + 1][1] = t4[3];
            }
#pragma unroll
            for (int nj = 0; nj < 8; nj++)
                mma_f16(sacc[nj], qh[s], kbh[nj][0], kbh[nj][1]);
        }

        // ---- bias (+ causal mask only on boundary tiles) ----
        if (k0 + 63 <= sp + q0) {
#pragma unroll
            for (int nj = 0; nj < 8; nj++) {
                int c = k0 + nj * 8 + (lane & 3) * 2;
                sacc[nj][0] -= slope * (float)(qp0 - c);
                sacc[nj][1] -= slope * (float)(qp0 - c - 1);
                sacc[nj][2] -= slope * (float)(qp1 - c);
                sacc[nj][3] -= slope * (float)(qp1 - c - 1);
            }
        } else {
#pragma unroll
            for (int nj = 0; nj < 8; nj++) {
                int c = k0 + nj * 8 + (lane & 3) * 2;
                sacc[nj][0] = (c     <= qp0) ? sacc[nj][0] - slope * (float)(qp0 - c)     : -1e30f;
                sacc[nj][1] = (c + 1 <= qp0) ? sacc[nj][1] - slope * (float)(qp0 - c - 1) : -1e30f;
                sacc[nj][2] = (c     <= qp1) ? sacc[nj][2] - slope * (float)(qp1 - c)     : -1e30f;
                sacc[nj][3] = (c + 1 <= qp1) ? sacc[nj][3] - slope * (float)(qp1 - c - 1) : -1e30f;
            }
        }

        // ---- online softmax ----
        float mx0 = -1e30f, mx1 = -1e30f;
#pragma unroll
        for (int nj = 0; nj < 8; nj++) {
            mx0 = fmaxf(mx0, fmaxf(sacc[nj][0], sacc[nj][1]));
            mx1 = fmaxf(mx1, fmaxf(sacc[nj][2], sacc[nj][3]));
        }
        mx0 = fmaxf(mx0, __shfl_xor_sync(0xffffffffu, mx0, 1));
        mx0 = fmaxf(mx0, __shfl_xor_sync(0xffffffffu, mx0, 2));
        mx1 = fmaxf(mx1, __shfl_xor_sync(0xffffffffu, mx1, 1));
        mx1 = fmaxf(mx1, __shfl_xor_sync(0xffffffffu, mx1, 2));
        float mn0 = fmaxf(m0r, mx0), mn1 = fmaxf(m1r, mx1);
        float corr0 = __expf(m0r - mn0), corr1 = __expf(m1r - mn1);
        m0r = mn0; m1r = mn1;

        float ls0 = 0.f, ls1 = 0.f;
#pragma unroll
        for (int nj = 0; nj < 8; nj++) {
            sacc[nj][0] = __expf(sacc[nj][0] - mn0);
            sacc[nj][1] = __expf(sacc[nj][1] - mn0);
            sacc[nj][2] = __expf(sacc[nj][2] - mn1);
            sacc[nj][3] = __expf(sacc[nj][3] - mn1);
            ls0 += sacc[nj][0] + sacc[nj][1];
            ls1 += sacc[nj][2] + sacc[nj][3];
        }
        ls0 += __shfl_xor_sync(0xffffffffu, ls0, 1);
        ls0 += __shfl_xor_sync(0xffffffffu, ls0, 2);
        ls1 += __shfl_xor_sync(0xffffffffu, ls1, 1);
        ls1 += __shfl_xor_sync(0xffffffffu, ls1, 2);
        l0r = l0r * corr0 + ls0;
        l1r = l1r * corr1 + ls1;

#pragma unroll
        for (int e = 0; e < 16; e++) {
            Oacc[e][0] *= corr0; Oacc[e][1] *= corr0;
            Oacc[e][2] *= corr1; Oacc[e][3] *= corr1;
        }

        // ---- P -> fp16 A-fragments (4 k16 tiles) ----
        uint32_t phi[4][4];
#pragma unroll
        for (int t = 0; t < 4; t++) {
            phi[t][0] = pack_f2h2(sacc[2 * t][0], sacc[2 * t][1]);
            phi[t][1] = pack_f2h2(sacc[2 * t][2], sacc[2 * t][3]);
            phi[t][2] = pack_f2h2(sacc[2 * t + 1][0], sacc[2 * t + 1][1]);
            phi[t][3] = pack_f2h2(sacc[2 * t + 1][2], sacc[2 * t + 1][3]);
        }

        // ---- O += P V ----
#pragma unroll
        for (int t = 0; t < 4; t++) {
#pragma unroll
            for (int u = 0; u < 8; u++) {
                uint32_t th[4];
                ldm_x4_t(th, sVh + aswz(t * 16 + fr, 2 * u + fs));
                mma_f16(Oacc[2 * u], phi[t], th[0], th[1]);
                mma_f16(Oacc[2 * u + 1], phi[t], th[2], th[3]);
            }
        }
        __syncthreads();
        if (kt + 2 <= kt_end) load_kv(kt + 2);
        else asm volatile("cp.async.commit_group;" ::: "memory");
    }

    // ---- epilogue: normalize + fp16 output ----
    float inv0 = 1.f / l0r, inv1 = 1.f / l1r;
    size_t row0g = (size_t)(b * S_ + row0);
#pragma unroll
    for (int e = 0; e < 16; e++) {
        int colb = h * 128 + e * 8 + (lane & 3) * 2;
        uint32_t hp0 = pack_f2h2(Oacc[e][0] * inv0, Oacc[e][1] * inv0);
        uint32_t hp1 = pack_f2h2(Oacc[e][2] * inv1, Oacc[e][3] * inv1);
        *(uint32_t*)&Ohi[row0g * 2048 + colb] = hp0;
        *(uint32_t*)&Ohi[(row0g + 8) * 2048 + colb] = hp1;
    }
}

// ---------------------------------------------------------------------------
extern "C" void kernel_launch(void* const* d_in, const int* in_sizes, int n_in,
                              void* d_out, int out_size)
{
    const float* residual = (const float*)d_in[0];
    const float* W_Q = (const float*)d_in[1];
    const float* W_K = (const float*)d_in[2];
    const float* W_V = (const float*)d_in[3];
    const float* W_O = (const float*)d_in[4];
    const int* sp = (const int*)d_in[5];

    float* out = (float*)d_out;
    float* k_cache = out + (size_t)B_ * S_ * D_;
    float* v_cache = k_cache + (size_t)B_ * S_ * KVH_ * DH_;

    float* qkv_ptr;
    __half *Ahi, *Whi, *WOhi, *Phi, *Khi, *Vhi;
    cudaGetSymbolAddress((void**)&qkv_ptr, g_qkv);
    cudaGetSymbolAddress((void**)&Ahi, g_Ahi);
    cudaGetSymbolAddress((void**)&Whi, g_Whi);
    cudaGetSymbolAddress((void**)&WOhi, g_WOhi);
    cudaGetSymbolAddress((void**)&Phi, g_Phi);
    cudaGetSymbolAddress((void**)&Khi, g_Khi);
    cudaGetSymbolAddress((void**)&Vhi, g_Vhi);

    cudaFuncSetAttribute(hmma_gemm, cudaFuncAttributeMaxDynamicSharedMemorySize,
                         GEMM_SMEM);
    cudaFuncSetAttribute(attn_mma_kernel, cudaFuncAttributeMaxDynamicSharedMemorySize,
                         ATT2_SMEM);

    // 0) rope table + merged converts (incl. W_O transpose)
    rope_table_kernel<<<S_, 64>>>(sp);
    prep_kernel<<<PREP_BLOCKS, 256>>>(residual, W_Q, W_K, W_V, W_O,
                                      Ahi, Whi, WOhi);

    // 1) fused QKV projection (fp16 single-pass)
    hmma_gemm<<<dim3(NQKV / 128, M_ / 128), 256, GEMM_SMEM>>>(
        Ahi, Whi, qkv_ptr, NQKV);

    // 2) RoPE producer (table-driven; Qhi reuses g_Ahi)
    rope_split_kernel<<<M_, 256>>>(qkv_ptr, k_cache, v_cache,
                                   Ahi, Khi, Vhi);

    // 3) tensor-core attention (fp16, fp32 acc) -> fp16 output
    attn_mma_kernel<<<dim3(S_ / 64, B_ * H_), 128, ATT2_SMEM>>>(
        Ahi, Khi, Vhi, Phi, sp);

    // 4) output projection (fp16 single-pass)
    hmma_gemm<<<dim3(D_ / 128, M_ / 128), 256, GEMM_SMEM>>>(
        Phi, WOhi, out, D_);
}

// round 13
// speedup vs baseline: 1.2388x; 1.0045x over previous
#include <cuda_runtime.h>
#include <cuda_fp16.h>
#include <math.h>
#include <stdint.h>

// Problem constants (fixed shapes from setup_inputs)
#define B_   2
#define S_   2048
#define D_   2048
#define H_   16
#define KVH_ 4
#define DH_  128
#define M_   (B_ * S_)          // 4096
#define NQKV 3072               // 2048 q + 512 k + 512 v

// Scratch (static device arrays; no runtime allocation allowed)
__device__ __half g_Ahi[M_ * D_];     // residual fp16
__device__ __half g_Whi[NQKV * D_];   // W_Q|W_K|W_V rows, fp16
__device__ __half g_WOhi[D_ * D_];    // W_O transposed [d][he], fp16
__device__ __half g_Phi[M_ * D_];     // attention output fp16
__device__ __half g_Qh[M_ * D_];      // roped+scaled Q, fp16
__device__ __half g_Khi[M_ * 512];
__device__ __half g_Vhi[M_ * 512];
__device__ float2 g_rope[S_ * 64];    // per (s, e): (cos, sin)

// ---------------------------------------------------------------------------
// helpers
// ---------------------------------------------------------------------------
__device__ __forceinline__ uint32_t smem_u32(const void* p) {
    uint32_t a;
    asm("{ .reg .u64 t; cvta.to.shared.u64 t, %1; cvt.u32.u64 %0, t; }"
        : "=r"(a) : "l"(p));
    return a;
}

__device__ __forceinline__ void cp16(uint32_t dst, const void* src) {
    asm volatile("cp.async.cg.shared.global [%0], [%1], 16;"
                 :: "r"(dst), "l"(src));
}

__device__ __forceinline__ void ldm_x4(uint32_t* r, uint32_t addr) {
    asm volatile("ldmatrix.sync.aligned.m8n8.x4.shared.b16 {%0,%1,%2,%3}, [%4];"
                 : "=r"(r[0]), "=r"(r[1]), "=r"(r[2]), "=r"(r[3]) : "r"(addr));
}

__device__ __forceinline__ void ldm_x4_t(uint32_t* r, uint32_t addr) {
    asm volatile("ldmatrix.sync.aligned.m8n8.x4.trans.shared.b16 {%0,%1,%2,%3}, [%4];"
                 : "=r"(r[0]), "=r"(r[1]), "=r"(r[2]), "=r"(r[3]) : "r"(addr));
}

__device__ __forceinline__ void mma_f16(float* c, const uint32_t* a,
                                        uint32_t b0, uint32_t b1) {
    asm volatile(
        "mma.sync.aligned.m16n8k16.row.col.f32.f16.f16.f32 "
        "{%0,%1,%2,%3}, {%4,%5,%6,%7}, {%8,%9}, {%0,%1,%2,%3};"
        : "+f"(c[0]), "+f"(c[1]), "+f"(c[2]), "+f"(c[3])
        : "r"(a[0]), "r"(a[1]), "r"(a[2]), "r"(a[3]), "r"(b0), "r"(b1));
}

// swizzled byte offset for a 16B segment (row r, seg s) in a [rows][32]fp16 block
__device__ __forceinline__ uint32_t swz_off(int r, int s) {
    return (uint32_t)(r * 64 + ((s ^ ((r >> 1) & 3)) * 16));
}

// swizzled byte offset for [rows][128 fp16] tiles (256B rows, 16 segs)
__device__ __forceinline__ uint32_t aswz(int r, int sg) {
    return (uint32_t)(r * 256 + ((sg ^ (r & 7)) * 16));
}

__device__ __forceinline__ uint32_t pack_f2h2(float x0, float x1) {
    __half2 p = __floats2half2_rn(x0, x1);
    return *(uint32_t*)&p;
}

// ---------------------------------------------------------------------------
// GEMM core macro body shared by both GEMM kernels (same mainloop as R9/R12)
// ---------------------------------------------------------------------------
#define GEMM_STAGE 16384
#define GEMM_SMEM (4 * GEMM_STAGE)
// qkv variant needs 128*130*4 = 66560 bytes for the epilogue staging
#define QKV_SMEM 66560

// ---------------------------------------------------------------------------
// GEMM (plain): C fp32, used for the output projection.
// ---------------------------------------------------------------------------
__global__ __launch_bounds__(256, 2) void hmma_gemm(
    const __half* __restrict__ Ah, const __half* __restrict__ Bh,
    float* __restrict__ C, int ldc)
{
    extern __shared__ char smem[];
    uint32_t sb = smem_u32(smem);

    int tid = threadIdx.x;
    int lane = tid & 31;
    int warp = tid >> 5;
    int warp_m = warp & 3;
    int warp_n = warp >> 2;
    int m0 = blockIdx.y * 128;
    int n0 = blockIdx.x * 128;

    int q = lane >> 3;
    int lrow = lane & 7;
    int arow_l = (q & 1) * 8 + lrow;
    int ksel = q >> 1;

    float acc[2][8][4];
#pragma unroll
    for (int i = 0; i < 2; i++)
#pragma unroll
        for (int j = 0; j < 8; j++)
#pragma unroll
            for (int k = 0; k < 4; k++) acc[i][j][k] = 0.f;

    auto load_chunk = [&](int c) {
        int k0 = c * 32;
        uint32_t buf = sb + (uint32_t)(c & 3) * GEMM_STAGE;
#pragma unroll
        for (int t = 0; t < 4; t++) {
            int g = tid + t * 256;
            int mat = g >> 9;
            int inner = g & 511;
            int r = inner >> 2;
            int s = inner & 3;
            const __half* base = mat ? Bh : Ah;
            int row = (mat ? n0 : m0) + r;
            const void* src = base + (size_t)row * 2048 + k0 + s * 8;
            cp16(buf + (uint32_t)mat * 8192u + swz_off(r, s), src);
        }
        asm volatile("cp.async.commit_group;" ::: "memory");
    };

    load_chunk(0);
    load_chunk(1);
    load_chunk(2);
    load_chunk(3);

    for (int c = 0; c < 64; c++) {
        asm volatile("cp.async.wait_group 3;" ::: "memory");
        __syncthreads();

        uint32_t buf = sb + (uint32_t)(c & 3) * GEMM_STAGE;
        uint32_t bAh = buf, bBh = buf + 8192;

#pragma unroll
        for (int ks = 0; ks < 2; ks++) {
            int s = ks * 2 + ksel;
            uint32_t ah[2][4];
#pragma unroll
            for (int mi = 0; mi < 2; mi++) {
                int r = warp_m * 32 + mi * 16 + arow_l;
                ldm_x4(ah[mi], bAh + swz_off(r, s));
            }
            uint32_t bh[8][2];
#pragma unroll
            for (int j = 0; j < 4; j++) {
                int r = warp_n * 64 + j * 16 + arow_l;
                uint32_t t4[4];
                ldm_x4(t4, bBh + swz_off(r, s));
                bh[j * 2 + 0][0] = t4[0]; bh[j * 2 + 0][1] = t4[2];
                bh[j * 2 + 1][0] = t4[1]; bh[j * 2 + 1][1] = t4[3];
            }
#pragma unroll
            for (int mi = 0; mi < 2; mi++) {
#pragma unroll
                for (int nj = 0; nj < 8; nj++)
                    mma_f16(acc[mi][nj], ah[mi], bh[nj][0], bh[nj][1]);
            }
        }
        __syncthreads();
        if (c + 4 < 64) load_chunk(c + 4);
        else asm volatile("cp.async.commit_group;" ::: "memory");
    }

    int rr = lane >> 2;
    int cc = (lane & 3) * 2;
#pragma unroll
    for (int mi = 0; mi < 2; mi++) {
        int r1 = m0 + warp_m * 32 + mi * 16 + rr;
#pragma unroll
        for (int nj = 0; nj < 8; nj++) {
            int col = n0 + warp_n * 64 + nj * 8 + cc;
            float2 v0 = make_float2(acc[mi][nj][0], acc[mi][nj][1]);
            float2 v1 = make_float2(acc[mi][nj][2], acc[mi][nj][3]);
            *(float2*)&C[(size_t)r1 * ldc + col] = v0;
            *(float2*)&C[(size_t)(r1 + 8) * ldc + col] = v1;
        }
    }
}

// ---------------------------------------------------------------------------
// GEMM + fused RoPE epilogue for the QKV projection.
// Tile n index = head: [0,16) q, [16,20) k, [20,24) v.
// Epilogue stages acc in smem (128x130 fp32), applies rope from g_rope, and
// writes finals: Q->g_Qh (fp16, scaled), K->kc fp32 + Khi fp16, V->vc + Vhi.
// ---------------------------------------------------------------------------
__global__ __launch_bounds__(256, 2) void hmma_gemm_qkv(
    const __half* __restrict__ Ah, const __half* __restrict__ Bh,
    __half* __restrict__ Qh,
    float* __restrict__ kc, __half* __restrict__ Khi,
    float* __restrict__ vc, __half* __restrict__ Vhi)
{
    extern __shared__ char smem[];
    uint32_t sb = smem_u32(smem);

    int tid = threadIdx.x;
    int lane = tid & 31;
    int warp = tid >> 5;
    int warp_m = warp & 3;
    int warp_n = warp >> 2;
    int m0 = blockIdx.y * 128;
    int n0 = blockIdx.x * 128;

    int q = lane >> 3;
    int lrow = lane & 7;
    int arow_l = (q & 1) * 8 + lrow;
    int ksel = q >> 1;

    float acc[2][8][4];
#pragma unroll
    for (int i = 0; i < 2; i++)
#pragma unroll
        for (int j = 0; j < 8; j++)
#pragma unroll
            for (int k = 0; k < 4; k++) acc[i][j][k] = 0.f;

    auto load_chunk = [&](int c) {
        int k0 = c * 32;
        uint32_t buf = sb + (uint32_t)(c & 3) * GEMM_STAGE;
#pragma unroll
        for (int t = 0; t < 4; t++) {
            int g = tid + t * 256;
            int mat = g >> 9;
            int inner = g & 511;
            int r = inner >> 2;
            int s = inner & 3;
            const __half* base = mat ? Bh : Ah;
            int row = (mat ? n0 : m0) + r;
            const void* src = base + (size_t)row * 2048 + k0 + s * 8;
            cp16(buf + (uint32_t)mat * 8192u + swz_off(r, s), src);
        }
        asm volatile("cp.async.commit_group;" ::: "memory");
    };

    load_chunk(0);
    load_chunk(1);
    load_chunk(2);
    load_chunk(3);

    for (int c = 0; c < 64; c++) {
        asm volatile("cp.async.wait_group 3;" ::: "memory");
        __syncthreads();

        uint32_t buf = sb + (uint32_t)(c & 3) * GEMM_STAGE;
        uint32_t bAh = buf, bBh = buf + 8192;

#pragma unroll
        for (int ks = 0; ks < 2; ks++) {
            int s = ks * 2 + ksel;
            uint32_t ah[2][4];
#pragma unroll
            for (int mi = 0; mi < 2; mi++) {
                int r = warp_m * 32 + mi * 16 + arow_l;
                ldm_x4(ah[mi], bAh + swz_off(r, s));
            }
            uint32_t bh[8][2];
#pragma unroll
            for (int j = 0; j < 4; j++) {
                int r = warp_n * 64 + j * 16 + arow_l;
                uint32_t t4[4];
                ldm_x4(t4, bBh + swz_off(r, s));
                bh[j * 2 + 0][0] = t4[0]; bh[j * 2 + 0][1] = t4[2];
                bh[j * 2 + 1][0] = t4[1]; bh[j * 2 + 1][1] = t4[3];
            }
#pragma unroll
            for (int mi = 0; mi < 2; mi++) {
#pragma unroll
                for (int nj = 0; nj < 8; nj++)
                    mma_f16(acc[mi][nj], ah[mi], bh[nj][0], bh[nj][1]);
            }
        }
        __syncthreads();
        if (c + 4 < 64) load_chunk(c + 4);
        else asm volatile("cp.async.commit_group;" ::: "memory");
    }
    // last compute iteration ended with __syncthreads(); smem is free now

    // ---- stage acc into smem fp32 [128][130] ----
    float* sm = (float*)smem;
    int rr = lane >> 2;
    int cc = (lane & 3) * 2;
#pragma unroll
    for (int mi = 0; mi < 2; mi++) {
        int rl = warp_m * 32 + mi * 16 + rr;
#pragma unroll
        for (int nj = 0; nj < 8; nj++) {
            int col = warp_n * 64 + nj * 8 + cc;
            *(float2*)&sm[rl * 130 + col] =
                make_float2(acc[mi][nj][0], acc[mi][nj][1]);
            *(float2*)&sm[(rl + 8) * 130 + col] =
                make_float2(acc[mi][nj][2], acc[mi][nj][3]);
        }
    }
    __syncthreads();

    // ---- fused rope / convert / scatter ----
    const float scale = 0.08838834764831845f;  // 1/sqrt(128)
    int tile = blockIdx.x;                      // 0..23
#pragma unroll
    for (int i = 0; i < 16; i++) {
        int idx = tid + i * 256;    // 0..4095
        int r = idx >> 5;           // 0..127
        int e2 = (idx & 31) * 2;    // 0..62 step 2
        int m = m0 + r;
        float2 x1 = *(float2*)&sm[r * 130 + e2];
        float2 x2 = *(float2*)&sm[r * 130 + e2 + 64];
        if (tile < 20) {
            const float2* rp = g_rope + (size_t)(m & (S_ - 1)) * 64 + e2;
            float2 r0 = rp[0], r1 = rp[1];
            float ya0 = x1.x * r0.x - x2.x * r0.y;
            float ya1 = x1.y * r1.x - x2.y * r1.y;
            float yb0 = x1.x * r0.y + x2.x * r0.x;
            float yb1 = x1.y * r1.y + x2.y * r1.x;
            if (tile < 16) {
                // q head: scale + fp16
                size_t o = (size_t)m * 2048 + tile * 128 + e2;
                *(uint32_t*)&Qh[o]      = pack_f2h2(ya0 * scale, ya1 * scale);
                *(uint32_t*)&Qh[o + 64] = pack_f2h2(yb0 * scale, yb1 * scale);
            } else {
                // k head: fp32 cache + fp16
                int h = tile - 16;
                size_t o = (size_t)m * 512 + h * 128 + e2;
                *(float2*)&kc[o]      = make_float2(ya0, ya1);
                *(float2*)&kc[o + 64] = make_float2(yb0, yb1);
                *(uint32_t*)&Khi[o]      = pack_f2h2(ya0, ya1);
                *(uint32_t*)&Khi[o + 64] = pack_f2h2(yb0, yb1);
            }
        } else {
            // v head: plain copy
            int h = tile - 20;
            size_t o = (size_t)m * 512 + h * 128 + e2;
            *(float2*)&vc[o]      = x1;
            *(float2*)&vc[o + 64] = x2;
            *(uint32_t*)&Vhi[o]      = pack_f2h2(x1.x, x1.y);
            *(uint32_t*)&Vhi[o + 64] = pack_f2h2(x2.x, x2.y);
        }
    }
}

// ---------------------------------------------------------------------------
// Rope table: per (s, e) pair -> (cos, sin) of (sp+s)*invfreq(e)
// ---------------------------------------------------------------------------
__global__ __launch_bounds__(64) void rope_table_kernel(const int* __restrict__ sp_ptr)
{
    const float LOG2_BASE_OVER_HALF = 13.287712379549449f / 64.0f;
    int s = blockIdx.x;
    int e = threadIdx.x;
    float pos = (float)(*sp_ptr + s);
    float inv = exp2f(-(float)e * LOG2_BASE_OVER_HALF);
    float sn, cs;
    sincosf(pos * inv, &sn, &cs);
    g_rope[s * 64 + e] = make_float2(cs, sn);
}

// ---------------------------------------------------------------------------
// Merged prep: fp32 -> fp16 for residual + W_Q + W_K + W_V, plus the
// W_O transpose+convert, in ONE launch.
// ---------------------------------------------------------------------------
#define N4_RES  (M_ * D_ / 4)
#define N4_WQ   (2048 * 2048 / 4)
#define N4_WK   (512 * 2048 / 4)
#define N4_ALL  (N4_RES + N4_WQ + 2 * N4_WK)
#define PREP_EW_BLOCKS ((N4_ALL + 255) / 256)
#define PREP_TR_BLOCKS (64 * 64)
#define PREP_BLOCKS (PREP_EW_BLOCKS + PREP_TR_BLOCKS)

__global__ __launch_bounds__(256) void prep_kernel(
    const float* __restrict__ residual, const float* __restrict__ WQ,
    const float* __restrict__ WK, const float* __restrict__ WV,
    const float* __restrict__ WO,
    __half* __restrict__ Ahi, __half* __restrict__ Whi,
    __half* __restrict__ WOhi)
{
    if (blockIdx.x < PREP_EW_BLOCKS) {
        int i = blockIdx.x * 256 + threadIdx.x;
        if (i >= N4_ALL) return;
        const float* src;
        __half* dst;
        int j = i;
        if (j < N4_RES) {
            src = residual; dst = Ahi;
        } else if ((j -= N4_RES) < N4_WQ) {
            src = WQ; dst = Whi;
        } else if ((j -= N4_WQ) < N4_WK) {
            src = WK; dst = Whi + (size_t)2048 * 2048;
        } else {
            j -= N4_WK;
            src = WV; dst = Whi + (size_t)2560 * 2048;
        }
        float4 v = ((const float4*)src)[j];
        ushort4 hv = make_ushort4(
            __half_as_ushort(__float2half_rn(v.x)),
            __half_as_ushort(__float2half_rn(v.y)),
            __half_as_ushort(__float2half_rn(v.z)),
            __half_as_ushort(__float2half_rn(v.w)));
        ((ushort4*)dst)[j] = hv;
    } else {
        __shared__ float t[32][33];
        int bid = blockIdx.x - PREP_EW_BLOCKS;
        int bx = (bid & 63) * 32;
        int by = (bid >> 6) * 32;
        int x = threadIdx.x & 31;
        int y0 = threadIdx.x >> 5;
#pragma unroll
        for (int i = 0; i < 32; i += 8)
            t[y0 + i][x] = WO[(size_t)(by + y0 + i) * 2048 + bx + x];
        __syncthreads();
#pragma unroll
        for (int i = 0; i < 32; i += 8) {
            float v = t[x][y0 + i];
            WOhi[(size_t)(bx + y0 + i) * 2048 + by + x] = __float2half_rn(v);
        }
    }
}

// ---------------------------------------------------------------------------
// Tensor-core flash attention (unchanged mainloop from R12).
// ---------------------------------------------------------------------------
#define ATT_KV_STAGE 32768
#define ATT2_SMEM (16384 + 2 * ATT_KV_STAGE)

__global__ __launch_bounds__(128, 2) void attn_mma_kernel(
    const __half* __restrict__ Qhi,
    const __half* __restrict__ Khi, const __half* __restrict__ Vhi,
    __half* __restrict__ Ohi,
    const int* __restrict__ sp_ptr)
{
    extern __shared__ char smem[];
    uint32_t sb = smem_u32(smem);
    const uint32_t sQh = sb;
    const uint32_t sKV = sb + 16384;

    int tid = threadIdx.x;
    int lane = tid & 31;
    int warp = tid >> 5;
    int bh = blockIdx.y;
    int b = bh >> 4, h = bh & 15, kvh = h >> 2;
    int q0 = blockIdx.x * 64;
    int sp = *sp_ptr;
    float slope = exp2f(-0.5f * (float)(h + 1));

    int fr = ((lane >> 3) & 1) * 8 + (lane & 7);
    int fs = lane >> 4;

    int kt_end = (sp + q0 + 63) >> 6;
    if (kt_end > S_ / 64 - 1) kt_end = S_ / 64 - 1;

    auto load_kv = [&](int kt) {
        int k0 = (kt <= kt_end ? kt : kt_end) * 64;
        uint32_t stage = sKV + (uint32_t)(kt & 1) * ATT_KV_STAGE;
#pragma unroll
        for (int i = 0; i < 16; i++) {
            int idx = tid + i * 128;
            int t = idx >> 10;
            int inner = idx & 1023;
            int r = inner >> 4, sg = inner & 15;
            const __half* basep = t ? Vhi : Khi;
            const __half* src =
                basep + (size_t)(b * S_ + k0 + r) * 512 + kvh * 128 + sg * 8;
            cp16(stage + (uint32_t)t * 16384u + aswz(r, sg), src);
        }
        asm volatile("cp.async.commit_group;" ::: "memory");
    };

#pragma unroll
    for (int i = 0; i < 8; i++) {
        int idx = tid + i * 128;
        int r = idx >> 4, sg = idx & 15;
        const __half* src = Qhi
            + (size_t)(b * S_ + q0 + r) * 2048 + h * 128 + sg * 8;
        cp16(sQh + aswz(r, sg), src);
    }
    asm volatile("cp.async.commit_group;" ::: "memory");
    load_kv(0);
    load_kv(1);

    asm volatile("cp.async.wait_group 2;" ::: "memory");
    __syncthreads();
    uint32_t qh[8][4];
#pragma unroll
    for (int s = 0; s < 8; s++)
        ldm_x4(qh[s], sQh + aswz(warp * 16 + fr, 2 * s + fs));

    float Oacc[16][4];
#pragma unroll
    for (int e = 0; e < 16; e++)
#pragma unroll
        for (int k = 0; k < 4; k++) Oacc[e][k] = 0.f;
    float m0r = -1e30f, m1r = -1e30f;
    float l0r = 0.f, l1r = 0.f;

    int row0 = q0 + warp * 16 + (lane >> 2);
    int qp0 = sp + row0, qp1 = qp0 + 8;

    for (int kt = 0; kt <= kt_end; kt++) {
        int k0 = kt * 64;
        asm volatile("cp.async.wait_group 1;" ::: "memory");
        __syncthreads();

        uint32_t stage = sKV + (uint32_t)(kt & 1) * ATT_KV_STAGE;
        uint32_t sKh = stage, sVh = stage + 16384;

        float sacc[8][4];
#pragma unroll
        for (int nj = 0; nj < 8; nj++)
#pragma unroll
            for (int k = 0; k < 4; k++) sacc[nj][k] = 0.f;

#pragma unroll
        for (int s = 0; s < 8; s++) {
            uint32_t kbh[8][2], t4[4];
#pragma unroll
            for (int j = 0; j < 4; j++) {
                ldm_x4(t4, sKh + aswz(j * 16 + fr, 2 * s + fs));
                kbh[2 * j][0] = t4[0]; kbh[2 * j][1] = t4[2];
                kbh[2 * j + 1][0] = t4[1]; kbh[2 * j + 1][1] = t4[3];
            }
#pragma unroll
            for (int nj = 0; nj < 8; nj++)
                mma_f16(sacc[nj], qh[s], kbh[nj][0], kbh[nj][1]);
        }

        if (k0 + 63 <= sp + q0) {
#pragma unroll
            for (int nj = 0; nj < 8; nj++) {
                int c = k0 + nj * 8 + (lane & 3) * 2;
                sacc[nj][0] -= slope * (float)(qp0 - c);
                sacc[nj][1] -= slope * (float)(qp0 - c - 1);
                sacc[nj][2] -= slope * (float)(qp1 - c);
                sacc[nj][3] -= slope * (float)(qp1 - c - 1);
            }
        } else {
#pragma unroll
            for (int nj = 0; nj < 8; nj++) {
                int c = k0 + nj * 8 + (lane & 3) * 2;
                sacc[nj][0] = (c     <= qp0) ? sacc[nj][0] - slope * (float)(qp0 - c)     : -1e30f;
                sacc[nj][1] = (c + 1 <= qp0) ? sacc[nj][1] - slope * (float)(qp0 - c - 1) : -1e30f;
                sacc[nj][2] = (c     <= qp1) ? sacc[nj][2] - slope * (float)(qp1 - c)     : -1e30f;
                sacc[nj][3] = (c + 1 <= qp1) ? sacc[nj][3] - slope * (float)(qp1 - c - 1) : -1e30f;
            }
        }

        float mx0 = -1e30f, mx1 = -1e30f;
#pragma unroll
        for (int nj = 0; nj < 8; nj++) {
            mx0 = fmaxf(mx0, fmaxf(sacc[nj][0], sacc[nj][1]));
            mx1 = fmaxf(mx1, fmaxf(sacc[nj][2], sacc[nj][3]));
        }
        mx0 = fmaxf(mx0, __shfl_xor_sync(0xffffffffu, mx0, 1));
        mx0 = fmaxf(mx0, __shfl_xor_sync(0xffffffffu, mx0, 2));
        mx1 = fmaxf(mx1, __shfl_xor_sync(0xffffffffu, mx1, 1));
        mx1 = fmaxf(mx1, __shfl_xor_sync(0xffffffffu, mx1, 2));
        float mn0 = fmaxf(m0r, mx0), mn1 = fmaxf(m1r, mx1);
        float corr0 = __expf(m0r - mn0), corr1 = __expf(m1r - mn1);
        m0r = mn0; m1r = mn1;

        float ls0 = 0.f, ls1 = 0.f;
#pragma unroll
        for (int nj = 0; nj < 8; nj++) {
            sacc[nj][0] = __expf(sacc[nj][0] - mn0);
            sacc[nj][1] = __expf(sacc[nj][1] - mn0);
            sacc[nj][2] = __expf(sacc[nj][2] - mn1);
            sacc[nj][3] = __expf(sacc[nj][3] - mn1);
            ls0 += sacc[nj][0] + sacc[nj][1];
            ls1 += sacc[nj][2] + sacc[nj][3];
        }
        ls0 += __shfl_xor_sync(0xffffffffu, ls0, 1);
        ls0 += __shfl_xor_sync(0xffffffffu, ls0, 2);
        ls1 += __shfl_xor_sync(0xffffffffu, ls1, 1);
        ls1 += __shfl_xor_sync(0xffffffffu, ls1, 2);
        l0r = l0r * corr0 + ls0;
        l1r = l1r * corr1 + ls1;

#pragma unroll
        for (int e = 0; e < 16; e++) {
            Oacc[e][0] *= corr0; Oacc[e][1] *= corr0;
            Oacc[e][2] *= corr1; Oacc[e][3] *= corr1;
        }

        uint32_t phi[4][4];
#pragma unroll
        for (int t = 0; t < 4; t++) {
            phi[t][0] = pack_f2h2(sacc[2 * t][0], sacc[2 * t][1]);
            phi[t][1] = pack_f2h2(sacc[2 * t][2], sacc[2 * t][3]);
            phi[t][2] = pack_f2h2(sacc[2 * t + 1][0], sacc[2 * t + 1][1]);
            phi[t][3] = pack_f2h2(sacc[2 * t + 1][2], sacc[2 * t + 1][3]);
        }

#pragma unroll
        for (int t = 0; t < 4; t++) {
#pragma unroll
            for (int u = 0; u < 8; u++) {
                uint32_t th[4];
                ldm_x4_t(th, sVh + aswz(t * 16 + fr, 2 * u + fs));
                mma_f16(Oacc[2 * u], phi[t], th[0], th[1]);
                mma_f16(Oacc[2 * u + 1], phi[t], th[2], th[3]);
            }
        }
        __syncthreads();
        if (kt + 2 <= kt_end) load_kv(kt + 2);
        else asm volatile("cp.async.commit_group;" ::: "memory");
    }

    float inv0 = 1.f / l0r, inv1 = 1.f / l1r;
    size_t row0g = (size_t)(b * S_ + row0);
#pragma unroll
    for (int e = 0; e < 16; e++) {
        int colb = h * 128 + e * 8 + (lane & 3) * 2;
        uint32_t hp0 = pack_f2h2(Oacc[e][0] * inv0, Oacc[e][1] * inv0);
        uint32_t hp1 = pack_f2h2(Oacc[e][2] * inv1, Oacc[e][3] * inv1);
        *(uint32_t*)&Ohi[row0g * 2048 + colb] = hp0;
        *(uint32_t*)&Ohi[(row0g + 8) * 2048 + colb] = hp1;
    }
}

// ---------------------------------------------------------------------------
extern "C" void kernel_launch(void* const* d_in, const int* in_sizes, int n_in,
                              void* d_out, int out_size)
{
    const float* residual = (const float*)d_in[0];
    const float* W_Q = (const float*)d_in[1];
    const float* W_K = (const float*)d_in[2];
    const float* W_V = (const float*)d_in[3];
    const float* W_O = (const float*)d_in[4];
    const int* sp = (const int*)d_in[5];

    float* out = (float*)d_out;
    float* k_cache = out + (size_t)B_ * S_ * D_;
    float* v_cache = k_cache + (size_t)B_ * S_ * KVH_ * DH_;

    __half *Ahi, *Whi, *WOhi, *Phi, *Qh, *Khi, *Vhi;
    cudaGetSymbolAddress((void**)&Ahi, g_Ahi);
    cudaGetSymbolAddress((void**)&Whi, g_Whi);
    cudaGetSymbolAddress((void**)&WOhi, g_WOhi);
    cudaGetSymbolAddress((void**)&Phi, g_Phi);
    cudaGetSymbolAddress((void**)&Qh, g_Qh);
    cudaGetSymbolAddress((void**)&Khi, g_Khi);
    cudaGetSymbolAddress((void**)&Vhi, g_Vhi);

    cudaFuncSetAttribute(hmma_gemm, cudaFuncAttributeMaxDynamicSharedMemorySize,
                         GEMM_SMEM);
    cudaFuncSetAttribute(hmma_gemm_qkv, cudaFuncAttributeMaxDynamicSharedMemorySize,
                         QKV_SMEM);
    cudaFuncSetAttribute(attn_mma_kernel, cudaFuncAttributeMaxDynamicSharedMemorySize,
                         ATT2_SMEM);

    // 0) rope table + merged converts (incl. W_O transpose)
    rope_table_kernel<<<S_, 64>>>(sp);
    prep_kernel<<<PREP_BLOCKS, 256>>>(residual, W_Q, W_K, W_V, W_O,
                                      Ahi, Whi, WOhi);

    // 1) fused QKV projection + rope epilogue
    hmma_gemm_qkv<<<dim3(NQKV / 128, M_ / 128), 256, QKV_SMEM>>>(
        Ahi, Whi, Qh, k_cache, Khi, v_cache, Vhi);

    // 2) tensor-core attention (fp16, fp32 acc) -> fp16 output
    attn_mma_kernel<<<dim3(S_ / 64, B_ * H_), 128, ATT2_SMEM>>>(
        Qh, Khi, Vhi, Phi, sp);

    // 3) output projection (fp16 single-pass)
    hmma_gemm<<<dim3(D_ / 128, M_ / 128), 256, GEMM_SMEM>>>(
        Phi, WOhi, out, D_);
}

// round 14
// speedup vs baseline: 1.2610x; 1.0179x over previous
#include <cuda_runtime.h>
#include <cuda_fp16.h>
#include <math.h>
#include <stdint.h>

// Problem constants (fixed shapes from setup_inputs)
#define B_   2
#define S_   2048
#define D_   2048
#define H_   16
#define KVH_ 4
#define DH_  128
#define M_   (B_ * S_)          // 4096
#define NQKV 3072               // 2048 q + 512 k + 512 v

// Scratch (static device arrays; no runtime allocation allowed)
__device__ __half g_Ahi[M_ * D_];     // residual fp16
__device__ __half g_Whi[NQKV * D_];   // W_Q|W_K|W_V rows, fp16
__device__ __half g_WOhi[D_ * D_];    // W_O transposed [d][he], fp16
__device__ __half g_Phi[M_ * D_];     // attention output fp16
__device__ __half g_Qh[M_ * D_];      // roped+scaled Q, fp16
__device__ __half g_Khi[M_ * 512];
__device__ __half g_Vhi[M_ * 512];
__device__ float2 g_rope[S_ * 64];    // per (s, e): (cos, sin)

// ---------------------------------------------------------------------------
// helpers
// ---------------------------------------------------------------------------
__device__ __forceinline__ uint32_t smem_u32(const void* p) {
    uint32_t a;
    asm("{ .reg .u64 t; cvta.to.shared.u64 t, %1; cvt.u32.u64 %0, t; }"
        : "=r"(a) : "l"(p));
    return a;
}

__device__ __forceinline__ void cp16(uint32_t dst, const void* src) {
    asm volatile("cp.async.cg.shared.global [%0], [%1], 16;"
                 :: "r"(dst), "l"(src));
}

__device__ __forceinline__ void ldm_x4(uint32_t* r, uint32_t addr) {
    asm volatile("ldmatrix.sync.aligned.m8n8.x4.shared.b16 {%0,%1,%2,%3}, [%4];"
                 : "=r"(r[0]), "=r"(r[1]), "=r"(r[2]), "=r"(r[3]) : "r"(addr));
}

__device__ __forceinline__ void ldm_x4_t(uint32_t* r, uint32_t addr) {
    asm volatile("ldmatrix.sync.aligned.m8n8.x4.trans.shared.b16 {%0,%1,%2,%3}, [%4];"
                 : "=r"(r[0]), "=r"(r[1]), "=r"(r[2]), "=r"(r[3]) : "r"(addr));
}

__device__ __forceinline__ void mma_f16(float* c, const uint32_t* a,
                                        uint32_t b0, uint32_t b1) {
    asm volatile(
        "mma.sync.aligned.m16n8k16.row.col.f32.f16.f16.f32 "
        "{%0,%1,%2,%3}, {%4,%5,%6,%7}, {%8,%9}, {%0,%1,%2,%3};"
        : "+f"(c[0]), "+f"(c[1]), "+f"(c[2]), "+f"(c[3])
        : "r"(a[0]), "r"(a[1]), "r"(a[2]), "r"(a[3]), "r"(b0), "r"(b1));
}

// swizzled byte offset for a 16B segment (row r, seg s) in a [rows][32]fp16 block
__device__ __forceinline__ uint32_t swz_off(int r, int s) {
    return (uint32_t)(r * 64 + ((s ^ ((r >> 1) & 3)) * 16));
}

// swizzled byte offset for [rows][128 fp16] tiles (256B rows, 16 segs)
__device__ __forceinline__ uint32_t aswz(int r, int sg) {
    return (uint32_t)(r * 256 + ((sg ^ (r & 7)) * 16));
}

__device__ __forceinline__ uint32_t pack_f2h2(float x0, float x1) {
    __half2 p = __floats2half2_rn(x0, x1);
    return *(uint32_t*)&p;
}

#define GEMM_STAGE 16384
#define GEMM_SMEM (4 * GEMM_STAGE)
#define QKV_SMEM 66560

// ---------------------------------------------------------------------------
// GEMM (plain): C fp32, used for the output projection. (R13 exact)
// ---------------------------------------------------------------------------
__global__ __launch_bounds__(256, 2) void hmma_gemm(
    const __half* __restrict__ Ah, const __half* __restrict__ Bh,
    float* __restrict__ C, int ldc)
{
    extern __shared__ char smem[];
    uint32_t sb = smem_u32(smem);

    int tid = threadIdx.x;
    int lane = tid & 31;
    int warp = tid >> 5;
    int warp_m = warp & 3;
    int warp_n = warp >> 2;
    int m0 = blockIdx.y * 128;
    int n0 = blockIdx.x * 128;

    int q = lane >> 3;
    int lrow = lane & 7;
    int arow_l = (q & 1) * 8 + lrow;
    int ksel = q >> 1;

    float acc[2][8][4];
#pragma unroll
    for (int i = 0; i < 2; i++)
#pragma unroll
        for (int j = 0; j < 8; j++)
#pragma unroll
            for (int k = 0; k < 4; k++) acc[i][j][k] = 0.f;

    auto load_chunk = [&](int c) {
        int k0 = c * 32;
        uint32_t buf = sb + (uint32_t)(c & 3) * GEMM_STAGE;
#pragma unroll
        for (int t = 0; t < 4; t++) {
            int g = tid + t * 256;
            int mat = g >> 9;
            int inner = g & 511;
            int r = inner >> 2;
            int s = inner & 3;
            const __half* base = mat ? Bh : Ah;
            int row = (mat ? n0 : m0) + r;
            const void* src = base + (size_t)row * 2048 + k0 + s * 8;
            cp16(buf + (uint32_t)mat * 8192u + swz_off(r, s), src);
        }
        asm volatile("cp.async.commit_group;" ::: "memory");
    };

    load_chunk(0);
    load_chunk(1);
    load_chunk(2);
    load_chunk(3);

    for (int c = 0; c < 64; c++) {
        asm volatile("cp.async.wait_group 3;" ::: "memory");
        __syncthreads();

        uint32_t buf = sb + (uint32_t)(c & 3) * GEMM_STAGE;
        uint32_t bAh = buf, bBh = buf + 8192;

#pragma unroll
        for (int ks = 0; ks < 2; ks++) {
            int s = ks * 2 + ksel;
            uint32_t ah[2][4];
#pragma unroll
            for (int mi = 0; mi < 2; mi++) {
                int r = warp_m * 32 + mi * 16 + arow_l;
                ldm_x4(ah[mi], bAh + swz_off(r, s));
            }
            uint32_t bh[8][2];
#pragma unroll
            for (int j = 0; j < 4; j++) {
                int r = warp_n * 64 + j * 16 + arow_l;
                uint32_t t4[4];
                ldm_x4(t4, bBh + swz_off(r, s));
                bh[j * 2 + 0][0] = t4[0]; bh[j * 2 + 0][1] = t4[2];
                bh[j * 2 + 1][0] = t4[1]; bh[j * 2 + 1][1] = t4[3];
            }
#pragma unroll
            for (int mi = 0; mi < 2; mi++) {
#pragma unroll
                for (int nj = 0; nj < 8; nj++)
                    mma_f16(acc[mi][nj], ah[mi], bh[nj][0], bh[nj][1]);
            }
        }
        __syncthreads();
        if (c + 4 < 64) load_chunk(c + 4);
        else asm volatile("cp.async.commit_group;" ::: "memory");
    }

    int rr = lane >> 2;
    int cc = (lane & 3) * 2;
#pragma unroll
    for (int mi = 0; mi < 2; mi++) {
        int r1 = m0 + warp_m * 32 + mi * 16 + rr;
#pragma unroll
        for (int nj = 0; nj < 8; nj++) {
            int col = n0 + warp_n * 64 + nj * 8 + cc;
            float2 v0 = make_float2(acc[mi][nj][0], acc[mi][nj][1]);
            float2 v1 = make_float2(acc[mi][nj][2], acc[mi][nj][3]);
            *(float2*)&C[(size_t)r1 * ldc + col] = v0;
            *(float2*)&C[(size_t)(r1 + 8) * ldc + col] = v1;
        }
    }
}

// ---------------------------------------------------------------------------
// GEMM + fused RoPE epilogue for the QKV projection. (R13 exact)
// ---------------------------------------------------------------------------
__global__ __launch_bounds__(256, 2) void hmma_gemm_qkv(
    const __half* __restrict__ Ah, const __half* __restrict__ Bh,
    __half* __restrict__ Qh,
    float* __restrict__ kc, __half* __restrict__ Khi,
    float* __restrict__ vc, __half* __restrict__ Vhi)
{
    extern __shared__ char smem[];
    uint32_t sb = smem_u32(smem);

    int tid = threadIdx.x;
    int lane = tid & 31;
    int warp = tid >> 5;
    int warp_m = warp & 3;
    int warp_n = warp >> 2;
    int m0 = blockIdx.y * 128;
    int n0 = blockIdx.x * 128;

    int q = lane >> 3;
    int lrow = lane & 7;
    int arow_l = (q & 1) * 8 + lrow;
    int ksel = q >> 1;

    float acc[2][8][4];
#pragma unroll
    for (int i = 0; i < 2; i++)
#pragma unroll
        for (int j = 0; j < 8; j++)
#pragma unroll
            for (int k = 0; k < 4; k++) acc[i][j][k] = 0.f;

    auto load_chunk = [&](int c) {
        int k0 = c * 32;
        uint32_t buf = sb + (uint32_t)(c & 3) * GEMM_STAGE;
#pragma unroll
        for (int t = 0; t < 4; t++) {
            int g = tid + t * 256;
            int mat = g >> 9;
            int inner = g & 511;
            int r = inner >> 2;
            int s = inner & 3;
            const __half* base = mat ? Bh : Ah;
            int row = (mat ? n0 : m0) + r;
            const void* src = base + (size_t)row * 2048 + k0 + s * 8;
            cp16(buf + (uint32_t)mat * 8192u + swz_off(r, s), src);
        }
        asm volatile("cp.async.commit_group;" ::: "memory");
    };

    load_chunk(0);
    load_chunk(1);
    load_chunk(2);
    load_chunk(3);

    for (int c = 0; c < 64; c++) {
        asm volatile("cp.async.wait_group 3;" ::: "memory");
        __syncthreads();

        uint32_t buf = sb + (uint32_t)(c & 3) * GEMM_STAGE;
        uint32_t bAh = buf, bBh = buf + 8192;

#pragma unroll
        for (int ks = 0; ks < 2; ks++) {
            int s = ks * 2 + ksel;
            uint32_t ah[2][4];
#pragma unroll
            for (int mi = 0; mi < 2; mi++) {
                int r = warp_m * 32 + mi * 16 + arow_l;
                ldm_x4(ah[mi], bAh + swz_off(r, s));
            }
            uint32_t bh[8][2];
#pragma unroll
            for (int j = 0; j < 4; j++) {
                int r = warp_n * 64 + j * 16 + arow_l;
                uint32_t t4[4];
                ldm_x4(t4, bBh + swz_off(r, s));
                bh[j * 2 + 0][0] = t4[0]; bh[j * 2 + 0][1] = t4[2];
                bh[j * 2 + 1][0] = t4[1]; bh[j * 2 + 1][1] = t4[3];
            }
#pragma unroll
            for (int mi = 0; mi < 2; mi++) {
#pragma unroll
                for (int nj = 0; nj < 8; nj++)
                    mma_f16(acc[mi][nj], ah[mi], bh[nj][0], bh[nj][1]);
            }
        }
        __syncthreads();
        if (c + 4 < 64) load_chunk(c + 4);
        else asm volatile("cp.async.commit_group;" ::: "memory");
    }

    // ---- stage acc into smem fp32 [128][130] ----
    float* sm = (float*)smem;
    int rr = lane >> 2;
    int cc = (lane & 3) * 2;
#pragma unroll
    for (int mi = 0; mi < 2; mi++) {
        int rl = warp_m * 32 + mi * 16 + rr;
#pragma unroll
        for (int nj = 0; nj < 8; nj++) {
            int col = warp_n * 64 + nj * 8 + cc;
            *(float2*)&sm[rl * 130 + col] =
                make_float2(acc[mi][nj][0], acc[mi][nj][1]);
            *(float2*)&sm[(rl + 8) * 130 + col] =
                make_float2(acc[mi][nj][2], acc[mi][nj][3]);
        }
    }
    __syncthreads();

    // ---- fused rope / convert / scatter ----
    const float scale = 0.08838834764831845f;  // 1/sqrt(128)
    int tile = blockIdx.x;                      // 0..23
#pragma unroll
    for (int i = 0; i < 16; i++) {
        int idx = tid + i * 256;
        int r = idx >> 5;
        int e2 = (idx & 31) * 2;
        int m = m0 + r;
        float2 x1 = *(float2*)&sm[r * 130 + e2];
        float2 x2 = *(float2*)&sm[r * 130 + e2 + 64];
        if (tile < 20) {
            const float2* rp = g_rope + (size_t)(m & (S_ - 1)) * 64 + e2;
            float2 r0 = rp[0], r1 = rp[1];
            float ya0 = x1.x * r0.x - x2.x * r0.y;
            float ya1 = x1.y * r1.x - x2.y * r1.y;
            float yb0 = x1.x * r0.y + x2.x * r0.x;
            float yb1 = x1.y * r1.y + x2.y * r1.x;
            if (tile < 16) {
                size_t o = (size_t)m * 2048 + tile * 128 + e2;
                *(uint32_t*)&Qh[o]      = pack_f2h2(ya0 * scale, ya1 * scale);
                *(uint32_t*)&Qh[o + 64] = pack_f2h2(yb0 * scale, yb1 * scale);
            } else {
                int h = tile - 16;
                size_t o = (size_t)m * 512 + h * 128 + e2;
                *(float2*)&kc[o]      = make_float2(ya0, ya1);
                *(float2*)&kc[o + 64] = make_float2(yb0, yb1);
                *(uint32_t*)&Khi[o]      = pack_f2h2(ya0, ya1);
                *(uint32_t*)&Khi[o + 64] = pack_f2h2(yb0, yb1);
            }
        } else {
            int h = tile - 20;
            size_t o = (size_t)m * 512 + h * 128 + e2;
            *(float2*)&vc[o]      = x1;
            *(float2*)&vc[o + 64] = x2;
            *(uint32_t*)&Vhi[o]      = pack_f2h2(x1.x, x1.y);
            *(uint32_t*)&Vhi[o + 64] = pack_f2h2(x2.x, x2.y);
        }
    }
}

// ---------------------------------------------------------------------------
// Merged prep: rope table + fp32->fp16 converts (grid-stride x4) + W_O
// transpose, all in ONE launch.
// Block ranges: [0, TBL) table | [TBL, TBL+EW) elementwise | rest transpose.
// ---------------------------------------------------------------------------
#define N4_RES  (M_ * D_ / 4)
#define N4_WQ   (2048 * 2048 / 4)
#define N4_WK   (512 * 2048 / 4)
#define N4_ALL  (N4_RES + N4_WQ + 2 * N4_WK)
#define PREP_TBL_BLOCKS (S_ * 64 / 256)                    // 512
#define PREP_EW_BLOCKS  ((N4_ALL + 1023) / 1024)           // 4 float4/thread
#define PREP_TR_BLOCKS  (64 * 64)
#define PREP_BLOCKS (PREP_TBL_BLOCKS + PREP_EW_BLOCKS + PREP_TR_BLOCKS)

__global__ __launch_bounds__(256) void prep_kernel(
    const float* __restrict__ residual, const float* __restrict__ WQ,
    const float* __restrict__ WK, const float* __restrict__ WV,
    const float* __restrict__ WO,
    __half* __restrict__ Ahi, __half* __restrict__ Whi,
    __half* __restrict__ WOhi,
    const int* __restrict__ sp_ptr)
{
    if (blockIdx.x < PREP_TBL_BLOCKS) {
        // rope table
        const float LOG2_BASE_OVER_HALF = 13.287712379549449f / 64.0f;
        int idx = blockIdx.x * 256 + threadIdx.x;   // 0..131071
        int s = idx >> 6, e = idx & 63;
        float pos = (float)(*sp_ptr + s);
        float inv = exp2f(-(float)e * LOG2_BASE_OVER_HALF);
        float sn, cs;
        sincosf(pos * inv, &sn, &cs);
        g_rope[idx] = make_float2(cs, sn);
    } else if (blockIdx.x < PREP_TBL_BLOCKS + PREP_EW_BLOCKS) {
        int bid = blockIdx.x - PREP_TBL_BLOCKS;
#pragma unroll
        for (int t = 0; t < 4; t++) {
            int i = (bid * 4 + t) * 256 + threadIdx.x;
            if (i >= N4_ALL) break;
            const float* src;
            __half* dst;
            int j = i;
            if (j < N4_RES) {
                src = residual; dst = Ahi;
            } else if ((j -= N4_RES) < N4_WQ) {
                src = WQ; dst = Whi;
            } else if ((j -= N4_WQ) < N4_WK) {
                src = WK; dst = Whi + (size_t)2048 * 2048;
            } else {
                j -= N4_WK;
                src = WV; dst = Whi + (size_t)2560 * 2048;
            }
            float4 v = ((const float4*)src)[j];
            ushort4 hv = make_ushort4(
                __half_as_ushort(__float2half_rn(v.x)),
                __half_as_ushort(__float2half_rn(v.y)),
                __half_as_ushort(__float2half_rn(v.z)),
                __half_as_ushort(__float2half_rn(v.w)));
            ((ushort4*)dst)[j] = hv;
        }
    } else {
        __shared__ float t[32][33];
        int bid = blockIdx.x - PREP_TBL_BLOCKS - PREP_EW_BLOCKS;
        int bx = (bid & 63) * 32;
        int by = (bid >> 6) * 32;
        int x = threadIdx.x & 31;
        int y0 = threadIdx.x >> 5;
#pragma unroll
        for (int i = 0; i < 32; i += 8)
            t[y0 + i][x] = WO[(size_t)(by + y0 + i) * 2048 + bx + x];
        __syncthreads();
#pragma unroll
        for (int i = 0; i < 32; i += 8) {
            float v = t[x][y0 + i];
            WOhi[(size_t)(bx + y0 + i) * 2048 + by + x] = __float2half_rn(v);
        }
    }
}

// ---------------------------------------------------------------------------
// Tensor-core flash attention (R13 exact mainloop).
// ---------------------------------------------------------------------------
#define ATT_KV_STAGE 32768
#define ATT2_SMEM (16384 + 2 * ATT_KV_STAGE)

__global__ __launch_bounds__(128, 2) void attn_mma_kernel(
    const __half* __restrict__ Qhi,
    const __half* __restrict__ Khi, const __half* __restrict__ Vhi,
    __half* __restrict__ Ohi,
    const int* __restrict__ sp_ptr)
{
    extern __shared__ char smem[];
    uint32_t sb = smem_u32(smem);
    const uint32_t sQh = sb;
    const uint32_t sKV = sb + 16384;

    int tid = threadIdx.x;
    int lane = tid & 31;
    int warp = tid >> 5;
    int bh = blockIdx.y;
    int b = bh >> 4, h = bh & 15, kvh = h >> 2;
    int q0 = blockIdx.x * 64;
    int sp = *sp_ptr;
    float slope = exp2f(-0.5f * (float)(h + 1));

    int fr = ((lane >> 3) & 1) * 8 + (lane & 7);
    int fs = lane >> 4;

    int kt_end = (sp + q0 + 63) >> 6;
    if (kt_end > S_ / 64 - 1) kt_end = S_ / 64 - 1;

    auto load_kv = [&](int kt) {
        int k0 = (kt <= kt_end ? kt : kt_end) * 64;
        uint32_t stage = sKV + (uint32_t)(kt & 1) * ATT_KV_STAGE;
#pragma unroll
        for (int i = 0; i < 16; i++) {
            int idx = tid + i * 128;
            int t = idx >> 10;
            int inner = idx & 1023;
            int r = inner >> 4, sg = inner & 15;
            const __half* basep = t ? Vhi : Khi;
            const __half* src =
                basep + (size_t)(b * S_ + k0 + r) * 512 + kvh * 128 + sg * 8;
            cp16(stage + (uint32_t)t * 16384u + aswz(r, sg), src);
        }
        asm volatile("cp.async.commit_group;" ::: "memory");
    };

#pragma unroll
    for (int i = 0; i < 8; i++) {
        int idx = tid + i * 128;
        int r = idx >> 4, sg = idx & 15;
        const __half* src = Qhi
            + (size_t)(b * S_ + q0 + r) * 2048 + h * 128 + sg * 8;
        cp16(sQh + aswz(r, sg), src);
    }
    asm volatile("cp.async.commit_group;" ::: "memory");
    load_kv(0);
    load_kv(1);

    asm volatile("cp.async.wait_group 2;" ::: "memory");
    __syncthreads();
    uint32_t qh[8][4];
#pragma unroll
    for (int s = 0; s < 8; s++)
        ldm_x4(qh[s], sQh + aswz(warp * 16 + fr, 2 * s + fs));

    float Oacc[16][4];
#pragma unroll
    for (int e = 0; e < 16; e++)
#pragma unroll
        for (int k = 0; k < 4; k++) Oacc[e][k] = 0.f;
    float m0r = -1e30f, m1r = -1e30f;
    float l0r = 0.f, l1r = 0.f;

    int row0 = q0 + warp * 16 + (lane >> 2);
    int qp0 = sp + row0, qp1 = qp0 + 8;

    for (int kt = 0; kt <= kt_end; kt++) {
        int k0 = kt * 64;
        asm volatile("cp.async.wait_group 1;" ::: "memory");
        __syncthreads();

        uint32_t stage = sKV + (uint32_t)(kt & 1) * ATT_KV_STAGE;
        uint32_t sKh = stage, sVh = stage + 16384;

        float sacc[8][4];
#pragma unroll
        for (int nj = 0; nj < 8; nj++)
#pragma unroll
            for (int k = 0; k < 4; k++) sacc[nj][k] = 0.f;

#pragma unroll
        for (int s = 0; s < 8; s++) {
            uint32_t kbh[8][2], t4[4];
#pragma unroll
            for (int j = 0; j < 4; j++) {
                ldm_x4(t4, sKh + aswz(j * 16 + fr, 2 * s + fs));
                kbh[2 * j][0] = t4[0]; kbh[2 * j][1] = t4[2];
                kbh[2 * j + 1][0] = t4[1]; kbh[2 * j + 1][1] = t4[3];
            }
#pragma unroll
            for (int nj = 0; nj < 8; nj++)
                mma_f16(sacc[nj], qh[s], kbh[nj][0], kbh[nj][1]);
        }

        if (k0 + 63 <= sp + q0) {
#pragma unroll
            for (int nj = 0; nj < 8; nj++) {
                int c = k0 + nj * 8 + (lane & 3) * 2;
                sacc[nj][0] -= slope * (float)(qp0 - c);
                sacc[nj][1] -= slope * (float)(qp0 - c - 1);
                sacc[nj][2] -= slope * (float)(qp1 - c);
                sacc[nj][3] -= slope * (float)(qp1 - c - 1);
            }
        } else {
#pragma unroll
            for (int nj = 0; nj < 8; nj++) {
                int c = k0 + nj * 8 + (lane & 3) * 2;
                sacc[nj][0] = (c     <= qp0) ? sacc[nj][0] - slope * (float)(qp0 - c)     : -1e30f;
                sacc[nj][1] = (c + 1 <= qp0) ? sacc[nj][1] - slope * (float)(qp0 - c - 1) : -1e30f;
                sacc[nj][2] = (c     <= qp1) ? sacc[nj][2] - slope * (float)(qp1 - c)     : -1e30f;
                sacc[nj][3] = (c + 1 <= qp1) ? sacc[nj][3] - slope * (float)(qp1 - c - 1) : -1e30f;
            }
        }

        float mx0 = -1e30f, mx1 = -1e30f;
#pragma unroll
        for (int nj = 0; nj < 8; nj++) {
            mx0 = fmaxf(mx0, fmaxf(sacc[nj][0], sacc[nj][1]));
            mx1 = fmaxf(mx1, fmaxf(sacc[nj][2], sacc[nj][3]));
        }
        mx0 = fmaxf(mx0, __shfl_xor_sync(0xffffffffu, mx0, 1));
        mx0 = fmaxf(mx0, __shfl_xor_sync(0xffffffffu, mx0, 2));
        mx1 = fmaxf(mx1, __shfl_xor_sync(0xffffffffu, mx1, 1));
        mx1 = fmaxf(mx1, __shfl_xor_sync(0xffffffffu, mx1, 2));
        float mn0 = fmaxf(m0r, mx0), mn1 = fmaxf(m1r, mx1);
        float corr0 = __expf(m0r - mn0), corr1 = __expf(m1r - mn1);
        m0r = mn0; m1r = mn1;

        float ls0 = 0.f, ls1 = 0.f;
#pragma unroll
        for (int nj = 0; nj < 8; nj++) {
            sacc[nj][0] = __expf(sacc[nj][0] - mn0);
            sacc[nj][1] = __expf(sacc[nj][1] - mn0);
            sacc[nj][2] = __expf(sacc[nj][2] - mn1);
            sacc[nj][3] = __expf(sacc[nj][3] - mn1);
            ls0 += sacc[nj][0] + sacc[nj][1];
            ls1 += sacc[nj][2] + sacc[nj][3];
        }
        ls0 += __shfl_xor_sync(0xffffffffu, ls0, 1);
        ls0 += __shfl_xor_sync(0xffffffffu, ls0, 2);
        ls1 += __shfl_xor_sync(0xffffffffu, ls1, 1);
        ls1 += __shfl_xor_sync(0xffffffffu, ls1, 2);
        l0r = l0r * corr0 + ls0;
        l1r = l1r * corr1 + ls1;

#pragma unroll
        for (int e = 0; e < 16; e++) {
            Oacc[e][0] *= corr0; Oacc[e][1] *= corr0;
            Oacc[e][2] *= corr1; Oacc[e][3] *= corr1;
        }

        uint32_t phi[4][4];
#pragma unroll
        for (int t = 0; t < 4; t++) {
            phi[t][0] = pack_f2h2(sacc[2 * t][0], sacc[2 * t][1]);
            phi[t][1] = pack_f2h2(sacc[2 * t][2], sacc[2 * t][3]);
            phi[t][2] = pack_f2h2(sacc[2 * t + 1][0], sacc[2 * t + 1][1]);
            phi[t][3] = pack_f2h2(sacc[2 * t + 1][2], sacc[2 * t + 1][3]);
        }

#pragma unroll
        for (int t = 0; t < 4; t++) {
#pragma unroll
            for (int u = 0; u < 8; u++) {
                uint32_t th[4];
                ldm_x4_t(th, sVh + aswz(t * 16 + fr, 2 * u + fs));
                mma_f16(Oacc[2 * u], phi[t], th[0], th[1]);
                mma_f16(Oacc[2 * u + 1], phi[t], th[2], th[3]);
            }
        }
        __syncthreads();
        if (kt + 2 <= kt_end) load_kv(kt + 2);
        else asm volatile("cp.async.commit_group;" ::: "memory");
    }

    float inv0 = 1.f / l0r, inv1 = 1.f / l1r;
    size_t row0g = (size_t)(b * S_ + row0);
#pragma unroll
    for (int e = 0; e < 16; e++) {
        int colb = h * 128 + e * 8 + (lane & 3) * 2;
        uint32_t hp0 = pack_f2h2(Oacc[e][0] * inv0, Oacc[e][1] * inv0);
        uint32_t hp1 = pack_f2h2(Oacc[e][2] * inv1, Oacc[e][3] * inv1);
        *(uint32_t*)&Ohi[row0g * 2048 + colb] = hp0;
        *(uint32_t*)&Ohi[(row0g + 8) * 2048 + colb] = hp1;
    }
}

// ---------------------------------------------------------------------------
extern "C" void kernel_launch(void* const* d_in, const int* in_sizes, int n_in,
                              void* d_out, int out_size)
{
    const float* residual = (const float*)d_in[0];
    const float* W_Q = (const float*)d_in[1];
    const float* W_K = (const float*)d_in[2];
    const float* W_V = (const float*)d_in[3];
    const float* W_O = (const float*)d_in[4];
    const int* sp = (const int*)d_in[5];

    float* out = (float*)d_out;
    float* k_cache = out + (size_t)B_ * S_ * D_;
    float* v_cache = k_cache + (size_t)B_ * S_ * KVH_ * DH_;

    __half *Ahi, *Whi, *WOhi, *Phi, *Qh, *Khi, *Vhi;
    cudaGetSymbolAddress((void**)&Ahi, g_Ahi);
    cudaGetSymbolAddress((void**)&Whi, g_Whi);
    cudaGetSymbolAddress((void**)&WOhi, g_WOhi);
    cudaGetSymbolAddress((void**)&Phi, g_Phi);
    cudaGetSymbolAddress((void**)&Qh, g_Qh);
    cudaGetSymbolAddress((void**)&Khi, g_Khi);
    cudaGetSymbolAddress((void**)&Vhi, g_Vhi);

    cudaFuncSetAttribute(hmma_gemm, cudaFuncAttributeMaxDynamicSharedMemorySize,
                         GEMM_SMEM);
    cudaFuncSetAttribute(hmma_gemm_qkv, cudaFuncAttributeMaxDynamicSharedMemorySize,
                         QKV_SMEM);
    cudaFuncSetAttribute(attn_mma_kernel, cudaFuncAttributeMaxDynamicSharedMemorySize,
                         ATT2_SMEM);

    // 0) single merged prep (rope table + converts + W_O transpose)
    prep_kernel<<<PREP_BLOCKS, 256>>>(residual, W_Q, W_K, W_V, W_O,
                                      Ahi, Whi, WOhi, sp);

    // 1) fused QKV projection + rope epilogue
    hmma_gemm_qkv<<<dim3(NQKV / 128, M_ / 128), 256, QKV_SMEM>>>(
        Ahi, Whi, Qh, k_cache, Khi, v_cache, Vhi);

    // 2) tensor-core attention (fp16, fp32 acc) -> fp16 output
    attn_mma_kernel<<<dim3(S_ / 64, B_ * H_), 128, ATT2_SMEM>>>(
        Qh, Khi, Vhi, Phi, sp);

    // 3) output projection (fp16 single-pass)
    hmma_gemm<<<dim3(D_ / 128, M_ / 128), 256, GEMM_SMEM>>>(
        Phi, WOhi, out, D_);
}

// round 15
// speedup vs baseline: 1.2691x; 1.0064x over previous
#include <cuda_runtime.h>
#include <cuda_fp16.h>
#include <math.h>
#include <stdint.h>

// Problem constants (fixed shapes from setup_inputs)
#define B_   2
#define S_   2048
#define D_   2048
#define H_   16
#define KVH_ 4
#define DH_  128
#define M_   (B_ * S_)          // 4096
#define NQKV 3072               // 2048 q + 512 k + 512 v

// Scratch (static device arrays; no runtime allocation allowed)
__device__ __half g_Ahi[M_ * D_];     // residual fp16
__device__ __half g_Whi[NQKV * D_];   // W_Q|W_K|W_V rows, fp16
__device__ __half g_WOhi[D_ * D_];    // W_O transposed [d][he], fp16
__device__ __half g_Phi[M_ * D_];     // attention output fp16
__device__ __half g_Qh[M_ * D_];      // roped+scaled Q, fp16
__device__ __half g_Khi[M_ * 512];
__device__ __half g_Vhi[M_ * 512];
__device__ float2 g_rope[S_ * 64];    // per (s, e): (cos, sin)

// ---------------------------------------------------------------------------
// helpers
// ---------------------------------------------------------------------------
__device__ __forceinline__ uint32_t smem_u32(const void* p) {
    uint32_t a;
    asm("{ .reg .u64 t; cvta.to.shared.u64 t, %1; cvt.u32.u64 %0, t; }"
        : "=r"(a) : "l"(p));
    return a;
}

__device__ __forceinline__ void cp16(uint32_t dst, const void* src) {
    asm volatile("cp.async.cg.shared.global [%0], [%1], 16;"
                 :: "r"(dst), "l"(src));
}

__device__ __forceinline__ void ldm_x4(uint32_t* r, uint32_t addr) {
    asm volatile("ldmatrix.sync.aligned.m8n8.x4.shared.b16 {%0,%1,%2,%3}, [%4];"
                 : "=r"(r[0]), "=r"(r[1]), "=r"(r[2]), "=r"(r[3]) : "r"(addr));
}

__device__ __forceinline__ void ldm_x4_t(uint32_t* r, uint32_t addr) {
    asm volatile("ldmatrix.sync.aligned.m8n8.x4.trans.shared.b16 {%0,%1,%2,%3}, [%4];"
                 : "=r"(r[0]), "=r"(r[1]), "=r"(r[2]), "=r"(r[3]) : "r"(addr));
}

__device__ __forceinline__ void mma_f16(float* c, const uint32_t* a,
                                        uint32_t b0, uint32_t b1) {
    asm volatile(
        "mma.sync.aligned.m16n8k16.row.col.f32.f16.f16.f32 "
        "{%0,%1,%2,%3}, {%4,%5,%6,%7}, {%8,%9}, {%0,%1,%2,%3};"
        : "+f"(c[0]), "+f"(c[1]), "+f"(c[2]), "+f"(c[3])
        : "r"(a[0]), "r"(a[1]), "r"(a[2]), "r"(a[3]), "r"(b0), "r"(b1));
}

// swizzled byte offset for a 16B segment (row r, seg s) in a [rows][32]fp16 block
__device__ __forceinline__ uint32_t swz_off(int r, int s) {
    return (uint32_t)(r * 64 + ((s ^ ((r >> 1) & 3)) * 16));
}

// swizzled byte offset for [rows][128 fp16] tiles (256B rows, 16 segs)
__device__ __forceinline__ uint32_t aswz(int r, int sg) {
    return (uint32_t)(r * 256 + ((sg ^ (r & 7)) * 16));
}

__device__ __forceinline__ uint32_t pack_f2h2(float x0, float x1) {
    __half2 p = __floats2half2_rn(x0, x1);
    return *(uint32_t*)&p;
}

#define GEMM_STAGE 16384
#define GEMM_SMEM (4 * GEMM_STAGE)
#define QKV_SMEM 66560

// ---------------------------------------------------------------------------
// GEMM (plain): C fp32, used for the output projection. (R14 exact)
// ---------------------------------------------------------------------------
__global__ __launch_bounds__(256, 2) void hmma_gemm(
    const __half* __restrict__ Ah, const __half* __restrict__ Bh,
    float* __restrict__ C, int ldc)
{
    extern __shared__ char smem[];
    uint32_t sb = smem_u32(smem);

    int tid = threadIdx.x;
    int lane = tid & 31;
    int warp = tid >> 5;
    int warp_m = warp & 3;
    int warp_n = warp >> 2;
    int m0 = blockIdx.y * 128;
    int n0 = blockIdx.x * 128;

    int q = lane >> 3;
    int lrow = lane & 7;
    int arow_l = (q & 1) * 8 + lrow;
    int ksel = q >> 1;

    float acc[2][8][4];
#pragma unroll
    for (int i = 0; i < 2; i++)
#pragma unroll
        for (int j = 0; j < 8; j++)
#pragma unroll
            for (int k = 0; k < 4; k++) acc[i][j][k] = 0.f;

    auto load_chunk = [&](int c) {
        int k0 = c * 32;
        uint32_t buf = sb + (uint32_t)(c & 3) * GEMM_STAGE;
#pragma unroll
        for (int t = 0; t < 4; t++) {
            int g = tid + t * 256;
            int mat = g >> 9;
            int inner = g & 511;
            int r = inner >> 2;
            int s = inner & 3;
            const __half* base = mat ? Bh : Ah;
            int row = (mat ? n0 : m0) + r;
            const void* src = base + (size_t)row * 2048 + k0 + s * 8;
            cp16(buf + (uint32_t)mat * 8192u + swz_off(r, s), src);
        }
        asm volatile("cp.async.commit_group;" ::: "memory");
    };

    load_chunk(0);
    load_chunk(1);
    load_chunk(2);
    load_chunk(3);

    for (int c = 0; c < 64; c++) {
        asm volatile("cp.async.wait_group 3;" ::: "memory");
        __syncthreads();

        uint32_t buf = sb + (uint32_t)(c & 3) * GEMM_STAGE;
        uint32_t bAh = buf, bBh = buf + 8192;

#pragma unroll
        for (int ks = 0; ks < 2; ks++) {
            int s = ks * 2 + ksel;
            uint32_t ah[2][4];
#pragma unroll
            for (int mi = 0; mi < 2; mi++) {
                int r = warp_m * 32 + mi * 16 + arow_l;
                ldm_x4(ah[mi], bAh + swz_off(r, s));
            }
            uint32_t bh[8][2];
#pragma unroll
            for (int j = 0; j < 4; j++) {
                int r = warp_n * 64 + j * 16 + arow_l;
                uint32_t t4[4];
                ldm_x4(t4, bBh + swz_off(r, s));
                bh[j * 2 + 0][0] = t4[0]; bh[j * 2 + 0][1] = t4[2];
                bh[j * 2 + 1][0] = t4[1]; bh[j * 2 + 1][1] = t4[3];
            }
#pragma unroll
            for (int mi = 0; mi < 2; mi++) {
#pragma unroll
                for (int nj = 0; nj < 8; nj++)
                    mma_f16(acc[mi][nj], ah[mi], bh[nj][0], bh[nj][1]);
            }
        }
        __syncthreads();
        if (c + 4 < 64) load_chunk(c + 4);
        else asm volatile("cp.async.commit_group;" ::: "memory");
    }

    int rr = lane >> 2;
    int cc = (lane & 3) * 2;
#pragma unroll
    for (int mi = 0; mi < 2; mi++) {
        int r1 = m0 + warp_m * 32 + mi * 16 + rr;
#pragma unroll
        for (int nj = 0; nj < 8; nj++) {
            int col = n0 + warp_n * 64 + nj * 8 + cc;
            float2 v0 = make_float2(acc[mi][nj][0], acc[mi][nj][1]);
            float2 v1 = make_float2(acc[mi][nj][2], acc[mi][nj][3]);
            *(float2*)&C[(size_t)r1 * ldc + col] = v0;
            *(float2*)&C[(size_t)(r1 + 8) * ldc + col] = v1;
        }
    }
}

// ---------------------------------------------------------------------------
// GEMM + fused RoPE epilogue for the QKV projection. (R14 exact)
// ---------------------------------------------------------------------------
__global__ __launch_bounds__(256, 2) void hmma_gemm_qkv(
    const __half* __restrict__ Ah, const __half* __restrict__ Bh,
    __half* __restrict__ Qh,
    float* __restrict__ kc, __half* __restrict__ Khi,
    float* __restrict__ vc, __half* __restrict__ Vhi)
{
    extern __shared__ char smem[];
    uint32_t sb = smem_u32(smem);

    int tid = threadIdx.x;
    int lane = tid & 31;
    int warp = tid >> 5;
    int warp_m = warp & 3;
    int warp_n = warp >> 2;
    int m0 = blockIdx.y * 128;
    int n0 = blockIdx.x * 128;

    int q = lane >> 3;
    int lrow = lane & 7;
    int arow_l = (q & 1) * 8 + lrow;
    int ksel = q >> 1;

    float acc[2][8][4];
#pragma unroll
    for (int i = 0; i < 2; i++)
#pragma unroll
        for (int j = 0; j < 8; j++)
#pragma unroll
            for (int k = 0; k < 4; k++) acc[i][j][k] = 0.f;

    auto load_chunk = [&](int c) {
        int k0 = c * 32;
        uint32_t buf = sb + (uint32_t)(c & 3) * GEMM_STAGE;
#pragma unroll
        for (int t = 0; t < 4; t++) {
            int g = tid + t * 256;
            int mat = g >> 9;
            int inner = g & 511;
            int r = inner >> 2;
            int s = inner & 3;
            const __half* base = mat ? Bh : Ah;
            int row = (mat ? n0 : m0) + r;
            const void* src = base + (size_t)row * 2048 + k0 + s * 8;
            cp16(buf + (uint32_t)mat * 8192u + swz_off(r, s), src);
        }
        asm volatile("cp.async.commit_group;" ::: "memory");
    };

    load_chunk(0);
    load_chunk(1);
    load_chunk(2);
    load_chunk(3);

    for (int c = 0; c < 64; c++) {
        asm volatile("cp.async.wait_group 3;" ::: "memory");
        __syncthreads();

        uint32_t buf = sb + (uint32_t)(c & 3) * GEMM_STAGE;
        uint32_t bAh = buf, bBh = buf + 8192;

#pragma unroll
        for (int ks = 0; ks < 2; ks++) {
            int s = ks * 2 + ksel;
            uint32_t ah[2][4];
#pragma unroll
            for (int mi = 0; mi < 2; mi++) {
                int r = warp_m * 32 + mi * 16 + arow_l;
                ldm_x4(ah[mi], bAh + swz_off(r, s));
            }
            uint32_t bh[8][2];
#pragma unroll
            for (int j = 0; j < 4; j++) {
                int r = warp_n * 64 + j * 16 + arow_l;
                uint32_t t4[4];
                ldm_x4(t4, bBh + swz_off(r, s));
                bh[j * 2 + 0][0] = t4[0]; bh[j * 2 + 0][1] = t4[2];
                bh[j * 2 + 1][0] = t4[1]; bh[j * 2 + 1][1] = t4[3];
            }
#pragma unroll
            for (int mi = 0; mi < 2; mi++) {
#pragma unroll
                for (int nj = 0; nj < 8; nj++)
                    mma_f16(acc[mi][nj], ah[mi], bh[nj][0], bh[nj][1]);
            }
        }
        __syncthreads();
        if (c + 4 < 64) load_chunk(c + 4);
        else asm volatile("cp.async.commit_group;" ::: "memory");
    }

    // ---- stage acc into smem fp32 [128][130] ----
    float* sm = (float*)smem;
    int rr = lane >> 2;
    int cc = (lane & 3) * 2;
#pragma unroll
    for (int mi = 0; mi < 2; mi++) {
        int rl = warp_m * 32 + mi * 16 + rr;
#pragma unroll
        for (int nj = 0; nj < 8; nj++) {
            int col = warp_n * 64 + nj * 8 + cc;
            *(float2*)&sm[rl * 130 + col] =
                make_float2(acc[mi][nj][0], acc[mi][nj][1]);
            *(float2*)&sm[(rl + 8) * 130 + col] =
                make_float2(acc[mi][nj][2], acc[mi][nj][3]);
        }
    }
    __syncthreads();

    // ---- fused rope / convert / scatter ----
    const float scale = 0.08838834764831845f;  // 1/sqrt(128)
    int tile = blockIdx.x;                      // 0..23
#pragma unroll
    for (int i = 0; i < 16; i++) {
        int idx = tid + i * 256;
        int r = idx >> 5;
        int e2 = (idx & 31) * 2;
        int m = m0 + r;
        float2 x1 = *(float2*)&sm[r * 130 + e2];
        float2 x2 = *(float2*)&sm[r * 130 + e2 + 64];
        if (tile < 20) {
            const float2* rp = g_rope + (size_t)(m & (S_ - 1)) * 64 + e2;
            float2 r0 = rp[0], r1 = rp[1];
            float ya0 = x1.x * r0.x - x2.x * r0.y;
            float ya1 = x1.y * r1.x - x2.y * r1.y;
            float yb0 = x1.x * r0.y + x2.x * r0.x;
            float yb1 = x1.y * r1.y + x2.y * r1.x;
            if (tile < 16) {
                size_t o = (size_t)m * 2048 + tile * 128 + e2;
                *(uint32_t*)&Qh[o]      = pack_f2h2(ya0 * scale, ya1 * scale);
                *(uint32_t*)&Qh[o + 64] = pack_f2h2(yb0 * scale, yb1 * scale);
            } else {
                int h = tile - 16;
                size_t o = (size_t)m * 512 + h * 128 + e2;
                *(float2*)&kc[o]      = make_float2(ya0, ya1);
                *(float2*)&kc[o + 64] = make_float2(yb0, yb1);
                *(uint32_t*)&Khi[o]      = pack_f2h2(ya0, ya1);
                *(uint32_t*)&Khi[o + 64] = pack_f2h2(yb0, yb1);
            }
        } else {
            int h = tile - 20;
            size_t o = (size_t)m * 512 + h * 128 + e2;
            *(float2*)&vc[o]      = x1;
            *(float2*)&vc[o + 64] = x2;
            *(uint32_t*)&Vhi[o]      = pack_f2h2(x1.x, x1.y);
            *(uint32_t*)&Vhi[o + 64] = pack_f2h2(x2.x, x2.y);
        }
    }
}

// ---------------------------------------------------------------------------
// Merged prep: rope table + fp32->fp16 converts (x4/thread) + W_O transpose.
// ---------------------------------------------------------------------------
#define N4_RES  (M_ * D_ / 4)
#define N4_WQ   (2048 * 2048 / 4)
#define N4_WK   (512 * 2048 / 4)
#define N4_ALL  (N4_RES + N4_WQ + 2 * N4_WK)
#define PREP_TBL_BLOCKS (S_ * 64 / 256)
#define PREP_EW_BLOCKS  ((N4_ALL + 1023) / 1024)
#define PREP_TR_BLOCKS  (64 * 64)
#define PREP_BLOCKS (PREP_TBL_BLOCKS + PREP_EW_BLOCKS + PREP_TR_BLOCKS)

__global__ __launch_bounds__(256) void prep_kernel(
    const float* __restrict__ residual, const float* __restrict__ WQ,
    const float* __restrict__ WK, const float* __restrict__ WV,
    const float* __restrict__ WO,
    __half* __restrict__ Ahi, __half* __restrict__ Whi,
    __half* __restrict__ WOhi,
    const int* __restrict__ sp_ptr)
{
    if (blockIdx.x < PREP_TBL_BLOCKS) {
        const float LOG2_BASE_OVER_HALF = 13.287712379549449f / 64.0f;
        int idx = blockIdx.x * 256 + threadIdx.x;
        int s = idx >> 6, e = idx & 63;
        float pos = (float)(*sp_ptr + s);
        float inv = exp2f(-(float)e * LOG2_BASE_OVER_HALF);
        float sn, cs;
        sincosf(pos * inv, &sn, &cs);
        g_rope[idx] = make_float2(cs, sn);
    } else if (blockIdx.x < PREP_TBL_BLOCKS + PREP_EW_BLOCKS) {
        int bid = blockIdx.x - PREP_TBL_BLOCKS;
#pragma unroll
        for (int t = 0; t < 4; t++) {
            int i = (bid * 4 + t) * 256 + threadIdx.x;
            if (i >= N4_ALL) break;
            const float* src;
            __half* dst;
            int j = i;
            if (j < N4_RES) {
                src = residual; dst = Ahi;
            } else if ((j -= N4_RES) < N4_WQ) {
                src = WQ; dst = Whi;
            } else if ((j -= N4_WQ) < N4_WK) {
                src = WK; dst = Whi + (size_t)2048 * 2048;
            } else {
                j -= N4_WK;
                src = WV; dst = Whi + (size_t)2560 * 2048;
            }
            float4 v = ((const float4*)src)[j];
            ushort4 hv = make_ushort4(
                __half_as_ushort(__float2half_rn(v.x)),
                __half_as_ushort(__float2half_rn(v.y)),
                __half_as_ushort(__float2half_rn(v.z)),
                __half_as_ushort(__float2half_rn(v.w)));
            ((ushort4*)dst)[j] = hv;
        }
    } else {
        __shared__ float t[32][33];
        int bid = blockIdx.x - PREP_TBL_BLOCKS - PREP_EW_BLOCKS;
        int bx = (bid & 63) * 32;
        int by = (bid >> 6) * 32;
        int x = threadIdx.x & 31;
        int y0 = threadIdx.x >> 5;
#pragma unroll
        for (int i = 0; i < 32; i += 8)
            t[y0 + i][x] = WO[(size_t)(by + y0 + i) * 2048 + bx + x];
        __syncthreads();
#pragma unroll
        for (int i = 0; i < 32; i += 8) {
            float v = t[x][y0 + i];
            WOhi[(size_t)(bx + y0 + i) * 2048 + by + x] = __float2half_rn(v);
        }
    }
}

// ---------------------------------------------------------------------------
// Tensor-core flash attention (R14 mainloop) with LONGEST-FIRST scheduling:
// q-tile index reversed so the 33-tile CTAs launch in wave 0.
// ---------------------------------------------------------------------------
#define ATT_KV_STAGE 32768
#define ATT2_SMEM (16384 + 2 * ATT_KV_STAGE)

__global__ __launch_bounds__(128, 2) void attn_mma_kernel(
    const __half* __restrict__ Qhi,
    const __half* __restrict__ Khi, const __half* __restrict__ Vhi,
    __half* __restrict__ Ohi,
    const int* __restrict__ sp_ptr)
{
    extern __shared__ char smem[];
    uint32_t sb = smem_u32(smem);
    const uint32_t sQh = sb;
    const uint32_t sKV = sb + 16384;

    int tid = threadIdx.x;
    int lane = tid & 31;
    int warp = tid >> 5;
    int bh = blockIdx.y;
    int b = bh >> 4, h = bh & 15, kvh = h >> 2;
    int q0 = (S_ / 64 - 1 - blockIdx.x) * 64;   // longest-first
    int sp = *sp_ptr;
    float slope = exp2f(-0.5f * (float)(h + 1));

    int fr = ((lane >> 3) & 1) * 8 + (lane & 7);
    int fs = lane >> 4;

    int kt_end = (sp + q0 + 63) >> 6;
    if (kt_end > S_ / 64 - 1) kt_end = S_ / 64 - 1;

    auto load_kv = [&](int kt) {
        int k0 = (kt <= kt_end ? kt : kt_end) * 64;
        uint32_t stage = sKV + (uint32_t)(kt & 1) * ATT_KV_STAGE;
#pragma unroll
        for (int i = 0; i < 16; i++) {
            int idx = tid + i * 128;
            int t = idx >> 10;
            int inner = idx & 1023;
            int r = inner >> 4, sg = inner & 15;
            const __half* basep = t ? Vhi : Khi;
            const __half* src =
                basep + (size_t)(b * S_ + k0 + r) * 512 + kvh * 128 + sg * 8;
            cp16(stage + (uint32_t)t * 16384u + aswz(r, sg), src);
        }
        asm volatile("cp.async.commit_group;" ::: "memory");
    };

#pragma unroll
    for (int i = 0; i < 8; i++) {
        int idx = tid + i * 128;
        int r = idx >> 4, sg = idx & 15;
        const __half* src = Qhi
            + (size_t)(b * S_ + q0 + r) * 2048 + h * 128 + sg * 8;
        cp16(sQh + aswz(r, sg), src);
    }
    asm volatile("cp.async.commit_group;" ::: "memory");
    load_kv(0);
    load_kv(1);

    asm volatile("cp.async.wait_group 2;" ::: "memory");
    __syncthreads();
    uint32_t qh[8][4];
#pragma unroll
    for (int s = 0; s < 8; s++)
        ldm_x4(qh[s], sQh + aswz(warp * 16 + fr, 2 * s + fs));

    float Oacc[16][4];
#pragma unroll
    for (int e = 0; e < 16; e++)
#pragma unroll
        for (int k = 0; k < 4; k++) Oacc[e][k] = 0.f;
    float m0r = -1e30f, m1r = -1e30f;
    float l0r = 0.f, l1r = 0.f;

    int row0 = q0 + warp * 16 + (lane >> 2);
    int qp0 = sp + row0, qp1 = qp0 + 8;

    for (int kt = 0; kt <= kt_end; kt++) {
        int k0 = kt * 64;
        asm volatile("cp.async.wait_group 1;" ::: "memory");
        __syncthreads();

        uint32_t stage = sKV + (uint32_t)(kt & 1) * ATT_KV_STAGE;
        uint32_t sKh = stage, sVh = stage + 16384;

        float sacc[8][4];
#pragma unroll
        for (int nj = 0; nj < 8; nj++)
#pragma unroll
            for (int k = 0; k < 4; k++) sacc[nj][k] = 0.f;

#pragma unroll
        for (int s = 0; s < 8; s++) {
            uint32_t kbh[8][2], t4[4];
#pragma unroll
            for (int j = 0; j < 4; j++) {
                ldm_x4(t4, sKh + aswz(j * 16 + fr, 2 * s + fs));
                kbh[2 * j][0] = t4[0]; kbh[2 * j][1] = t4[2];
                kbh[2 * j + 1][0] = t4[1]; kbh[2 * j + 1][1] = t4[3];
            }
#pragma unroll
            for (int nj = 0; nj < 8; nj++)
                mma_f16(sacc[nj], qh[s], kbh[nj][0], kbh[nj][1]);
        }

        if (k0 + 63 <= sp + q0) {
#pragma unroll
            for (int nj = 0; nj < 8; nj++) {
                int c = k0 + nj * 8 + (lane & 3) * 2;
                sacc[nj][0] -= slope * (float)(qp0 - c);
                sacc[nj][1] -= slope * (float)(qp0 - c - 1);
                sacc[nj][2] -= slope * (float)(qp1 - c);
                sacc[nj][3] -= slope * (float)(qp1 - c - 1);
            }
        } else {
#pragma unroll
            for (int nj = 0; nj < 8; nj++) {
                int c = k0 + nj * 8 + (lane & 3) * 2;
                sacc[nj][0] = (c     <= qp0) ? sacc[nj][0] - slope * (float)(qp0 - c)     : -1e30f;
                sacc[nj][1] = (c + 1 <= qp0) ? sacc[nj][1] - slope * (float)(qp0 - c - 1) : -1e30f;
                sacc[nj][2] = (c     <= qp1) ? sacc[nj][2] - slope * (float)(qp1 - c)     : -1e30f;
                sacc[nj][3] = (c + 1 <= qp1) ? sacc[nj][3] - slope * (float)(qp1 - c - 1) : -1e30f;
            }
        }

        float mx0 = -1e30f, mx1 = -1e30f;
#pragma unroll
        for (int nj = 0; nj < 8; nj++) {
            mx0 = fmaxf(mx0, fmaxf(sacc[nj][0], sacc[nj][1]));
            mx1 = fmaxf(mx1, fmaxf(sacc[nj][2], sacc[nj][3]));
        }
        mx0 = fmaxf(mx0, __shfl_xor_sync(0xffffffffu, mx0, 1));
        mx0 = fmaxf(mx0, __shfl_xor_sync(0xffffffffu, mx0, 2));
        mx1 = fmaxf(mx1, __shfl_xor_sync(0xffffffffu, mx1, 1));
        mx1 = fmaxf(mx1, __shfl_xor_sync(0xffffffffu, mx1, 2));
        float mn0 = fmaxf(m0r, mx0), mn1 = fmaxf(m1r, mx1);
        float corr0 = __expf(m0r - mn0), corr1 = __expf(m1r - mn1);
        m0r = mn0; m1r = mn1;

        float ls0 = 0.f, ls1 = 0.f;
#pragma unroll
        for (int nj = 0; nj < 8; nj++) {
            sacc[nj][0] = __expf(sacc[nj][0] - mn0);
            sacc[nj][1] = __expf(sacc[nj][1] - mn0);
            sacc[nj][2] = __expf(sacc[nj][2] - mn1);
            sacc[nj][3] = __expf(sacc[nj][3] - mn1);
            ls0 += sacc[nj][0] + sacc[nj][1];
            ls1 += sacc[nj][2] + sacc[nj][3];
        }
        ls0 += __shfl_xor_sync(0xffffffffu, ls0, 1);
        ls0 += __shfl_xor_sync(0xffffffffu, ls0, 2);
        ls1 += __shfl_xor_sync(0xffffffffu, ls1, 1);
        ls1 += __shfl_xor_sync(0xffffffffu, ls1, 2);
        l0r = l0r * corr0 + ls0;
        l1r = l1r * corr1 + ls1;

#pragma unroll
        for (int e = 0; e < 16; e++) {
            Oacc[e][0] *= corr0; Oacc[e][1] *= corr0;
            Oacc[e][2] *= corr1; Oacc[e][3] *= corr1;
        }

        uint32_t phi[4][4];
#pragma unroll
        for (int t = 0; t < 4; t++) {
            phi[t][0] = pack_f2h2(sacc[2 * t][0], sacc[2 * t][1]);
            phi[t][1] = pack_f2h2(sacc[2 * t][2], sacc[2 * t][3]);
            phi[t][2] = pack_f2h2(sacc[2 * t + 1][0], sacc[2 * t + 1][1]);
            phi[t][3] = pack_f2h2(sacc[2 * t + 1][2], sacc[2 * t + 1][3]);
        }

#pragma unroll
        for (int t = 0; t < 4; t++) {
#pragma unroll
            for (int u = 0; u < 8; u++) {
                uint32_t th[4];
                ldm_x4_t(th, sVh + aswz(t * 16 + fr, 2 * u + fs));
                mma_f16(Oacc[2 * u], phi[t], th[0], th[1]);
                mma_f16(Oacc[2 * u + 1], phi[t], th[2], th[3]);
            }
        }
        __syncthreads();
        if (kt + 2 <= kt_end) load_kv(kt + 2);
        else asm volatile("cp.async.commit_group;" ::: "memory");
    }

    float inv0 = 1.f / l0r, inv1 = 1.f / l1r;
    size_t row0g = (size_t)(b * S_ + row0);
#pragma unroll
    for (int e = 0; e < 16; e++) {
        int colb = h * 128 + e * 8 + (lane & 3) * 2;
        uint32_t hp0 = pack_f2h2(Oacc[e][0] * inv0, Oacc[e][1] * inv0);
        uint32_t hp1 = pack_f2h2(Oacc[e][2] * inv1, Oacc[e][3] * inv1);
        *(uint32_t*)&Ohi[row0g * 2048 + colb] = hp0;
        *(uint32_t*)&Ohi[(row0g + 8) * 2048 + colb] = hp1;
    }
}

// ---------------------------------------------------------------------------
extern "C" void kernel_launch(void* const* d_in, const int* in_sizes, int n_in,
                              void* d_out, int out_size)
{
    const float* residual = (const float*)d_in[0];
    const float* W_Q = (const float*)d_in[1];
    const float* W_K = (const float*)d_in[2];
    const float* W_V = (const float*)d_in[3];
    const float* W_O = (const float*)d_in[4];
    const int* sp = (const int*)d_in[5];

    float* out = (float*)d_out;
    float* k_cache = out + (size_t)B_ * S_ * D_;
    float* v_cache = k_cache + (size_t)B_ * S_ * KVH_ * DH_;

    __half *Ahi, *Whi, *WOhi, *Phi, *Qh, *Khi, *Vhi;
    cudaGetSymbolAddress((void**)&Ahi, g_Ahi);
    cudaGetSymbolAddress((void**)&Whi, g_Whi);
    cudaGetSymbolAddress((void**)&WOhi, g_WOhi);
    cudaGetSymbolAddress((void**)&Phi, g_Phi);
    cudaGetSymbolAddress((void**)&Qh, g_Qh);
    cudaGetSymbolAddress((void**)&Khi, g_Khi);
    cudaGetSymbolAddress((void**)&Vhi, g_Vhi);

    cudaFuncSetAttribute(hmma_gemm, cudaFuncAttributeMaxDynamicSharedMemorySize,
                         GEMM_SMEM);
    cudaFuncSetAttribute(hmma_gemm_qkv, cudaFuncAttributeMaxDynamicSharedMemorySize,
                         QKV_SMEM);
    cudaFuncSetAttribute(attn_mma_kernel, cudaFuncAttributeMaxDynamicSharedMemorySize,
                         ATT2_SMEM);

    // 0) single merged prep (rope table + converts + W_O transpose)
    prep_kernel<<<PREP_BLOCKS, 256>>>(residual, W_Q, W_K, W_V, W_O,
                                      Ahi, Whi, WOhi, sp);

    // 1) fused QKV projection + rope epilogue
    hmma_gemm_qkv<<<dim3(NQKV / 128, M_ / 128), 256, QKV_SMEM>>>(
        Ahi, Whi, Qh, k_cache, Khi, v_cache, Vhi);

    // 2) tensor-core attention (fp16, fp32 acc, longest-first) -> fp16 output
    attn_mma_kernel<<<dim3(S_ / 64, B_ * H_), 128, ATT2_SMEM>>>(
        Qh, Khi, Vhi, Phi, sp);

    // 3) output projection (fp16 single-pass)
    hmma_gemm<<<dim3(D_ / 128, M_ / 128), 256, GEMM_SMEM>>>(
        Phi, WOhi, out, D_);
}

// round 16
// speedup vs baseline: 1.3006x; 1.0248x over previous
#include <cuda_runtime.h>
#include <cuda_fp16.h>
#include <math.h>
#include <stdint.h>

// Problem constants (fixed shapes from setup_inputs)
#define B_   2
#define S_   2048
#define D_   2048
#define H_   16
#define KVH_ 4
#define DH_  128
#define M_   (B_ * S_)          // 4096
#define NQKV 3072               // 2048 q + 512 k + 512 v

// Scratch (static device arrays; no runtime allocation allowed)
__device__ __half g_Ahi[M_ * D_];     // residual fp16
__device__ __half g_Whi[NQKV * D_];   // W_Q|W_K|W_V rows, fp16
__device__ __half g_WOhi[D_ * D_];    // W_O transposed [d][he], fp16
__device__ __half g_Phi[M_ * D_];     // attention output fp16
__device__ __half g_Qh[M_ * D_];      // roped+scaled Q, fp16
__device__ __half g_Khi[M_ * 512];
__device__ __half g_Vhi[M_ * 512];
__device__ float2 g_rope[S_ * 64];    // per (s, e): (cos, sin)

// ---------------------------------------------------------------------------
// helpers
// ---------------------------------------------------------------------------
__device__ __forceinline__ uint32_t smem_u32(const void* p) {
    uint32_t a;
    asm("{ .reg .u64 t; cvta.to.shared.u64 t, %1; cvt.u32.u64 %0, t; }"
        : "=r"(a) : "l"(p));
    return a;
}

__device__ __forceinline__ void cp16(uint32_t dst, const void* src) {
    asm volatile("cp.async.cg.shared.global [%0], [%1], 16;"
                 :: "r"(dst), "l"(src));
}

__device__ __forceinline__ void ldm_x4(uint32_t* r, uint32_t addr) {
    asm volatile("ldmatrix.sync.aligned.m8n8.x4.shared.b16 {%0,%1,%2,%3}, [%4];"
                 : "=r"(r[0]), "=r"(r[1]), "=r"(r[2]), "=r"(r[3]) : "r"(addr));
}

__device__ __forceinline__ void ldm_x4_t(uint32_t* r, uint32_t addr) {
    asm volatile("ldmatrix.sync.aligned.m8n8.x4.trans.shared.b16 {%0,%1,%2,%3}, [%4];"
                 : "=r"(r[0]), "=r"(r[1]), "=r"(r[2]), "=r"(r[3]) : "r"(addr));
}

__device__ __forceinline__ void mma_f16(float* c, const uint32_t* a,
                                        uint32_t b0, uint32_t b1) {
    asm volatile(
        "mma.sync.aligned.m16n8k16.row.col.f32.f16.f16.f32 "
        "{%0,%1,%2,%3}, {%4,%5,%6,%7}, {%8,%9}, {%0,%1,%2,%3};"
        : "+f"(c[0]), "+f"(c[1]), "+f"(c[2]), "+f"(c[3])
        : "r"(a[0]), "r"(a[1]), "r"(a[2]), "r"(a[3]), "r"(b0), "r"(b1));
}

// swizzled byte offset for a 16B segment (row r, seg s) in a [rows][32]fp16 block
__device__ __forceinline__ uint32_t swz_off(int r, int s) {
    return (uint32_t)(r * 64 + ((s ^ ((r >> 1) & 3)) * 16));
}

// swizzled byte offset for [rows][128 fp16] tiles (256B rows, 16 segs)
__device__ __forceinline__ uint32_t aswz(int r, int sg) {
    return (uint32_t)(r * 256 + ((sg ^ (r & 7)) * 16));
}

__device__ __forceinline__ uint32_t pack_f2h2(float x0, float x1) {
    __half2 p = __floats2half2_rn(x0, x1);
    return *(uint32_t*)&p;
}

#define GEMM_STAGE 16384
#define GEMM_SMEM (4 * GEMM_STAGE)
#define QKV_SMEM 66560

// ---------------------------------------------------------------------------
// GEMM (plain): C fp32, used for the output projection. (R14 exact)
// ---------------------------------------------------------------------------
__global__ __launch_bounds__(256, 2) void hmma_gemm(
    const __half* __restrict__ Ah, const __half* __restrict__ Bh,
    float* __restrict__ C, int ldc)
{
    extern __shared__ char smem[];
    uint32_t sb = smem_u32(smem);

    int tid = threadIdx.x;
    int lane = tid & 31;
    int warp = tid >> 5;
    int warp_m = warp & 3;
    int warp_n = warp >> 2;
    int m0 = blockIdx.y * 128;
    int n0 = blockIdx.x * 128;

    int q = lane >> 3;
    int lrow = lane & 7;
    int arow_l = (q & 1) * 8 + lrow;
    int ksel = q >> 1;

    float acc[2][8][4];
#pragma unroll
    for (int i = 0; i < 2; i++)
#pragma unroll
        for (int j = 0; j < 8; j++)
#pragma unroll
            for (int k = 0; k < 4; k++) acc[i][j][k] = 0.f;

    auto load_chunk = [&](int c) {
        int k0 = c * 32;
        uint32_t buf = sb + (uint32_t)(c & 3) * GEMM_STAGE;
#pragma unroll
        for (int t = 0; t < 4; t++) {
            int g = tid + t * 256;
            int mat = g >> 9;
            int inner = g & 511;
            int r = inner >> 2;
            int s = inner & 3;
            const __half* base = mat ? Bh : Ah;
            int row = (mat ? n0 : m0) + r;
            const void* src = base + (size_t)row * 2048 + k0 + s * 8;
            cp16(buf + (uint32_t)mat * 8192u + swz_off(r, s), src);
        }
        asm volatile("cp.async.commit_group;" ::: "memory");
    };

    load_chunk(0);
    load_chunk(1);
    load_chunk(2);
    load_chunk(3);

    for (int c = 0; c < 64; c++) {
        asm volatile("cp.async.wait_group 3;" ::: "memory");
        __syncthreads();

        uint32_t buf = sb + (uint32_t)(c & 3) * GEMM_STAGE;
        uint32_t bAh = buf, bBh = buf + 8192;

#pragma unroll
        for (int ks = 0; ks < 2; ks++) {
            int s = ks * 2 + ksel;
            uint32_t ah[2][4];
#pragma unroll
            for (int mi = 0; mi < 2; mi++) {
                int r = warp_m * 32 + mi * 16 + arow_l;
                ldm_x4(ah[mi], bAh + swz_off(r, s));
            }
            uint32_t bh[8][2];
#pragma unroll
            for (int j = 0; j < 4; j++) {
                int r = warp_n * 64 + j * 16 + arow_l;
                uint32_t t4[4];
                ldm_x4(t4, bBh + swz_off(r, s));
                bh[j * 2 + 0][0] = t4[0]; bh[j * 2 + 0][1] = t4[2];
                bh[j * 2 + 1][0] = t4[1]; bh[j * 2 + 1][1] = t4[3];
            }
#pragma unroll
            for (int mi = 0; mi < 2; mi++) {
#pragma unroll
                for (int nj = 0; nj < 8; nj++)
                    mma_f16(acc[mi][nj], ah[mi], bh[nj][0], bh[nj][1]);
            }
        }
        __syncthreads();
        if (c + 4 < 64) load_chunk(c + 4);
        else asm volatile("cp.async.commit_group;" ::: "memory");
    }

    int rr = lane >> 2;
    int cc = (lane & 3) * 2;
#pragma unroll
    for (int mi = 0; mi < 2; mi++) {
        int r1 = m0 + warp_m * 32 + mi * 16 + rr;
#pragma unroll
        for (int nj = 0; nj < 8; nj++) {
            int col = n0 + warp_n * 64 + nj * 8 + cc;
            float2 v0 = make_float2(acc[mi][nj][0], acc[mi][nj][1]);
            float2 v1 = make_float2(acc[mi][nj][2], acc[mi][nj][3]);
            *(float2*)&C[(size_t)r1 * ldc + col] = v0;
            *(float2*)&C[(size_t)(r1 + 8) * ldc + col] = v1;
        }
    }
}

// ---------------------------------------------------------------------------
// GEMM + fused RoPE epilogue for the QKV projection. (R14 exact)
// ---------------------------------------------------------------------------
__global__ __launch_bounds__(256, 2) void hmma_gemm_qkv(
    const __half* __restrict__ Ah, const __half* __restrict__ Bh,
    __half* __restrict__ Qh,
    float* __restrict__ kc, __half* __restrict__ Khi,
    float* __restrict__ vc, __half* __restrict__ Vhi)
{
    extern __shared__ char smem[];
    uint32_t sb = smem_u32(smem);

    int tid = threadIdx.x;
    int lane = tid & 31;
    int warp = tid >> 5;
    int warp_m = warp & 3;
    int warp_n = warp >> 2;
    int m0 = blockIdx.y * 128;
    int n0 = blockIdx.x * 128;

    int q = lane >> 3;
    int lrow = lane & 7;
    int arow_l = (q & 1) * 8 + lrow;
    int ksel = q >> 1;

    float acc[2][8][4];
#pragma unroll
    for (int i = 0; i < 2; i++)
#pragma unroll
        for (int j = 0; j < 8; j++)
#pragma unroll
            for (int k = 0; k < 4; k++) acc[i][j][k] = 0.f;

    auto load_chunk = [&](int c) {
        int k0 = c * 32;
        uint32_t buf = sb + (uint32_t)(c & 3) * GEMM_STAGE;
#pragma unroll
        for (int t = 0; t < 4; t++) {
            int g = tid + t * 256;
            int mat = g >> 9;
            int inner = g & 511;
            int r = inner >> 2;
            int s = inner & 3;
            const __half* base = mat ? Bh : Ah;
            int row = (mat ? n0 : m0) + r;
            const void* src = base + (size_t)row * 2048 + k0 + s * 8;
            cp16(buf + (uint32_t)mat * 8192u + swz_off(r, s), src);
        }
        asm volatile("cp.async.commit_group;" ::: "memory");
    };

    load_chunk(0);
    load_chunk(1);
    load_chunk(2);
    load_chunk(3);

    for (int c = 0; c < 64; c++) {
        asm volatile("cp.async.wait_group 3;" ::: "memory");
        __syncthreads();

        uint32_t buf = sb + (uint32_t)(c & 3) * GEMM_STAGE;
        uint32_t bAh = buf, bBh = buf + 8192;

#pragma unroll
        for (int ks = 0; ks < 2; ks++) {
            int s = ks * 2 + ksel;
            uint32_t ah[2][4];
#pragma unroll
            for (int mi = 0; mi < 2; mi++) {
                int r = warp_m * 32 + mi * 16 + arow_l;
                ldm_x4(ah[mi], bAh + swz_off(r, s));
            }
            uint32_t bh[8][2];
#pragma unroll
            for (int j = 0; j < 4; j++) {
                int r = warp_n * 64 + j * 16 + arow_l;
                uint32_t t4[4];
                ldm_x4(t4, bBh + swz_off(r, s));
                bh[j * 2 + 0][0] = t4[0]; bh[j * 2 + 0][1] = t4[2];
                bh[j * 2 + 1][0] = t4[1]; bh[j * 2 + 1][1] = t4[3];
            }
#pragma unroll
            for (int mi = 0; mi < 2; mi++) {
#pragma unroll
                for (int nj = 0; nj < 8; nj++)
                    mma_f16(acc[mi][nj], ah[mi], bh[nj][0], bh[nj][1]);
            }
        }
        __syncthreads();
        if (c + 4 < 64) load_chunk(c + 4);
        else asm volatile("cp.async.commit_group;" ::: "memory");
    }

    // ---- stage acc into smem fp32 [128][130] ----
    float* sm = (float*)smem;
    int rr = lane >> 2;
    int cc = (lane & 3) * 2;
#pragma unroll
    for (int mi = 0; mi < 2; mi++) {
        int rl = warp_m * 32 + mi * 16 + rr;
#pragma unroll
        for (int nj = 0; nj < 8; nj++) {
            int col = warp_n * 64 + nj * 8 + cc;
            *(float2*)&sm[rl * 130 + col] =
                make_float2(acc[mi][nj][0], acc[mi][nj][1]);
            *(float2*)&sm[(rl + 8) * 130 + col] =
                make_float2(acc[mi][nj][2], acc[mi][nj][3]);
        }
    }
    __syncthreads();

    // ---- fused rope / convert / scatter ----
    const float scale = 0.08838834764831845f;  // 1/sqrt(128)
    int tile = blockIdx.x;                      // 0..23
#pragma unroll
    for (int i = 0; i < 16; i++) {
        int idx = tid + i * 256;
        int r = idx >> 5;
        int e2 = (idx & 31) * 2;
        int m = m0 + r;
        float2 x1 = *(float2*)&sm[r * 130 + e2];
        float2 x2 = *(float2*)&sm[r * 130 + e2 + 64];
        if (tile < 20) {
            const float2* rp = g_rope + (size_t)(m & (S_ - 1)) * 64 + e2;
            float2 r0 = rp[0], r1 = rp[1];
            float ya0 = x1.x * r0.x - x2.x * r0.y;
            float ya1 = x1.y * r1.x - x2.y * r1.y;
            float yb0 = x1.x * r0.y + x2.x * r0.x;
            float yb1 = x1.y * r1.y + x2.y * r1.x;
            if (tile < 16) {
                size_t o = (size_t)m * 2048 + tile * 128 + e2;
                *(uint32_t*)&Qh[o]      = pack_f2h2(ya0 * scale, ya1 * scale);
                *(uint32_t*)&Qh[o + 64] = pack_f2h2(yb0 * scale, yb1 * scale);
            } else {
                int h = tile - 16;
                size_t o = (size_t)m * 512 + h * 128 + e2;
                *(float2*)&kc[o]      = make_float2(ya0, ya1);
                *(float2*)&kc[o + 64] = make_float2(yb0, yb1);
                *(uint32_t*)&Khi[o]      = pack_f2h2(ya0, ya1);
                *(uint32_t*)&Khi[o + 64] = pack_f2h2(yb0, yb1);
            }
        } else {
            int h = tile - 20;
            size_t o = (size_t)m * 512 + h * 128 + e2;
            *(float2*)&vc[o]      = x1;
            *(float2*)&vc[o + 64] = x2;
            *(uint32_t*)&Vhi[o]      = pack_f2h2(x1.x, x1.y);
            *(uint32_t*)&Vhi[o + 64] = pack_f2h2(x2.x, x2.y);
        }
    }
}

// ---------------------------------------------------------------------------
// Merged prep: rope table + fp32->fp16 converts (x4/thread) + W_O transpose.
// ---------------------------------------------------------------------------
#define N4_RES  (M_ * D_ / 4)
#define N4_WQ   (2048 * 2048 / 4)
#define N4_WK   (512 * 2048 / 4)
#define N4_ALL  (N4_RES + N4_WQ + 2 * N4_WK)
#define PREP_TBL_BLOCKS (S_ * 64 / 256)
#define PREP_EW_BLOCKS  ((N4_ALL + 1023) / 1024)
#define PREP_TR_BLOCKS  (64 * 64)
#define PREP_BLOCKS (PREP_TBL_BLOCKS + PREP_EW_BLOCKS + PREP_TR_BLOCKS)

__global__ __launch_bounds__(256) void prep_kernel(
    const float* __restrict__ residual, const float* __restrict__ WQ,
    const float* __restrict__ WK, const float* __restrict__ WV,
    const float* __restrict__ WO,
    __half* __restrict__ Ahi, __half* __restrict__ Whi,
    __half* __restrict__ WOhi,
    const int* __restrict__ sp_ptr)
{
    if (blockIdx.x < PREP_TBL_BLOCKS) {
        const float LOG2_BASE_OVER_HALF = 13.287712379549449f / 64.0f;
        int idx = blockIdx.x * 256 + threadIdx.x;
        int s = idx >> 6, e = idx & 63;
        float pos = (float)(*sp_ptr + s);
        float inv = exp2f(-(float)e * LOG2_BASE_OVER_HALF);
        float sn, cs;
        sincosf(pos * inv, &sn, &cs);
        g_rope[idx] = make_float2(cs, sn);
    } else if (blockIdx.x < PREP_TBL_BLOCKS + PREP_EW_BLOCKS) {
        int bid = blockIdx.x - PREP_TBL_BLOCKS;
#pragma unroll
        for (int t = 0; t < 4; t++) {
            int i = (bid * 4 + t) * 256 + threadIdx.x;
            if (i >= N4_ALL) break;
            const float* src;
            __half* dst;
            int j = i;
            if (j < N4_RES) {
                src = residual; dst = Ahi;
            } else if ((j -= N4_RES) < N4_WQ) {
                src = WQ; dst = Whi;
            } else if ((j -= N4_WQ) < N4_WK) {
                src = WK; dst = Whi + (size_t)2048 * 2048;
            } else {
                j -= N4_WK;
                src = WV; dst = Whi + (size_t)2560 * 2048;
            }
            float4 v = ((const float4*)src)[j];
            ushort4 hv = make_ushort4(
                __half_as_ushort(__float2half_rn(v.x)),
                __half_as_ushort(__float2half_rn(v.y)),
                __half_as_ushort(__float2half_rn(v.z)),
                __half_as_ushort(__float2half_rn(v.w)));
            ((ushort4*)dst)[j] = hv;
        }
    } else {
        __shared__ float t[32][33];
        int bid = blockIdx.x - PREP_TBL_BLOCKS - PREP_EW_BLOCKS;
        int bx = (bid & 63) * 32;
        int by = (bid >> 6) * 32;
        int x = threadIdx.x & 31;
        int y0 = threadIdx.x >> 5;
#pragma unroll
        for (int i = 0; i < 32; i += 8)
            t[y0 + i][x] = WO[(size_t)(by + y0 + i) * 2048 + bx + x];
        __syncthreads();
#pragma unroll
        for (int i = 0; i < 32; i += 8) {
            float v = t[x][y0 + i];
            WOhi[(size_t)(bx + y0 + i) * 2048 + by + x] = __float2half_rn(v);
        }
    }
}

// ---------------------------------------------------------------------------
// Tensor-core flash attention. Global longest-first 1-D grid:
// bid -> qt descending (outer), bh (inner). Diagonal-tile MMA skipping:
// per-warp skip of fully-masked QK n8-blocks / PV k16-chunks (exact zeros).
// ---------------------------------------------------------------------------
#define ATT_KV_STAGE 32768
#define ATT2_SMEM (16384 + 2 * ATT_KV_STAGE)

__global__ __launch_bounds__(128, 2) void attn_mma_kernel(
    const __half* __restrict__ Qhi,
    const __half* __restrict__ Khi, const __half* __restrict__ Vhi,
    __half* __restrict__ Ohi,
    const int* __restrict__ sp_ptr)
{
    extern __shared__ char smem[];
    uint32_t sb = smem_u32(smem);
    const uint32_t sQh = sb;
    const uint32_t sKV = sb + 16384;

    int tid = threadIdx.x;
    int lane = tid & 31;
    int warp = tid >> 5;
    int bid = blockIdx.x;                 // 0..1023
    int bh = bid & 31;                    // inner: head-batch
    int b = bh >> 4, h = bh & 15, kvh = h >> 2;
    int q0 = (S_ / 64 - 1 - (bid >> 5)) * 64;   // outer: qt descending
    int sp = *sp_ptr;
    float slope = exp2f(-0.5f * (float)(h + 1));

    int fr = ((lane >> 3) & 1) * 8 + (lane & 7);
    int fs = lane >> 4;

    int kt_end = (sp + q0 + 63) >> 6;
    if (kt_end > S_ / 64 - 1) kt_end = S_ / 64 - 1;

    auto load_kv = [&](int kt) {
        int k0 = (kt <= kt_end ? kt : kt_end) * 64;
        uint32_t stage = sKV + (uint32_t)(kt & 1) * ATT_KV_STAGE;
#pragma unroll
        for (int i = 0; i < 16; i++) {
            int idx = tid + i * 128;
            int t = idx >> 10;
            int inner = idx & 1023;
            int r = inner >> 4, sg = inner & 15;
            const __half* basep = t ? Vhi : Khi;
            const __half* src =
                basep + (size_t)(b * S_ + k0 + r) * 512 + kvh * 128 + sg * 8;
            cp16(stage + (uint32_t)t * 16384u + aswz(r, sg), src);
        }
        asm volatile("cp.async.commit_group;" ::: "memory");
    };

#pragma unroll
    for (int i = 0; i < 8; i++) {
        int idx = tid + i * 128;
        int r = idx >> 4, sg = idx & 15;
        const __half* src = Qhi
            + (size_t)(b * S_ + q0 + r) * 2048 + h * 128 + sg * 8;
        cp16(sQh + aswz(r, sg), src);
    }
    asm volatile("cp.async.commit_group;" ::: "memory");
    load_kv(0);
    load_kv(1);

    asm volatile("cp.async.wait_group 2;" ::: "memory");
    __syncthreads();
    uint32_t qh[8][4];
#pragma unroll
    for (int s = 0; s < 8; s++)
        ldm_x4(qh[s], sQh + aswz(warp * 16 + fr, 2 * s + fs));

    float Oacc[16][4];
#pragma unroll
    for (int e = 0; e < 16; e++)
#pragma unroll
        for (int k = 0; k < 4; k++) Oacc[e][k] = 0.f;
    float m0r = -1e30f, m1r = -1e30f;
    float l0r = 0.f, l1r = 0.f;

    int row0 = q0 + warp * 16 + (lane >> 2);
    int qp0 = sp + row0, qp1 = qp0 + 8;
    int qpmax = sp + q0 + warp * 16 + 15;   // max key pos visible to this warp

    for (int kt = 0; kt <= kt_end; kt++) {
        int k0 = kt * 64;
        asm volatile("cp.async.wait_group 1;" ::: "memory");
        __syncthreads();

        uint32_t stage = sKV + (uint32_t)(kt & 1) * ATT_KV_STAGE;
        uint32_t sKh = stage, sVh = stage + 16384;
        bool interior = (k0 + 63 <= sp + q0);

        // ---- S = Q K^T ----
        float sacc[8][4];
#pragma unroll
        for (int nj = 0; nj < 8; nj++)
#pragma unroll
            for (int k = 0; k < 4; k++) sacc[nj][k] = 0.f;

        if (interior) {
#pragma unroll
            for (int s = 0; s < 8; s++) {
                uint32_t kbh[8][2], t4[4];
#pragma unroll
                for (int j = 0; j < 4; j++) {
                    ldm_x4(t4, sKh + aswz(j * 16 + fr, 2 * s + fs));
                    kbh[2 * j][0] = t4[0]; kbh[2 * j][1] = t4[2];
                    kbh[2 * j + 1][0] = t4[1]; kbh[2 * j + 1][1] = t4[3];
                }
#pragma unroll
                for (int nj = 0; nj < 8; nj++)
                    mma_f16(sacc[nj], qh[s], kbh[nj][0], kbh[nj][1]);
            }
            // bias only (no mask possible)
#pragma unroll
            for (int nj = 0; nj < 8; nj++) {
                int c = k0 + nj * 8 + (lane & 3) * 2;
                sacc[nj][0] -= slope * (float)(qp0 - c);
                sacc[nj][1] -= slope * (float)(qp0 - c - 1);
                sacc[nj][2] -= slope * (float)(qp1 - c);
                sacc[nj][3] -= slope * (float)(qp1 - c - 1);
            }
        } else {
            // boundary: skip fully-masked n8 blocks (warp-uniform)
#pragma unroll
            for (int s = 0; s < 8; s++) {
                uint32_t kbh[8][2], t4[4];
#pragma unroll
                for (int j = 0; j < 4; j++) {
                    if (k0 + j * 16 <= qpmax) {
                        ldm_x4(t4, sKh + aswz(j * 16 + fr, 2 * s + fs));
                        kbh[2 * j][0] = t4[0]; kbh[2 * j][1] = t4[2];
                        kbh[2 * j + 1][0] = t4[1]; kbh[2 * j + 1][1] = t4[3];
                    }
                }
#pragma unroll
                for (int nj = 0; nj < 8; nj++)
                    if (k0 + nj * 8 <= qpmax)
                        mma_f16(sacc[nj], qh[s], kbh[nj][0], kbh[nj][1]);
            }
#pragma unroll
            for (int nj = 0; nj < 8; nj++) {
                int c = k0 + nj * 8 + (lane & 3) * 2;
                sacc[nj][0] = (c     <= qp0) ? sacc[nj][0] - slope * (float)(qp0 - c)     : -1e30f;
                sacc[nj][1] = (c + 1 <= qp0) ? sacc[nj][1] - slope * (float)(qp0 - c - 1) : -1e30f;
                sacc[nj][2] = (c     <= qp1) ? sacc[nj][2] - slope * (float)(qp1 - c)     : -1e30f;
                sacc[nj][3] = (c + 1 <= qp1) ? sacc[nj][3] - slope * (float)(qp1 - c - 1) : -1e30f;
            }
        }

        // ---- online softmax ----
        float mx0 = -1e30f, mx1 = -1e30f;
#pragma unroll
        for (int nj = 0; nj < 8; nj++) {
            mx0 = fmaxf(mx0, fmaxf(sacc[nj][0], sacc[nj][1]));
            mx1 = fmaxf(mx1, fmaxf(sacc[nj][2], sacc[nj][3]));
        }
        mx0 = fmaxf(mx0, __shfl_xor_sync(0xffffffffu, mx0, 1));
        mx0 = fmaxf(mx0, __shfl_xor_sync(0xffffffffu, mx0, 2));
        mx1 = fmaxf(mx1, __shfl_xor_sync(0xffffffffu, mx1, 1));
        mx1 = fmaxf(mx1, __shfl_xor_sync(0xffffffffu, mx1, 2));
        float mn0 = fmaxf(m0r, mx0), mn1 = fmaxf(m1r, mx1);
        float corr0 = __expf(m0r - mn0), corr1 = __expf(m1r - mn1);
        m0r = mn0; m1r = mn1;

        float ls0 = 0.f, ls1 = 0.f;
#pragma unroll
        for (int nj = 0; nj < 8; nj++) {
            sacc[nj][0] = __expf(sacc[nj][0] - mn0);
            sacc[nj][1] = __expf(sacc[nj][1] - mn0);
            sacc[nj][2] = __expf(sacc[nj][2] - mn1);
            sacc[nj][3] = __expf(sacc[nj][3] - mn1);
            ls0 += sacc[nj][0] + sacc[nj][1];
            ls1 += sacc[nj][2] + sacc[nj][3];
        }
        ls0 += __shfl_xor_sync(0xffffffffu, ls0, 1);
        ls0 += __shfl_xor_sync(0xffffffffu, ls0, 2);
        ls1 += __shfl_xor_sync(0xffffffffu, ls1, 1);
        ls1 += __shfl_xor_sync(0xffffffffu, ls1, 2);
        l0r = l0r * corr0 + ls0;
        l1r = l1r * corr1 + ls1;

#pragma unroll
        for (int e = 0; e < 16; e++) {
            Oacc[e][0] *= corr0; Oacc[e][1] *= corr0;
            Oacc[e][2] *= corr1; Oacc[e][3] *= corr1;
        }

        // ---- P -> fp16 A-fragments (4 k16 tiles) ----
        uint32_t phi[4][4];
#pragma unroll
        for (int t = 0; t < 4; t++) {
            phi[t][0] = pack_f2h2(sacc[2 * t][0], sacc[2 * t][1]);
            phi[t][1] = pack_f2h2(sacc[2 * t][2], sacc[2 * t][3]);
            phi[t][2] = pack_f2h2(sacc[2 * t + 1][0], sacc[2 * t + 1][1]);
            phi[t][3] = pack_f2h2(sacc[2 * t + 1][2], sacc[2 * t + 1][3]);
        }

        // ---- O += P V ----
        if (interior) {
#pragma unroll
            for (int t = 0; t < 4; t++) {
#pragma unroll
                for (int u = 0; u < 8; u++) {
                    uint32_t th[4];
                    ldm_x4_t(th, sVh + aswz(t * 16 + fr, 2 * u + fs));
                    mma_f16(Oacc[2 * u], phi[t], th[0], th[1]);
                    mma_f16(Oacc[2 * u + 1], phi[t], th[2], th[3]);
                }
            }
        } else {
            // skip k16 chunks whose keys are all masked for this warp (P == 0)
#pragma unroll
            for (int t = 0; t < 4; t++) {
                if (k0 + t * 16 <= qpmax) {
#pragma unroll
                    for (int u = 0; u < 8; u++) {
                        uint32_t th[4];
                        ldm_x4_t(th, sVh + aswz(t * 16 + fr, 2 * u + fs));
                        mma_f16(Oacc[2 * u], phi[t], th[0], th[1]);
                        mma_f16(Oacc[2 * u + 1], phi[t], th[2], th[3]);
                    }
                }
            }
        }
        __syncthreads();
        if (kt + 2 <= kt_end) load_kv(kt + 2);
        else asm volatile("cp.async.commit_group;" ::: "memory");
    }

    float inv0 = 1.f / l0r, inv1 = 1.f / l1r;
    size_t row0g = (size_t)(b * S_ + row0);
#pragma unroll
    for (int e = 0; e < 16; e++) {
        int colb = h * 128 + e * 8 + (lane & 3) * 2;
        uint32_t hp0 = pack_f2h2(Oacc[e][0] * inv0, Oacc[e][1] * inv0);
        uint32_t hp1 = pack_f2h2(Oacc[e][2] * inv1, Oacc[e][3] * inv1);
        *(uint32_t*)&Ohi[row0g * 2048 + colb] = hp0;
        *(uint32_t*)&Ohi[(row0g + 8) * 2048 + colb] = hp1;
    }
}

// ---------------------------------------------------------------------------
extern "C" void kernel_launch(void* const* d_in, const int* in_sizes, int n_in,
                              void* d_out, int out_size)
{
    const float* residual = (const float*)d_in[0];
    const float* W_Q = (const float*)d_in[1];
    const float* W_K = (const float*)d_in[2];
    const float* W_V = (const float*)d_in[3];
    const float* W_O = (const float*)d_in[4];
    const int* sp = (const int*)d_in[5];

    float* out = (float*)d_out;
    float* k_cache = out + (size_t)B_ * S_ * D_;
    float* v_cache = k_cache + (size_t)B_ * S_ * KVH_ * DH_;

    __half *Ahi, *Whi, *WOhi, *Phi, *Qh, *Khi, *Vhi;
    cudaGetSymbolAddress((void**)&Ahi, g_Ahi);
    cudaGetSymbolAddress((void**)&Whi, g_Whi);
    cudaGetSymbolAddress((void**)&WOhi, g_WOhi);
    cudaGetSymbolAddress((void**)&Phi, g_Phi);
    cudaGetSymbolAddress((void**)&Qh, g_Qh);
    cudaGetSymbolAddress((void**)&Khi, g_Khi);
    cudaGetSymbolAddress((void**)&Vhi, g_Vhi);

    cudaFuncSetAttribute(hmma_gemm, cudaFuncAttributeMaxDynamicSharedMemorySize,
                         GEMM_SMEM);
    cudaFuncSetAttribute(hmma_gemm_qkv, cudaFuncAttributeMaxDynamicSharedMemorySize,
                         QKV_SMEM);
    cudaFuncSetAttribute(attn_mma_kernel, cudaFuncAttributeMaxDynamicSharedMemorySize,
                         ATT2_SMEM);

    // 0) single merged prep (rope table + converts + W_O transpose)
    prep_kernel<<<PREP_BLOCKS, 256>>>(residual, W_Q, W_K, W_V, W_O,
                                      Ahi, Whi, WOhi, sp);

    // 1) fused QKV projection + rope epilogue
    hmma_gemm_qkv<<<dim3(NQKV / 128, M_ / 128), 256, QKV_SMEM>>>(
        Ahi, Whi, Qh, k_cache, Khi, v_cache, Vhi);

    // 2) attention: global longest-first 1-D grid, diagonal MMA skipping
    attn_mma_kernel<<<(S_ / 64) * B_ * H_, 128, ATT2_SMEM>>>(
        Qh, Khi, Vhi, Phi, sp);

    // 3) output projection (fp16 single-pass)
    hmma_gemm<<<dim3(D_ / 128, M_ / 128), 256, GEMM_SMEM>>>(
        Phi, WOhi, out, D_);
}

// round 17
// speedup vs baseline: 1.3395x; 1.0299x over previous
#include <cuda_runtime.h>
#include <cuda_fp16.h>
#include <math.h>
#include <stdint.h>

// Problem constants (fixed shapes from setup_inputs)
#define B_   2
#define S_   2048
#define D_   2048
#define H_   16
#define KVH_ 4
#define DH_  128
#define M_   (B_ * S_)          // 4096
#define NQKV 3072               // 2048 q + 512 k + 512 v

// Scratch (static device arrays; no runtime allocation allowed)
__device__ __half g_Ahi[M_ * D_];     // residual fp16
__device__ __half g_Whi[NQKV * D_];   // W_Q|W_K|W_V rows, fp16
__device__ __half g_WOh[D_ * D_];     // W_O [he][d] fp16 (NOT transposed)
__device__ __half g_Phi[M_ * D_];     // attention output fp16
__device__ __half g_Qh[M_ * D_];      // roped+scaled Q, fp16
__device__ __half g_Khi[M_ * 512];
__device__ __half g_Vhi[M_ * 512];
__device__ float2 g_rope[S_ * 64];    // per (s, e): (cos, sin)

// ---------------------------------------------------------------------------
// helpers
// ---------------------------------------------------------------------------
__device__ __forceinline__ uint32_t smem_u32(const void* p) {
    uint32_t a;
    asm("{ .reg .u64 t; cvta.to.shared.u64 t, %1; cvt.u32.u64 %0, t; }"
        : "=r"(a) : "l"(p));
    return a;
}

__device__ __forceinline__ void cp16(uint32_t dst, const void* src) {
    asm volatile("cp.async.cg.shared.global [%0], [%1], 16;"
                 :: "r"(dst), "l"(src));
}

__device__ __forceinline__ void ldm_x4(uint32_t* r, uint32_t addr) {
    asm volatile("ldmatrix.sync.aligned.m8n8.x4.shared.b16 {%0,%1,%2,%3}, [%4];"
                 : "=r"(r[0]), "=r"(r[1]), "=r"(r[2]), "=r"(r[3]) : "r"(addr));
}

__device__ __forceinline__ void ldm_x4_t(uint32_t* r, uint32_t addr) {
    asm volatile("ldmatrix.sync.aligned.m8n8.x4.trans.shared.b16 {%0,%1,%2,%3}, [%4];"
                 : "=r"(r[0]), "=r"(r[1]), "=r"(r[2]), "=r"(r[3]) : "r"(addr));
}

__device__ __forceinline__ void mma_f16(float* c, const uint32_t* a,
                                        uint32_t b0, uint32_t b1) {
    asm volatile(
        "mma.sync.aligned.m16n8k16.row.col.f32.f16.f16.f32 "
        "{%0,%1,%2,%3}, {%4,%5,%6,%7}, {%8,%9}, {%0,%1,%2,%3};"
        : "+f"(c[0]), "+f"(c[1]), "+f"(c[2]), "+f"(c[3])
        : "r"(a[0]), "r"(a[1]), "r"(a[2]), "r"(a[3]), "r"(b0), "r"(b1));
}

// swizzled byte offset for a 16B segment (row r, seg s) in a [rows][32]fp16 block
__device__ __forceinline__ uint32_t swz_off(int r, int s) {
    return (uint32_t)(r * 64 + ((s ^ ((r >> 1) & 3)) * 16));
}

// swizzled byte offset for [rows][128 fp16] tiles (256B rows, 16 segs)
__device__ __forceinline__ uint32_t aswz(int r, int sg) {
    return (uint32_t)(r * 256 + ((sg ^ (r & 7)) * 16));
}

__device__ __forceinline__ uint32_t pack_f2h2(float x0, float x1) {
    __half2 p = __floats2half2_rn(x0, x1);
    return *(uint32_t*)&p;
}

#define GEMM_STAGE 16384
#define GEMM_SMEM (4 * GEMM_STAGE)
#define QKV_SMEM 66560

// ---------------------------------------------------------------------------
// GEMM (out-proj): C[m,d] = sum_he A[m,he] * WO[he,d].
// B loaded k-major-in-rows ([32 he][128 d], contiguous d) + ldmatrix.trans,
// mirroring the attention PV path — no pre-transposed weights needed.
// ---------------------------------------------------------------------------
__global__ __launch_bounds__(256, 2) void hmma_gemm_wo(
    const __half* __restrict__ Ah, const __half* __restrict__ Bw,
    float* __restrict__ C, int ldc)
{
    extern __shared__ char smem[];
    uint32_t sb = smem_u32(smem);

    int tid = threadIdx.x;
    int lane = tid & 31;
    int warp = tid >> 5;
    int warp_m = warp & 3;
    int warp_n = warp >> 2;
    int m0 = blockIdx.y * 128;
    int n0 = blockIdx.x * 128;

    int q = lane >> 3;
    int lrow = lane & 7;
    int arow_l = (q & 1) * 8 + lrow;
    int ksel = q >> 1;
    int fr = arow_l;          // ldmatrix.trans row addressing (same form)
    int fs = lane >> 4;

    float acc[2][8][4];
#pragma unroll
    for (int i = 0; i < 2; i++)
#pragma unroll
        for (int j = 0; j < 8; j++)
#pragma unroll
            for (int k = 0; k < 4; k++) acc[i][j][k] = 0.f;

    auto load_chunk = [&](int c) {
        int k0 = c * 32;
        uint32_t buf = sb + (uint32_t)(c & 3) * GEMM_STAGE;
        // A: [128 m][32 k] fp16, 512 segs
#pragma unroll
        for (int t = 0; t < 2; t++) {
            int g = tid + t * 256;       // 0..511
            int r = g >> 2;
            int s = g & 3;
            const void* src = Ah + (size_t)(m0 + r) * 2048 + k0 + s * 8;
            cp16(buf + swz_off(r, s), src);
        }
        // B: [32 he][128 d] fp16, 512 segs (contiguous along d)
#pragma unroll
        for (int t = 0; t < 2; t++) {
            int g = tid + t * 256;       // 0..511
            int r = g >> 4;              // he row 0..31
            int sg = g & 15;             // d seg 0..15
            const void* src = Bw + (size_t)(k0 + r) * 2048 + n0 + sg * 8;
            cp16(buf + 8192u + aswz(r, sg), src);
        }
        asm volatile("cp.async.commit_group;" ::: "memory");
    };

    load_chunk(0);
    load_chunk(1);
    load_chunk(2);
    load_chunk(3);

    for (int c = 0; c < 64; c++) {
        asm volatile("cp.async.wait_group 3;" ::: "memory");
        __syncthreads();

        uint32_t buf = sb + (uint32_t)(c & 3) * GEMM_STAGE;
        uint32_t bAh = buf, bBh = buf + 8192;

#pragma unroll
        for (int ks = 0; ks < 2; ks++) {
            int s = ks * 2 + ksel;
            uint32_t ah[2][4];
#pragma unroll
            for (int mi = 0; mi < 2; mi++) {
                int r = warp_m * 32 + mi * 16 + arow_l;
                ldm_x4(ah[mi], bAh + swz_off(r, s));
            }
#pragma unroll
            for (int uu = 0; uu < 4; uu++) {
                uint32_t th[4];
                int uu2 = warp_n * 4 + uu;
                ldm_x4_t(th, bBh + aswz(ks * 16 + fr, 2 * uu2 + fs));
#pragma unroll
                for (int mi = 0; mi < 2; mi++) {
                    mma_f16(acc[mi][uu * 2],     ah[mi], th[0], th[1]);
                    mma_f16(acc[mi][uu * 2 + 1], ah[mi], th[2], th[3]);
                }
            }
        }
        __syncthreads();
        if (c + 4 < 64) load_chunk(c + 4);
        else asm volatile("cp.async.commit_group;" ::: "memory");
    }

    int rr = lane >> 2;
    int cc = (lane & 3) * 2;
#pragma unroll
    for (int mi = 0; mi < 2; mi++) {
        int r1 = m0 + warp_m * 32 + mi * 16 + rr;
#pragma unroll
        for (int nj = 0; nj < 8; nj++) {
            int col = n0 + warp_n * 64 + nj * 8 + cc;
            float2 v0 = make_float2(acc[mi][nj][0], acc[mi][nj][1]);
            float2 v1 = make_float2(acc[mi][nj][2], acc[mi][nj][3]);
            *(float2*)&C[(size_t)r1 * ldc + col] = v0;
            *(float2*)&C[(size_t)(r1 + 8) * ldc + col] = v1;
        }
    }
}

// ---------------------------------------------------------------------------
// GEMM + fused RoPE epilogue for the QKV projection. (R16 exact)
// ---------------------------------------------------------------------------
__global__ __launch_bounds__(256, 2) void hmma_gemm_qkv(
    const __half* __restrict__ Ah, const __half* __restrict__ Bh,
    __half* __restrict__ Qh,
    float* __restrict__ kc, __half* __restrict__ Khi,
    float* __restrict__ vc, __half* __restrict__ Vhi)
{
    extern __shared__ char smem[];
    uint32_t sb = smem_u32(smem);

    int tid = threadIdx.x;
    int lane = tid & 31;
    int warp = tid >> 5;
    int warp_m = warp & 3;
    int warp_n = warp >> 2;
    int m0 = blockIdx.y * 128;
    int n0 = blockIdx.x * 128;

    int q = lane >> 3;
    int lrow = lane & 7;
    int arow_l = (q & 1) * 8 + lrow;
    int ksel = q >> 1;

    float acc[2][8][4];
#pragma unroll
    for (int i = 0; i < 2; i++)
#pragma unroll
        for (int j = 0; j < 8; j++)
#pragma unroll
            for (int k = 0; k < 4; k++) acc[i][j][k] = 0.f;

    auto load_chunk = [&](int c) {
        int k0 = c * 32;
        uint32_t buf = sb + (uint32_t)(c & 3) * GEMM_STAGE;
#pragma unroll
        for (int t = 0; t < 4; t++) {
            int g = tid + t * 256;
            int mat = g >> 9;
            int inner = g & 511;
            int r = inner >> 2;
            int s = inner & 3;
            const __half* base = mat ? Bh : Ah;
            int row = (mat ? n0 : m0) + r;
            const void* src = base + (size_t)row * 2048 + k0 + s * 8;
            cp16(buf + (uint32_t)mat * 8192u + swz_off(r, s), src);
        }
        asm volatile("cp.async.commit_group;" ::: "memory");
    };

    load_chunk(0);
    load_chunk(1);
    load_chunk(2);
    load_chunk(3);

    for (int c = 0; c < 64; c++) {
        asm volatile("cp.async.wait_group 3;" ::: "memory");
        __syncthreads();

        uint32_t buf = sb + (uint32_t)(c & 3) * GEMM_STAGE;
        uint32_t bAh = buf, bBh = buf + 8192;

#pragma unroll
        for (int ks = 0; ks < 2; ks++) {
            int s = ks * 2 + ksel;
            uint32_t ah[2][4];
#pragma unroll
            for (int mi = 0; mi < 2; mi++) {
                int r = warp_m * 32 + mi * 16 + arow_l;
                ldm_x4(ah[mi], bAh + swz_off(r, s));
            }
            uint32_t bh[8][2];
#pragma unroll
            for (int j = 0; j < 4; j++) {
                int r = warp_n * 64 + j * 16 + arow_l;
                uint32_t t4[4];
                ldm_x4(t4, bBh + swz_off(r, s));
                bh[j * 2 + 0][0] = t4[0]; bh[j * 2 + 0][1] = t4[2];
                bh[j * 2 + 1][0] = t4[1]; bh[j * 2 + 1][1] = t4[3];
            }
#pragma unroll
            for (int mi = 0; mi < 2; mi++) {
#pragma unroll
                for (int nj = 0; nj < 8; nj++)
                    mma_f16(acc[mi][nj], ah[mi], bh[nj][0], bh[nj][1]);
            }
        }
        __syncthreads();
        if (c + 4 < 64) load_chunk(c + 4);
        else asm volatile("cp.async.commit_group;" ::: "memory");
    }

    // ---- stage acc into smem fp32 [128][130] ----
    float* sm = (float*)smem;
    int rr = lane >> 2;
    int cc = (lane & 3) * 2;
#pragma unroll
    for (int mi = 0; mi < 2; mi++) {
        int rl = warp_m * 32 + mi * 16 + rr;
#pragma unroll
        for (int nj = 0; nj < 8; nj++) {
            int col = warp_n * 64 + nj * 8 + cc;
            *(float2*)&sm[rl * 130 + col] =
                make_float2(acc[mi][nj][0], acc[mi][nj][1]);
            *(float2*)&sm[(rl + 8) * 130 + col] =
                make_float2(acc[mi][nj][2], acc[mi][nj][3]);
        }
    }
    __syncthreads();

    // ---- fused rope / convert / scatter ----
    const float scale = 0.08838834764831845f;  // 1/sqrt(128)
    int tile = blockIdx.x;                      // 0..23
#pragma unroll
    for (int i = 0; i < 16; i++) {
        int idx = tid + i * 256;
        int r = idx >> 5;
        int e2 = (idx & 31) * 2;
        int m = m0 + r;
        float2 x1 = *(float2*)&sm[r * 130 + e2];
        float2 x2 = *(float2*)&sm[r * 130 + e2 + 64];
        if (tile < 20) {
            const float2* rp = g_rope + (size_t)(m & (S_ - 1)) * 64 + e2;
            float2 r0 = rp[0], r1 = rp[1];
            float ya0 = x1.x * r0.x - x2.x * r0.y;
            float ya1 = x1.y * r1.x - x2.y * r1.y;
            float yb0 = x1.x * r0.y + x2.x * r0.x;
            float yb1 = x1.y * r1.y + x2.y * r1.x;
            if (tile < 16) {
                size_t o = (size_t)m * 2048 + tile * 128 + e2;
                *(uint32_t*)&Qh[o]      = pack_f2h2(ya0 * scale, ya1 * scale);
                *(uint32_t*)&Qh[o + 64] = pack_f2h2(yb0 * scale, yb1 * scale);
            } else {
                int h = tile - 16;
                size_t o = (size_t)m * 512 + h * 128 + e2;
                *(float2*)&kc[o]      = make_float2(ya0, ya1);
                *(float2*)&kc[o + 64] = make_float2(yb0, yb1);
                *(uint32_t*)&Khi[o]      = pack_f2h2(ya0, ya1);
                *(uint32_t*)&Khi[o + 64] = pack_f2h2(yb0, yb1);
            }
        } else {
            int h = tile - 20;
            size_t o = (size_t)m * 512 + h * 128 + e2;
            *(float2*)&vc[o]      = x1;
            *(float2*)&vc[o + 64] = x2;
            *(uint32_t*)&Vhi[o]      = pack_f2h2(x1.x, x1.y);
            *(uint32_t*)&Vhi[o + 64] = pack_f2h2(x2.x, x2.y);
        }
    }
}

// ---------------------------------------------------------------------------
// Merged prep: rope table + fp32->fp16 converts (x4/thread) for
// residual + W_Q + W_K + W_V + W_O (no transpose needed anymore).
// ---------------------------------------------------------------------------
#define N4_RES  (M_ * D_ / 4)
#define N4_WQ   (2048 * 2048 / 4)
#define N4_WK   (512 * 2048 / 4)
#define N4_WO   (2048 * 2048 / 4)
#define N4_ALL  (N4_RES + N4_WQ + 2 * N4_WK + N4_WO)
#define PREP_TBL_BLOCKS (S_ * 64 / 256)
#define PREP_EW_BLOCKS  ((N4_ALL + 1023) / 1024)
#define PREP_BLOCKS (PREP_TBL_BLOCKS + PREP_EW_BLOCKS)

__global__ __launch_bounds__(256) void prep_kernel(
    const float* __restrict__ residual, const float* __restrict__ WQ,
    const float* __restrict__ WK, const float* __restrict__ WV,
    const float* __restrict__ WO,
    __half* __restrict__ Ahi, __half* __restrict__ Whi,
    __half* __restrict__ WOh,
    const int* __restrict__ sp_ptr)
{
    if (blockIdx.x < PREP_TBL_BLOCKS) {
        const float LOG2_BASE_OVER_HALF = 13.287712379549449f / 64.0f;
        int idx = blockIdx.x * 256 + threadIdx.x;
        int s = idx >> 6, e = idx & 63;
        float pos = (float)(*sp_ptr + s);
        float inv = exp2f(-(float)e * LOG2_BASE_OVER_HALF);
        float sn, cs;
        sincosf(pos * inv, &sn, &cs);
        g_rope[idx] = make_float2(cs, sn);
    } else {
        int bid = blockIdx.x - PREP_TBL_BLOCKS;
#pragma unroll
        for (int t = 0; t < 4; t++) {
            int i = (bid * 4 + t) * 256 + threadIdx.x;
            if (i >= N4_ALL) break;
            const float* src;
            __half* dst;
            int j = i;
            if (j < N4_RES) {
                src = residual; dst = Ahi;
            } else if ((j -= N4_RES) < N4_WQ) {
                src = WQ; dst = Whi;
            } else if ((j -= N4_WQ) < N4_WK) {
                src = WK; dst = Whi + (size_t)2048 * 2048;
            } else if ((j -= N4_WK) < N4_WK) {
                src = WV; dst = Whi + (size_t)2560 * 2048;
            } else {
                j -= N4_WK;
                src = WO; dst = WOh;
            }
            float4 v = ((const float4*)src)[j];
            ushort4 hv = make_ushort4(
                __half_as_ushort(__float2half_rn(v.x)),
                __half_as_ushort(__float2half_rn(v.y)),
                __half_as_ushort(__float2half_rn(v.z)),
                __half_as_ushort(__float2half_rn(v.w)));
            ((ushort4*)dst)[j] = hv;
        }
    }
}

// ---------------------------------------------------------------------------
// Tensor-core flash attention (R16 exact: global longest-first + diag skip).
// ---------------------------------------------------------------------------
#define ATT_KV_STAGE 32768
#define ATT2_SMEM (16384 + 2 * ATT_KV_STAGE)

__global__ __launch_bounds__(128, 2) void attn_mma_kernel(
    const __half* __restrict__ Qhi,
    const __half* __restrict__ Khi, const __half* __restrict__ Vhi,
    __half* __restrict__ Ohi,
    const int* __restrict__ sp_ptr)
{
    extern __shared__ char smem[];
    uint32_t sb = smem_u32(smem);
    const uint32_t sQh = sb;
    const uint32_t sKV = sb + 16384;

    int tid = threadIdx.x;
    int lane = tid & 31;
    int warp = tid >> 5;
    int bid = blockIdx.x;
    int bh = bid & 31;
    int b = bh >> 4, h = bh & 15, kvh = h >> 2;
    int q0 = (S_ / 64 - 1 - (bid >> 5)) * 64;
    int sp = *sp_ptr;
    float slope = exp2f(-0.5f * (float)(h + 1));

    int fr = ((lane >> 3) & 1) * 8 + (lane & 7);
    int fs = lane >> 4;

    int kt_end = (sp + q0 + 63) >> 6;
    if (kt_end > S_ / 64 - 1) kt_end = S_ / 64 - 1;

    auto load_kv = [&](int kt) {
        int k0 = (kt <= kt_end ? kt : kt_end) * 64;
        uint32_t stage = sKV + (uint32_t)(kt & 1) * ATT_KV_STAGE;
#pragma unroll
        for (int i = 0; i < 16; i++) {
            int idx = tid + i * 128;
            int t = idx >> 10;
            int inner = idx & 1023;
            int r = inner >> 4, sg = inner & 15;
            const __half* basep = t ? Vhi : Khi;
            const __half* src =
                basep + (size_t)(b * S_ + k0 + r) * 512 + kvh * 128 + sg * 8;
            cp16(stage + (uint32_t)t * 16384u + aswz(r, sg), src);
        }
        asm volatile("cp.async.commit_group;" ::: "memory");
    };

#pragma unroll
    for (int i = 0; i < 8; i++) {
        int idx = tid + i * 128;
        int r = idx >> 4, sg = idx & 15;
        const __half* src = Qhi
            + (size_t)(b * S_ + q0 + r) * 2048 + h * 128 + sg * 8;
        cp16(sQh + aswz(r, sg), src);
    }
    asm volatile("cp.async.commit_group;" ::: "memory");
    load_kv(0);
    load_kv(1);

    asm volatile("cp.async.wait_group 2;" ::: "memory");
    __syncthreads();
    uint32_t qh[8][4];
#pragma unroll
    for (int s = 0; s < 8; s++)
        ldm_x4(qh[s], sQh + aswz(warp * 16 + fr, 2 * s + fs));

    float Oacc[16][4];
#pragma unroll
    for (int e = 0; e < 16; e++)
#pragma unroll
        for (int k = 0; k < 4; k++) Oacc[e][k] = 0.f;
    float m0r = -1e30f, m1r = -1e30f;
    float l0r = 0.f, l1r = 0.f;

    int row0 = q0 + warp * 16 + (lane >> 2);
    int qp0 = sp + row0, qp1 = qp0 + 8;
    int qpmax = sp + q0 + warp * 16 + 15;

    for (int kt = 0; kt <= kt_end; kt++) {
        int k0 = kt * 64;
        asm volatile("cp.async.wait_group 1;" ::: "memory");
        __syncthreads();

        uint32_t stage = sKV + (uint32_t)(kt & 1) * ATT_KV_STAGE;
        uint32_t sKh = stage, sVh = stage + 16384;
        bool interior = (k0 + 63 <= sp + q0);

        float sacc[8][4];
#pragma unroll
        for (int nj = 0; nj < 8; nj++)
#pragma unroll
            for (int k = 0; k < 4; k++) sacc[nj][k] = 0.f;

        if (interior) {
#pragma unroll
            for (int s = 0; s < 8; s++) {
                uint32_t kbh[8][2], t4[4];
#pragma unroll
                for (int j = 0; j < 4; j++) {
                    ldm_x4(t4, sKh + aswz(j * 16 + fr, 2 * s + fs));
                    kbh[2 * j][0] = t4[0]; kbh[2 * j][1] = t4[2];
                    kbh[2 * j + 1][0] = t4[1]; kbh[2 * j + 1][1] = t4[3];
                }
#pragma unroll
                for (int nj = 0; nj < 8; nj++)
                    mma_f16(sacc[nj], qh[s], kbh[nj][0], kbh[nj][1]);
            }
#pragma unroll
            for (int nj = 0; nj < 8; nj++) {
                int c = k0 + nj * 8 + (lane & 3) * 2;
                sacc[nj][0] -= slope * (float)(qp0 - c);
                sacc[nj][1] -= slope * (float)(qp0 - c - 1);
                sacc[nj][2] -= slope * (float)(qp1 - c);
                sacc[nj][3] -= slope * (float)(qp1 - c - 1);
            }
        } else {
#pragma unroll
            for (int s = 0; s < 8; s++) {
                uint32_t kbh[8][2], t4[4];
#pragma unroll
                for (int j = 0; j < 4; j++) {
                    if (k0 + j * 16 <= qpmax) {
                        ldm_x4(t4, sKh + aswz(j * 16 + fr, 2 * s + fs));
                        kbh[2 * j][0] = t4[0]; kbh[2 * j][1] = t4[2];
                        kbh[2 * j + 1][0] = t4[1]; kbh[2 * j + 1][1] = t4[3];
                    }
                }
#pragma unroll
                for (int nj = 0; nj < 8; nj++)
                    if (k0 + nj * 8 <= qpmax)
                        mma_f16(sacc[nj], qh[s], kbh[nj][0], kbh[nj][1]);
            }
#pragma unroll
            for (int nj = 0; nj < 8; nj++) {
                int c = k0 + nj * 8 + (lane & 3) * 2;
                sacc[nj][0] = (c     <= qp0) ? sacc[nj][0] - slope * (float)(qp0 - c)     : -1e30f;
                sacc[nj][1] = (c + 1 <= qp0) ? sacc[nj][1] - slope * (float)(qp0 - c - 1) : -1e30f;
                sacc[nj][2] = (c     <= qp1) ? sacc[nj][2] - slope * (float)(qp1 - c)     : -1e30f;
                sacc[nj][3] = (c + 1 <= qp1) ? sacc[nj][3] - slope * (float)(qp1 - c - 1) : -1e30f;
            }
        }

        float mx0 = -1e30f, mx1 = -1e30f;
#pragma unroll
        for (int nj = 0; nj < 8; nj++) {
            mx0 = fmaxf(mx0, fmaxf(sacc[nj][0], sacc[nj][1]));
            mx1 = fmaxf(mx1, fmaxf(sacc[nj][2], sacc[nj][3]));
        }
        mx0 = fmaxf(mx0, __shfl_xor_sync(0xffffffffu, mx0, 1));
        mx0 = fmaxf(mx0, __shfl_xor_sync(0xffffffffu, mx0, 2));
        mx1 = fmaxf(mx1, __shfl_xor_sync(0xffffffffu, mx1, 1));
        mx1 = fmaxf(mx1, __shfl_xor_sync(0xffffffffu, mx1, 2));
        float mn0 = fmaxf(m0r, mx0), mn1 = fmaxf(m1r, mx1);
        float corr0 = __expf(m0r - mn0), corr1 = __expf(m1r - mn1);
        m0r = mn0; m1r = mn1;

        float ls0 = 0.f, ls1 = 0.f;
#pragma unroll
        for (int nj = 0; nj < 8; nj++) {
            sacc[nj][0] = __expf(sacc[nj][0] - mn0);
            sacc[nj][1] = __expf(sacc[nj][1] - mn0);
            sacc[nj][2] = __expf(sacc[nj][2] - mn1);
            sacc[nj][3] = __expf(sacc[nj][3] - mn1);
            ls0 += sacc[nj][0] + sacc[nj][1];
            ls1 += sacc[nj][2] + sacc[nj][3];
        }
        ls0 += __shfl_xor_sync(0xffffffffu, ls0, 1);
        ls0 += __shfl_xor_sync(0xffffffffu, ls0, 2);
        ls1 += __shfl_xor_sync(0xffffffffu, ls1, 1);
        ls1 += __shfl_xor_sync(0xffffffffu, ls1, 2);
        l0r = l0r * corr0 + ls0;
        l1r = l1r * corr1 + ls1;

#pragma unroll
        for (int e = 0; e < 16; e++) {
            Oacc[e][0] *= corr0; Oacc[e][1] *= corr0;
            Oacc[e][2] *= corr1; Oacc[e][3] *= corr1;
        }

        uint32_t phi[4][4];
#pragma unroll
        for (int t = 0; t < 4; t++) {
            phi[t][0] = pack_f2h2(sacc[2 * t][0], sacc[2 * t][1]);
            phi[t][1] = pack_f2h2(sacc[2 * t][2], sacc[2 * t][3]);
            phi[t][2] = pack_f2h2(sacc[2 * t + 1][0], sacc[2 * t + 1][1]);
            phi[t][3] = pack_f2h2(sacc[2 * t + 1][2], sacc[2 * t + 1][3]);
        }

        if (interior) {
#pragma unroll
            for (int t = 0; t < 4; t++) {
#pragma unroll
                for (int u = 0; u < 8; u++) {
                    uint32_t th[4];
                    ldm_x4_t(th, sVh + aswz(t * 16 + fr, 2 * u + fs));
                    mma_f16(Oacc[2 * u], phi[t], th[0], th[1]);
                    mma_f16(Oacc[2 * u + 1], phi[t], th[2], th[3]);
                }
            }
        } else {
#pragma unroll
            for (int t = 0; t < 4; t++) {
                if (k0 + t * 16 <= qpmax) {
#pragma unroll
                    for (int u = 0; u < 8; u++) {
                        uint32_t th[4];
                        ldm_x4_t(th, sVh + aswz(t * 16 + fr, 2 * u + fs));
                        mma_f16(Oacc[2 * u], phi[t], th[0], th[1]);
                        mma_f16(Oacc[2 * u + 1], phi[t], th[2], th[3]);
                    }
                }
            }
        }
        __syncthreads();
        if (kt + 2 <= kt_end) load_kv(kt + 2);
        else asm volatile("cp.async.commit_group;" ::: "memory");
    }

    float inv0 = 1.f / l0r, inv1 = 1.f / l1r;
    size_t row0g = (size_t)(b * S_ + row0);
#pragma unroll
    for (int e = 0; e < 16; e++) {
        int colb = h * 128 + e * 8 + (lane & 3) * 2;
        uint32_t hp0 = pack_f2h2(Oacc[e][0] * inv0, Oacc[e][1] * inv0);
        uint32_t hp1 = pack_f2h2(Oacc[e][2] * inv1, Oacc[e][3] * inv1);
        *(uint32_t*)&Ohi[row0g * 2048 + colb] = hp0;
        *(uint32_t*)&Ohi[(row0g + 8) * 2048 + colb] = hp1;
    }
}

// ---------------------------------------------------------------------------
extern "C" void kernel_launch(void* const* d_in, const int* in_sizes, int n_in,
                              void* d_out, int out_size)
{
    const float* residual = (const float*)d_in[0];
    const float* W_Q = (const float*)d_in[1];
    const float* W_K = (const float*)d_in[2];
    const float* W_V = (const float*)d_in[3];
    const float* W_O = (const float*)d_in[4];
    const int* sp = (const int*)d_in[5];

    float* out = (float*)d_out;
    float* k_cache = out + (size_t)B_ * S_ * D_;
    float* v_cache = k_cache + (size_t)B_ * S_ * KVH_ * DH_;

    __half *Ahi, *Whi, *WOh, *Phi, *Qh, *Khi, *Vhi;
    cudaGetSymbolAddress((void**)&Ahi, g_Ahi);
    cudaGetSymbolAddress((void**)&Whi, g_Whi);
    cudaGetSymbolAddress((void**)&WOh, g_WOh);
    cudaGetSymbolAddress((void**)&Phi, g_Phi);
    cudaGetSymbolAddress((void**)&Qh, g_Qh);
    cudaGetSymbolAddress((void**)&Khi, g_Khi);
    cudaGetSymbolAddress((void**)&Vhi, g_Vhi);

    cudaFuncSetAttribute(hmma_gemm_wo, cudaFuncAttributeMaxDynamicSharedMemorySize,
                         GEMM_SMEM);
    cudaFuncSetAttribute(hmma_gemm_qkv, cudaFuncAttributeMaxDynamicSharedMemorySize,
                         QKV_SMEM);
    cudaFuncSetAttribute(attn_mma_kernel, cudaFuncAttributeMaxDynamicSharedMemorySize,
                         ATT2_SMEM);

    // 0) single merged prep (rope table + all converts, no transpose)
    prep_kernel<<<PREP_BLOCKS, 256>>>(residual, W_Q, W_K, W_V, W_O,
                                      Ahi, Whi, WOh, sp);

    // 1) fused QKV projection + rope epilogue
    hmma_gemm_qkv<<<dim3(NQKV / 128, M_ / 128), 256, QKV_SMEM>>>(
        Ahi, Whi, Qh, k_cache, Khi, v_cache, Vhi);

    // 2) attention: global longest-first 1-D grid, diagonal MMA skipping
    attn_mma_kernel<<<(S_ / 64) * B_ * H_, 128, ATT2_SMEM>>>(
        Qh, Khi, Vhi, Phi, sp);

    // 3) output projection (B via ldmatrix.trans, untransposed W_O)
    hmma_gemm_wo<<<dim3(D_ / 128, M_ / 128), 256, GEMM_SMEM>>>(
        Phi, WOh, out, D_);
}